// round 12
// baseline (speedup 1.0000x reference)
#include <cuda_runtime.h>

constexpr int NYg = 1024;
constexpr int NXg = 2048;
constexpr int N0  = NYg * NXg;
constexpr float DT = 0.1f;
constexpr float NU = 0.01f;
constexpr float UB = 1.0f;
constexpr float C12 = 1.0f / 12.0f;
constexpr float C3  = 1.0f / 3.0f;

__device__ float g_u2[N0];
__device__ float g_v2[N0];
__device__ float g_b [N0];
__device__ float g_pa[N0];
__device__ float g_pb[N0];
__device__ float g_r1a[512 * 1024];
__device__ float g_r1b[512 * 1024];
__device__ float g_r2a[256 * 512];
__device__ float g_r2b[256 * 512];
__device__ float g_r3a[128 * 256];
__device__ float g_r3b[128 * 256];
__device__ float g_A5[32 * 64];

// ---------- boundary-condition loaders ----------
__device__ __forceinline__ float ldU(const float* __restrict__ u, int y, int x) {
    if (y < 0 || y >= NYg) return UB;
    if (x < 0) return UB;
    if (x >= NXg) return u[y * NXg + NXg - 1];
    return u[y * NXg + x];
}
__device__ __forceinline__ float ldV(const float* __restrict__ v, int y, int x) {
    if (x >= NXg) { if (y < 0 || y >= NYg) return 0.0f; return v[y * NXg + NXg - 1]; }
    if (y < 0 || y >= NYg || x < 0) return 0.0f;
    return v[y * NXg + x];
}
__device__ __forceinline__ float ldP(const float* __restrict__ p, int y, int x) {
    if (x >= NXg) return 0.0f;
    int yy = min(max(y, 0), NYg - 1);
    int xx = max(x, 0);
    return p[yy * NXg + xx];
}

// generic prolong S8
__device__ __forceinline__ float prolong_S8(const float* __restrict__ A, int stride,
                                            int yb, int xb, int y, int x)
{
    int r0 = ((y - 1) >> 1) - yb;
    int c0 = ((x - 1) >> 1) - xb;
    int py = y & 1, px = x & 1;
    float wr0 = (float)(1 + py), wr1 = (float)(2 - py);
    float wc0 = (float)(1 + px), wc1 = (float)(2 - px);
    const float* row0 = A + r0 * stride + c0;
    const float* row1 = row0 + stride;
    float V00 = row0[0], V01 = row0[1], V10 = row1[0], V11 = row1[1];
    float S9 = wr0 * (wc0 * V00 + wc1 * V01) + wr1 * (wc0 * V10 + wc1 * V11);
    float ctr = py ? (px ? V00 : V01) : (px ? V10 : V11);
    return S9 - ctr;
}

// restriction pyramid from per-thread r1 value
__device__ __forceinline__ void rr_pyramid(float r1v, int bx, int by, int t,
    float* __restrict__ r1o, float* __restrict__ r2o, float* __restrict__ r3o,
    float* __restrict__ s1, float* __restrict__ s2)
{
    int ry = t >> 6, rx = t & 63;
    r1o[(4 * by + ry) * 1024 + 64 * bx + rx] = r1v;
    s1[ry * 64 + rx] = r1v;
    __syncthreads();
    if (t < 64) {
        int ty = t >> 5, tx = t & 31;
        float v = 0.25f * (s1[2*ty*64 + 2*tx] + s1[2*ty*64 + 2*tx + 1]
                         + s1[(2*ty+1)*64 + 2*tx] + s1[(2*ty+1)*64 + 2*tx + 1]);
        r2o[(2 * by + ty) * 512 + 32 * bx + tx] = v;
        s2[ty * 32 + tx] = v;
    }
    __syncthreads();
    if (t < 16) {
        float v = 0.25f * (s2[2*t] + s2[2*t + 1] + s2[32 + 2*t] + s2[32 + 2*t + 1]);
        r3o[by * 256 + 16 * bx + t] = v;
    }
}

// ============ fused momentum + divergence + initial residual pyramid ============
__global__ __launch_bounds__(256) void k_mom(
    const float* __restrict__ u, const float* __restrict__ v,
    const float* __restrict__ p, const float* __restrict__ sig,
    float* __restrict__ u2g, float* __restrict__ v2g, float* __restrict__ bg,
    float* __restrict__ r1o, float* __restrict__ r2o, float* __restrict__ r3o)
{
    __shared__ float su[14][136], sv[14][136], sp[14][136];
    __shared__ float sbu[12][136], sbv[12][136];
    __shared__ float su2[10][136], sv2[10][136];
    float* sb = &sbu[0][0];
    float* s1 = sb + 8 * 130;
    float* s2 = s1 + 256;

    cudaGridDependencySynchronize();

    int x0 = blockIdx.x * 128, y0 = blockIdx.y * 8;
    int t = threadIdx.y * 32 + threadIdx.x;

    for (int idx = t; idx < 14 * 34; idx += 256) {
        int ry = idx / 34, rc = idx - ry * 34;
        int gy = y0 - 3 + ry, gx = x0 - 4 + rc * 4;
        float4 a, bb, c;
        if (gy >= 0 && gy < NYg && gx >= 0 && gx + 3 < NXg) {
            a  = *(const float4*)(u + gy * NXg + gx);
            bb = *(const float4*)(v + gy * NXg + gx);
            c  = *(const float4*)(p + gy * NXg + gx);
        } else {
            a  = make_float4(ldU(u,gy,gx), ldU(u,gy,gx+1), ldU(u,gy,gx+2), ldU(u,gy,gx+3));
            bb = make_float4(ldV(v,gy,gx), ldV(v,gy,gx+1), ldV(v,gy,gx+2), ldV(v,gy,gx+3));
            c  = make_float4(ldP(p,gy,gx), ldP(p,gy,gx+1), ldP(p,gy,gx+2), ldP(p,gy,gx+3));
        }
        *(float4*)&su[ry][rc*4] = a;
        *(float4*)&sv[ry][rc*4] = bb;
        *(float4*)&sp[ry][rc*4] = c;
    }
    __syncthreads();

    for (int idx = t; idx < 12 * 32; idx += 256) {
        int ry = idx >> 5, q = idx & 31;
        int c = 4 + 4 * q;
        int gy = y0 - 2 + ry;
        if (gy < 0 || gy >= NYg) {
            *(float4*)&sbu[ry][c] = make_float4(UB, UB, UB, UB);
            *(float4*)&sbv[ry][c] = make_float4(0.f, 0.f, 0.f, 0.f);
            continue;
        }
        int r = ry + 1;
        float4 vc4 = *(const float4*)&sv[r][c];
        float v00[4] = {vc4.x, vc4.y, vc4.z, vc4.w};
        float u00[4], obu[4], obv[4];
        {
            float R[3][6];
#pragma unroll
            for (int j = 0; j < 3; j++) {
                const float* rp_ = &su[r - 1 + j][0];
                float4 m = *(const float4*)(rp_ + c);
                R[j][0]=rp_[c-1]; R[j][1]=m.x; R[j][2]=m.y; R[j][3]=m.z; R[j][4]=m.w; R[j][5]=rp_[c+4];
            }
#pragma unroll
            for (int k = 0; k < 4; k++) {
                float ADx = (R[0][k+2]-R[0][k] + 4.f*(R[1][k+2]-R[1][k]) + R[2][k+2]-R[2][k]) * C12;
                float ADy = (R[2][k]+4.f*R[2][k+1]+R[2][k+2] - R[0][k]-4.f*R[0][k+1]-R[0][k+2]) * C12;
                float c0 = R[1][k+1];
                float AD2 = (R[0][k]+R[0][k+1]+R[0][k+2]+R[1][k]+R[1][k+2]
                           + R[2][k]+R[2][k+1]+R[2][k+2] - 8.f*c0) * C3;
                u00[k] = c0;
                obu[k] = c0 + 0.5f*(NU*AD2*DT - c0*ADx*DT - v00[k]*ADy*DT);
            }
        }
        {
            float R[3][6];
#pragma unroll
            for (int j = 0; j < 3; j++) {
                const float* rp_ = &sv[r - 1 + j][0];
                float4 m = *(const float4*)(rp_ + c);
                R[j][0]=rp_[c-1]; R[j][1]=m.x; R[j][2]=m.y; R[j][3]=m.z; R[j][4]=m.w; R[j][5]=rp_[c+4];
            }
#pragma unroll
            for (int k = 0; k < 4; k++) {
                float ADx = (R[0][k+2]-R[0][k] + 4.f*(R[1][k+2]-R[1][k]) + R[2][k+2]-R[2][k]) * C12;
                float ADy = (R[2][k]+4.f*R[2][k+1]+R[2][k+2] - R[0][k]-4.f*R[0][k+1]-R[0][k+2]) * C12;
                float c0 = R[1][k+1];
                float AD2 = (R[0][k]+R[0][k+1]+R[0][k+2]+R[1][k]+R[1][k+2]
                           + R[2][k]+R[2][k+1]+R[2][k+2] - 8.f*c0) * C3;
                obv[k] = c0 + 0.5f*(NU*AD2*DT - u00[k]*ADx*DT - c0*ADy*DT);
            }
        }
        {
            float R[3][6];
#pragma unroll
            for (int j = 0; j < 3; j++) {
                const float* rp_ = &sp[r - 1 + j][0];
                float4 m = *(const float4*)(rp_ + c);
                R[j][0]=rp_[c-1]; R[j][1]=m.x; R[j][2]=m.y; R[j][3]=m.z; R[j][4]=m.w; R[j][5]=rp_[c+4];
            }
#pragma unroll
            for (int k = 0; k < 4; k++) {
                float Gx = (R[0][k+2]-R[0][k] + 4.f*(R[1][k+2]-R[1][k]) + R[2][k+2]-R[2][k]) * (C12 * DT);
                float Gy = (R[2][k]+4.f*R[2][k+1]+R[2][k+2] - R[0][k]-4.f*R[0][k+1]-R[0][k+2]) * (C12 * DT);
                obu[k] -= Gx; obv[k] -= Gy;
            }
        }
        float4 sg4 = *(const float4*)(sig + gy * NXg + (x0 - 4 + c));
        float sgv[4] = {sg4.x, sg4.y, sg4.z, sg4.w};
#pragma unroll
        for (int k = 0; k < 4; k++) {
            float damp = 1.0f / (1.0f + DT * sgv[k]);
            obu[k] *= damp; obv[k] *= damp;
        }
        *(float4*)&sbu[ry][c] = make_float4(obu[0], obu[1], obu[2], obu[3]);
        *(float4*)&sbv[ry][c] = make_float4(obv[0], obv[1], obv[2], obv[3]);
    }
    if (t < 48) {
        int ry = t >> 2, ec = t & 3;
        int c = (ec < 2) ? (2 + ec) : (130 + ec);
        int gy = y0 - 2 + ry, gx = x0 - 4 + c;
        if (gy < 0 || gy >= NYg || gx < 0) { sbu[ry][c] = UB; sbv[ry][c] = 0.0f; }
        else if (gx < NXg) {
            int r = ry + 1;
            float umm=su[r-1][c-1], um0=su[r-1][c], ump=su[r-1][c+1];
            float u0m=su[r  ][c-1], u00=su[r  ][c], u0p=su[r  ][c+1];
            float upm=su[r+1][c-1], up0=su[r+1][c], upp=su[r+1][c+1];
            float vmm=sv[r-1][c-1], vm0=sv[r-1][c], vmp=sv[r-1][c+1];
            float v0m=sv[r  ][c-1], v00=sv[r  ][c], v0p=sv[r  ][c+1];
            float vpm=sv[r+1][c-1], vp0=sv[r+1][c], vpp=sv[r+1][c+1];
            float pmm=sp[r-1][c-1], pm0=sp[r-1][c], pmp=sp[r-1][c+1];
            float p0m=sp[r  ][c-1],                  p0p=sp[r  ][c+1];
            float ppm=sp[r+1][c-1], pp0=sp[r+1][c], ppp=sp[r+1][c+1];
            float ADx_u = (-umm + ump - 4.0f*u0m + 4.0f*u0p - upm + upp) * C12;
            float ADy_u = (-umm - 4.0f*um0 - ump + upm + 4.0f*up0 + upp) * C12;
            float AD2_u = (umm + um0 + ump + u0m + u0p + upm + up0 + upp - 8.0f*u00) * C3;
            float ADx_v = (-vmm + vmp - 4.0f*v0m + 4.0f*v0p - vpm + vpp) * C12;
            float ADy_v = (-vmm - 4.0f*vm0 - vmp + vpm + 4.0f*vp0 + vpp) * C12;
            float AD2_v = (vmm + vm0 + vmp + v0m + v0p + vpm + vp0 + vpp - 8.0f*v00) * C3;
            float Gx = (-pmm + pmp - 4.0f*p0m + 4.0f*p0p - ppm + ppp) * (C12 * DT);
            float Gy = (-pmm - 4.0f*pm0 - pmp + ppm + 4.0f*pp0 + ppp) * (C12 * DT);
            float damp = 1.0f / (1.0f + DT * sig[gy * NXg + gx]);
            sbu[ry][c] = (u00 + 0.5f*(NU*AD2_u*DT - u00*ADx_u*DT - v00*ADy_u*DT) - Gx) * damp;
            sbv[ry][c] = (v00 + 0.5f*(NU*AD2_v*DT - u00*ADx_v*DT - v00*ADy_v*DT) - Gy) * damp;
        }
    }
    __syncthreads();
    if (x0 + 128 == NXg && t < 12) { sbu[t][132] = sbu[t][131]; sbv[t][132] = sbv[t][131]; }
    __syncthreads();

    for (int idx = t; idx < 10 * 32; idx += 256) {
        int ry = idx >> 5, q = idx & 31;
        int c = 4 + 4 * q;
        int gy = y0 - 1 + ry;
        if (gy < 0 || gy >= NYg) {
            *(float4*)&su2[ry][c] = make_float4(UB, UB, UB, UB);
            *(float4*)&sv2[ry][c] = make_float4(0.f, 0.f, 0.f, 0.f);
            continue;
        }
        int rb = ry + 1, rp = ry + 2;
        float4 uo4 = *(const float4*)&su[rp][c];
        float4 vo4 = *(const float4*)&sv[rp][c];
        float4 bu4 = *(const float4*)&sbu[rb][c];
        float4 bv4 = *(const float4*)&sbv[rb][c];
        float uo[4] = {uo4.x, uo4.y, uo4.z, uo4.w};
        float vo[4] = {vo4.x, vo4.y, vo4.z, vo4.w};
        float bu0[4] = {bu4.x, bu4.y, bu4.z, bu4.w};
        float bv0[4] = {bv4.x, bv4.y, bv4.z, bv4.w};
        float ou[4], ov[4];
        {
            float R[3][6];
#pragma unroll
            for (int j = 0; j < 3; j++) {
                const float* rp_ = &sbu[rb - 1 + j][0];
                float4 m = *(const float4*)(rp_ + c);
                R[j][0]=rp_[c-1]; R[j][1]=m.x; R[j][2]=m.y; R[j][3]=m.z; R[j][4]=m.w; R[j][5]=rp_[c+4];
            }
#pragma unroll
            for (int k = 0; k < 4; k++) {
                float ADx = (R[0][k+2]-R[0][k] + 4.f*(R[1][k+2]-R[1][k]) + R[2][k+2]-R[2][k]) * C12;
                float ADy = (R[2][k]+4.f*R[2][k+1]+R[2][k+2] - R[0][k]-4.f*R[0][k+1]-R[0][k+2]) * C12;
                float c0 = R[1][k+1];
                float AD2 = (R[0][k]+R[0][k+1]+R[0][k+2]+R[1][k]+R[1][k+2]
                           + R[2][k]+R[2][k+1]+R[2][k+2] - 8.f*c0) * C3;
                ou[k] = uo[k] + NU*AD2*DT - bu0[k]*ADx*DT - bv0[k]*ADy*DT;
            }
        }
        {
            float R[3][6];
#pragma unroll
            for (int j = 0; j < 3; j++) {
                const float* rp_ = &sbv[rb - 1 + j][0];
                float4 m = *(const float4*)(rp_ + c);
                R[j][0]=rp_[c-1]; R[j][1]=m.x; R[j][2]=m.y; R[j][3]=m.z; R[j][4]=m.w; R[j][5]=rp_[c+4];
            }
#pragma unroll
            for (int k = 0; k < 4; k++) {
                float ADx = (R[0][k+2]-R[0][k] + 4.f*(R[1][k+2]-R[1][k]) + R[2][k+2]-R[2][k]) * C12;
                float ADy = (R[2][k]+4.f*R[2][k+1]+R[2][k+2] - R[0][k]-4.f*R[0][k+1]-R[0][k+2]) * C12;
                float c0 = R[1][k+1];
                float AD2 = (R[0][k]+R[0][k+1]+R[0][k+2]+R[1][k]+R[1][k+2]
                           + R[2][k]+R[2][k+1]+R[2][k+2] - 8.f*c0) * C3;
                ov[k] = vo[k] + NU*AD2*DT - bu0[k]*ADx*DT - bv0[k]*ADy*DT;
            }
        }
        {
            float R[3][6];
#pragma unroll
            for (int j = 0; j < 3; j++) {
                const float* rp_ = &sp[rp - 1 + j][0];
                float4 m = *(const float4*)(rp_ + c);
                R[j][0]=rp_[c-1]; R[j][1]=m.x; R[j][2]=m.y; R[j][3]=m.z; R[j][4]=m.w; R[j][5]=rp_[c+4];
            }
#pragma unroll
            for (int k = 0; k < 4; k++) {
                float Gx = (R[0][k+2]-R[0][k] + 4.f*(R[1][k+2]-R[1][k]) + R[2][k+2]-R[2][k]) * (C12 * DT);
                float Gy = (R[2][k]+4.f*R[2][k+1]+R[2][k+2] - R[0][k]-4.f*R[0][k+1]-R[0][k+2]) * (C12 * DT);
                ou[k] -= Gx; ov[k] -= Gy;
            }
        }
        float4 sg4 = *(const float4*)(sig + gy * NXg + (x0 - 4 + c));
        float sgv[4] = {sg4.x, sg4.y, sg4.z, sg4.w};
#pragma unroll
        for (int k = 0; k < 4; k++) {
            float damp = 1.0f / (1.0f + DT * sgv[k]);
            ou[k] *= damp; ov[k] *= damp;
        }
        *(float4*)&su2[ry][c] = make_float4(ou[0], ou[1], ou[2], ou[3]);
        *(float4*)&sv2[ry][c] = make_float4(ov[0], ov[1], ov[2], ov[3]);
    }
    if (t < 20) {
        int ry = t >> 1;
        int c = (t & 1) ? 132 : 3;
        int gy = y0 - 1 + ry, gx = x0 - 4 + c;
        if (gy < 0 || gy >= NYg || gx < 0) { su2[ry][c] = UB; sv2[ry][c] = 0.0f; }
        else if (gx < NXg) {
            int rb = ry + 1, rp = ry + 2;
            float umm=sbu[rb-1][c-1], um0=sbu[rb-1][c], ump=sbu[rb-1][c+1];
            float u0m=sbu[rb  ][c-1], bu0=sbu[rb  ][c], u0p=sbu[rb  ][c+1];
            float upm=sbu[rb+1][c-1], up0=sbu[rb+1][c], upp=sbu[rb+1][c+1];
            float vmm=sbv[rb-1][c-1], vm0=sbv[rb-1][c], vmp=sbv[rb-1][c+1];
            float v0m=sbv[rb  ][c-1], bv0=sbv[rb  ][c], v0p=sbv[rb  ][c+1];
            float vpm=sbv[rb+1][c-1], vp0=sbv[rb+1][c], vpp=sbv[rb+1][c+1];
            float pmm=sp[rp-1][c-1], pm0=sp[rp-1][c], pmp=sp[rp-1][c+1];
            float p0m=sp[rp  ][c-1],                  p0p=sp[rp  ][c+1];
            float ppm=sp[rp+1][c-1], pp0=sp[rp+1][c], ppp=sp[rp+1][c+1];
            float ADx_u = (-umm + ump - 4.0f*u0m + 4.0f*u0p - upm + upp) * C12;
            float ADy_u = (-umm - 4.0f*um0 - ump + upm + 4.0f*up0 + upp) * C12;
            float AD2_u = (umm + um0 + ump + u0m + u0p + upm + up0 + upp - 8.0f*bu0) * C3;
            float ADx_v = (-vmm + vmp - 4.0f*v0m + 4.0f*v0p - vpm + vpp) * C12;
            float ADy_v = (-vmm - 4.0f*vm0 - vmp + vpm + 4.0f*vp0 + vpp) * C12;
            float AD2_v = (vmm + vm0 + vmp + v0m + v0p + vpm + vp0 + vpp - 8.0f*bv0) * C3;
            float Gx = (-pmm + pmp - 4.0f*p0m + 4.0f*p0p - ppm + ppp) * (C12 * DT);
            float Gy = (-pmm - 4.0f*pm0 - pmp + ppm + 4.0f*pp0 + ppp) * (C12 * DT);
            float damp = 1.0f / (1.0f + DT * sig[gy * NXg + gx]);
            su2[ry][c] = (su[rp][c] + NU*AD2_u*DT - bu0*ADx_u*DT - bv0*ADy_u*DT - Gx) * damp;
            sv2[ry][c] = (sv[rp][c] + NU*AD2_v*DT - bu0*ADx_v*DT - bv0*ADy_v*DT - Gy) * damp;
        }
    }
    __syncthreads();
    if (x0 + 128 == NXg && t < 10) { su2[t][132] = su2[t][131]; sv2[t][132] = sv2[t][131]; }
    __syncthreads();

    int ty = t >> 5, tx = t & 31;
    int gy = y0 + ty, gxb = x0 + tx * 4;
    int i = gy * NXg + gxb;
    float ob[4], ou[4], ov[4];
#pragma unroll
    for (int k = 0; k < 4; k++) {
        int c = tx * 4 + k + 4;
        float dudx = (-su2[ty][c-1] + su2[ty][c+1] - 4.0f*su2[ty+1][c-1] + 4.0f*su2[ty+1][c+1]
                      - su2[ty+2][c-1] + su2[ty+2][c+1]) * C12;
        float dvdy = (-sv2[ty][c-1] - 4.0f*sv2[ty][c] - sv2[ty][c+1]
                      + sv2[ty+2][c-1] + 4.0f*sv2[ty+2][c] + sv2[ty+2][c+1]) * C12;
        ob[k] = -(dudx + dvdy) * (1.0f / DT);
        ou[k] = su2[ty+1][c];
        ov[k] = sv2[ty+1][c];
    }
    *(float4*)(bg  + i) = make_float4(ob[0], ob[1], ob[2], ob[3]);
    *(float4*)(u2g + i) = make_float4(ou[0], ou[1], ou[2], ou[3]);
    *(float4*)(v2g + i) = make_float4(ov[0], ov[1], ov[2], ov[3]);
    __syncthreads();
#pragma unroll
    for (int k = 0; k < 4; k++) sb[ty * 130 + tx * 4 + k] = ob[k];
    __syncthreads();

    {
        int ry = t >> 6, rx = t & 63;
        int fy = 2 * ry, fx = 2 * rx;
        float s[4][4];
#pragma unroll
        for (int r = 0; r < 4; r++)
#pragma unroll
            for (int c = 0; c < 4; c++)
                s[r][c] = sp[fy + r + 2][fx + 3 + c];
        float h[4][2];
#pragma unroll
        for (int r = 0; r < 4; r++) {
            h[r][0] = s[r][0] + s[r][1] + s[r][2];
            h[r][1] = s[r][1] + s[r][2] + s[r][3];
        }
        float b00 = sb[fy * 130 + fx],       b01 = sb[fy * 130 + fx + 1];
        float b10 = sb[(fy + 1) * 130 + fx], b11 = sb[(fy + 1) * 130 + fx + 1];
        float acc = 0.0f;
        acc += (h[0][0] + h[1][0] + h[2][0] - 9.0f * s[1][1]) * C3 - b00;
        acc += (h[0][1] + h[1][1] + h[2][1] - 9.0f * s[1][2]) * C3 - b01;
        acc += (h[1][0] + h[2][0] + h[3][0] - 9.0f * s[2][1]) * C3 - b10;
        acc += (h[1][1] + h[2][1] + h[3][1] - 9.0f * s[2][2]) * C3 - b11;
        rr_pyramid(0.25f * acc, blockIdx.x, blockIdx.y, t, r1o, r2o, r3o, s1, s2);
    }
}

// ---------- coarse pyramid: r3 -> ... -> A5 (shortened chain) ----------
__global__ __launch_bounds__(1024) void k_coarse(
    const float* __restrict__ r3, float* __restrict__ A5g)
{
    __shared__ float sr5[32 * 64];
    __shared__ float sr6[16 * 32], sr7[8 * 16], sr8[4 * 8], sr9[8];
    __shared__ float sA10[2], sA9[8], sA8[32], sA7[128], sA6[512];
    int t = threadIdx.x;

    cudaTriggerProgrammaticLaunchCompletion();
    cudaGridDependencySynchronize();

    for (int i = t; i < 2048; i += 1024) {
        int y = i >> 6, x = i & 63;
        float s = 0.0f;
#pragma unroll
        for (int dy = 0; dy < 4; dy++) {
            float4 q = *(const float4*)(r3 + (4 * y + dy) * 256 + 4 * x);
            s += q.x + q.y + q.z + q.w;
        }
        sr5[i] = 0.0625f * s;
    }
    __syncthreads();

    if (t < 512) {
        int y = t >> 5, x = t & 31;
        sr6[t] = 0.25f * (sr5[(2*y)*64 + 2*x] + sr5[(2*y)*64 + 2*x + 1]
                        + sr5[(2*y+1)*64 + 2*x] + sr5[(2*y+1)*64 + 2*x + 1]);
    } else if (t < 640) {
        int i = t - 512; int y = i >> 4, x = i & 15;
        float s = 0.0f;
#pragma unroll
        for (int dy = 0; dy < 4; dy++)
#pragma unroll
            for (int dx = 0; dx < 4; dx++)
                s += sr5[(4*y + dy)*64 + 4*x + dx];
        sr7[i] = 0.0625f * s;
    } else if (t < 672) {
        int i = t - 640; int y = i >> 3, x = i & 7;
        float s = 0.0f;
        for (int dy = 0; dy < 8; dy++)
#pragma unroll
            for (int dx = 0; dx < 8; dx++)
                s += sr5[(8*y + dy)*64 + 8*x + dx];
        sr8[i] = 0.015625f * s;
    }
    __syncthreads();

    if (t < 32) {
        if (t < 8) {
            int y = t >> 2, x = t & 3;
            sr9[t] = 0.25f * (sr8[(2*y)*8 + 2*x] + sr8[(2*y)*8 + 2*x + 1]
                            + sr8[(2*y+1)*8 + 2*x] + sr8[(2*y+1)*8 + 2*x + 1]);
        }
        __syncwarp();
        if (t < 2) {
            float r10 = 0.25f * (sr9[2*t] + sr9[2*t + 1] + sr9[4 + 2*t] + sr9[4 + 2*t + 1]);
            sA10[t] = -0.375f * r10;
        }
        __syncwarp();
        if (t < 8) {
            int y = t >> 2, x = t & 3;
            float S = 0.0f;
#pragma unroll
            for (int dy = -1; dy <= 1; dy++)
#pragma unroll
                for (int dx = -1; dx <= 1; dx++) {
                    if (dy == 0 && dx == 0) continue;
                    int yy = y + dy, xx = x + dx;
                    if (yy >= 0 && yy < 2 && xx >= 0 && xx < 4) S += sA10[xx >> 1];
                }
            sA9[t] = 0.125f * S - 0.375f * sr9[t];
        }
        __syncwarp();
        {
            int y = t >> 3, x = t & 7;
            float S = 0.0f;
#pragma unroll
            for (int dy = -1; dy <= 1; dy++)
#pragma unroll
                for (int dx = -1; dx <= 1; dx++) {
                    if (dy == 0 && dx == 0) continue;
                    int yy = y + dy, xx = x + dx;
                    if (yy >= 0 && yy < 4 && xx >= 0 && xx < 8) S += sA9[(yy >> 1) * 4 + (xx >> 1)];
                }
            sA8[t] = 0.125f * S - 0.375f * sr8[t];
        }
    }
    __syncthreads();

    if (t < 128) {
        int y = t >> 4, x = t & 15;
        float S = 0.0f;
#pragma unroll
        for (int dy = -1; dy <= 1; dy++)
#pragma unroll
            for (int dx = -1; dx <= 1; dx++) {
                if (dy == 0 && dx == 0) continue;
                int yy = y + dy, xx = x + dx;
                if (yy >= 0 && yy < 8 && xx >= 0 && xx < 16) S += sA8[(yy >> 1) * 8 + (xx >> 1)];
            }
        sA7[t] = 0.125f * S - 0.375f * sr7[t];
    }
    __syncthreads();
    if (t < 512) {
        int y = t >> 5, x = t & 31;
        float S = 0.0f;
#pragma unroll
        for (int dy = -1; dy <= 1; dy++)
#pragma unroll
            for (int dx = -1; dx <= 1; dx++) {
                if (dy == 0 && dx == 0) continue;
                int yy = y + dy, xx = x + dx;
                if (yy >= 0 && yy < 16 && xx >= 0 && xx < 32) S += sA7[(yy >> 1) * 16 + (xx >> 1)];
            }
        sA6[t] = 0.125f * S - 0.375f * sr6[t];
    }
    __syncthreads();
    for (int i = t; i < 2048; i += 1024) {   // A5 -> global (final level here)
        int y = i >> 6, x = i & 63;
        float S = 0.0f;
#pragma unroll
        for (int dy = -1; dy <= 1; dy++)
#pragma unroll
            for (int dx = -1; dx <= 1; dx++) {
                if (dy == 0 && dx == 0) continue;
                int yy = y + dy, xx = x + dx;
                if (yy >= 0 && yy < 32 && xx >= 0 && xx < 64) S += sA6[(yy >> 1) * 32 + (xx >> 1)];
            }
        A5g[i] = 0.125f * S - 0.375f * sr5[i];
    }
}

// ============ fused up-sweep (A4 local) + fine smooth + (residual pyramid | projection) ============
template<bool FINAL>
__global__ __launch_bounds__(256) void k_up(
    const float* __restrict__ p, const float* __restrict__ b,
    const float* __restrict__ r1, const float* __restrict__ r2,
    const float* __restrict__ r3, const float* __restrict__ A5,
    float* __restrict__ pn,
    float* __restrict__ r1o, float* __restrict__ r2o, float* __restrict__ r3o,
    const float* __restrict__ u2, const float* __restrict__ v2,
    const float* __restrict__ sig, float* __restrict__ out)
{
    __shared__ float sp[12][136];
    __shared__ float spn[10][136];
    __shared__ float sA1[8][68];
    __shared__ float sA2[6][36];
    __shared__ float sA3[5][20];
    __shared__ float sA4[4][12];
    __shared__ float sA5s[4][8];
    __shared__ float sr4[48];
    __shared__ float s1[4 * 64];
    __shared__ float s2[2 * 32];

    int bx = blockIdx.x, by = blockIdx.y;
    int x0 = bx * 128, y0 = by * 8;
    int t = threadIdx.x;
    int y4b = (by - 3) >> 1, x4b = 8 * bx - 2;
    int y5b = (y4b - 1) >> 1, x5b = (x4b - 1) >> 1;
    int y3b = by - 2,        x3b = 16 * bx - 2;
    int y2b = 2 * by - 2,    x2b = 32 * bx - 2;
    int y1b = 4 * by - 2,    x1b = 64 * bx - 2;

    // ================= PREAMBLE (independent of k_coarse's A5) =================
    for (int idx = t; idx < 12 * 34; idx += 256) {
        int ry = idx / 34, rc = idx - ry * 34;
        int gy = y0 - 2 + ry, gx = x0 - 4 + rc * 4;
        float4 c;
        if (gy >= 0 && gy < NYg && gx >= 0 && gx + 3 < NXg)
            c = *(const float4*)(p + gy * NXg + gx);
        else
            c = make_float4(ldP(p,gy,gx), ldP(p,gy,gx+1), ldP(p,gy,gx+2), ldP(p,gy,gx+3));
        *(float4*)&sp[ry][rc * 4] = c;
    }
    float rv3 = 0.0f, rv2 = 0.0f, rv1[3] = {0.0f, 0.0f, 0.0f};
    if (t < 100) {
        int ly = t / 20, lx = t - ly * 20;
        int y3 = y3b + ly, x3 = x3b + lx;
        if (y3 >= 0 && y3 < 128 && x3 >= 0 && x3 < 256) rv3 = r3[y3 * 256 + x3];
    }
    if (t < 216) {
        int ly = t / 36, lx = t - ly * 36;
        int y2 = y2b + ly, x2 = x2b + lx;
        if (y2 >= 0 && y2 < 256 && x2 >= 0 && x2 < 512) rv2 = r2[y2 * 512 + x2];
    }
#pragma unroll
    for (int j = 0; j < 3; j++) {
        int i = t + j * 256;
        if (i < 8 * 68) {
            int ly = i / 68, lx = i - ly * 68;
            int y1 = y1b + ly, x1 = x1b + lx;
            if (x1 < 1024) {
                int y1c = min(max(y1, 0), 511), x1c = max(x1, 0);
                rv1[j] = r1[y1c * 1024 + x1c];
            }
        }
    }
    // r4 patch (from r3, written >=2 kernels back — safe pre-sync)
    if (t < 48) {
        int ly = t / 12, lx = t - ly * 12;
        int y4 = y4b + ly, x4 = x4b + lx;
        float v = 0.0f;
        if (y4 >= 0 && y4 < 64 && x4 >= 0 && x4 < 128) {
            const float* q = r3 + (2 * y4) * 256 + 2 * x4;
            v = 0.25f * (q[0] + q[1] + q[256] + q[257]);
        }
        sr4[t] = v;
    }
    __syncthreads();

    // staging: T = 0.125*S8(bc_p(p)) - 0.375*b for all 10 rows (quads)
    for (int idx = t; idx < 320; idx += 256) {
        int ry = idx >> 5, q = idx & 31;
        int gy = y0 - 1 + ry;
        if (gy < 0 || gy >= NYg) continue;
        int r = ry + 1;
        int c = 4 + 4 * q;
        float row[3][6];
#pragma unroll
        for (int j = 0; j < 3; j++) {
            const float* rp_ = &sp[r - 1 + j][0];
            float4 m = *(const float4*)(rp_ + c);
            row[j][0] = rp_[c - 1];
            row[j][1] = m.x; row[j][2] = m.y; row[j][3] = m.z; row[j][4] = m.w;
            row[j][5] = rp_[c + 4];
        }
        float h[6];
#pragma unroll
        for (int j = 0; j < 6; j++) h[j] = row[0][j] + row[1][j] + row[2][j];
        float4 b4 = *(const float4*)(b + gy * NXg + x0 + 4 * q);
        float bb[4] = {b4.x, b4.y, b4.z, b4.w};
        float T[4];
#pragma unroll
        for (int k = 0; k < 4; k++) {
            float S8 = h[k] + h[k + 1] + h[k + 2] - row[1][k + 1];
            T[k] = 0.125f * S8 - 0.375f * bb[k];
        }
        *(float4*)&spn[ry][c] = make_float4(T[0], T[1], T[2], T[3]);
    }
    if (t < 20) {
        int ry = t >> 1;
        int c = (t & 1) ? 132 : 3;
        int gy = y0 - 1 + ry, gx = x0 - 4 + c;
        if (gy >= 0 && gy < NYg && gx >= 0 && gx < NXg) {
            int r = ry + 1;
            float S = sp[r-1][c-1] + sp[r-1][c] + sp[r-1][c+1]
                    + sp[r  ][c-1] +              sp[r  ][c+1]
                    + sp[r+1][c-1] + sp[r+1][c] + sp[r+1][c+1];
            spn[ry][c] = 0.125f * S - 0.375f * b[gy * NXg + gx];
        }
    }

    // ================= wait for k_coarse (A5) =================
    cudaGridDependencySynchronize();

    if (t < 32) {
        int ly = t >> 3, lx = t & 7;
        int y5 = y5b + ly, x5 = x5b + lx;
        sA5s[ly][lx] = (y5 >= 0 && y5 < 32 && x5 >= 0 && x5 < 64) ? A5[y5 * 64 + x5] : 0.0f;
    }
    __syncthreads();
    if (t < 48) {
        int ly = t / 12, lx = t - ly * 12;
        int y4 = y4b + ly, x4 = x4b + lx;
        float val = 0.0f;
        if (y4 >= 0 && y4 < 64 && x4 >= 0 && x4 < 128)
            val = 0.125f * prolong_S8(&sA5s[0][0], 8, y5b, x5b, y4, x4) - 0.375f * sr4[t];
        sA4[ly][lx] = val;
    }
    __syncthreads();

    if (t < 100) {
        int ly = t / 20, lx = t - ly * 20;
        int y3 = y3b + ly, x3 = x3b + lx;
        float val = 0.0f;
        if (y3 >= 0 && y3 < 128 && x3 >= 0 && x3 < 256)
            val = 0.125f * prolong_S8(&sA4[0][0], 12, y4b, x4b, y3, x3) - 0.375f * rv3;
        sA3[ly][lx] = val;
    }
    __syncthreads();
    if (t < 216) {
        int ly = t / 36, lx = t - ly * 36;
        int y2 = y2b + ly, x2 = x2b + lx;
        float val = 0.0f;
        if (y2 >= 0 && y2 < 256 && x2 >= 0 && x2 < 512)
            val = 0.125f * prolong_S8(&sA3[0][0], 20, y3b, x3b, y2, x2) - 0.375f * rv2;
        sA2[ly][lx] = val;
    }
    __syncthreads();
#pragma unroll
    for (int j = 0; j < 3; j++) {
        int i = t + j * 256;
        if (i < 8 * 68) {
            int ly = i / 68, lx = i - ly * 68;
            int y1 = y1b + ly, x1 = x1b + lx;
            float val = 0.0f;
            if (x1 < 1024) {
                int y1c = min(max(y1, 0), 511), x1c = max(x1, 0);
                val = 0.125f * prolong_S8(&sA2[0][0], 36, y2b, x2b, y1c, x1c) - 0.375f * rv1[j];
            }
            sA1[ly][lx] = val;
        }
    }
    __syncthreads();

    // finalize: pn = T - 0.125*Sa
    for (int idx = t; idx < 320; idx += 256) {
        int ry = idx >> 5, q = idx & 31;
        int gy = y0 - 1 + ry;
        if (gy < 0 || gy >= NYg) continue;
        int c = 4 + 4 * q;
        int gxb = x0 + 4 * q;
        float4 tv = *(const float4*)&spn[ry][c];
        float T[4] = {tv.x, tv.y, tv.z, tv.w};
        int py = gy & 1;
        int r0 = ((gy - 1) >> 1) - y1b;
        int C  = (gxb >> 1) - x1b;
        const float* R0 = &sA1[r0][0];
        const float* R1 = &sA1[r0 + 1][0];
        const float* Rc = py ? R0 : R1;
        float w0 = py ? 2.0f : 1.0f, w1 = 3.0f - w0;
        float rs[4];
#pragma unroll
        for (int j = 0; j < 4; j++) rs[j] = w0 * R0[C - 1 + j] + w1 * R1[C - 1 + j];
        float Sa[4];
        Sa[0] = rs[0] + 2.0f * rs[1] - Rc[C];
        Sa[1] = 2.0f * rs[1] + rs[2] - Rc[C];
        Sa[2] = rs[1] + 2.0f * rs[2] - Rc[C + 1];
        Sa[3] = 2.0f * rs[2] + rs[3] - Rc[C + 1];
        *(float4*)&spn[ry][c] = make_float4(T[0] - 0.125f * Sa[0], T[1] - 0.125f * Sa[1],
                                            T[2] - 0.125f * Sa[2], T[3] - 0.125f * Sa[3]);
    }
    if (t < 20) {
        int ry = t >> 1;
        int c = (t & 1) ? 132 : 3;
        int gy = y0 - 1 + ry, gx = x0 - 4 + c;
        if (gy >= 0 && gy < NYg && gx >= 0 && gx < NXg) {
            float Sa = prolong_S8(&sA1[0][0], 68, y1b, x1b, gy, gx);
            spn[ry][c] -= 0.125f * Sa;
        }
    }
    __syncthreads();
    if (t < 10) {
        if (bx == 0) {
            int src = (by == 0 && t == 0) ? 1 : ((by == 127 && t == 9) ? 8 : t);
            spn[t][3] = spn[src][4];
        }
        if (bx == 15) spn[t][132] = 0.0f;
    }
    if (by == 0) {
        for (int c = t; c < 130; c += 256) {
            float v;
            if (c == 0 && bx == 0)         v = spn[1][4];
            else if (c == 129 && bx == 15) v = 0.0f;
            else                           v = spn[1][c + 3];
            spn[0][c + 3] = v;
        }
    }
    if (by == 127) {
        for (int c = t; c < 130; c += 256) {
            float v;
            if (c == 0 && bx == 0)         v = spn[8][4];
            else if (c == 129 && bx == 15) v = 0.0f;
            else                           v = spn[8][c + 3];
            spn[9][c + 3] = v;
        }
    }
    __syncthreads();

    int ty = t >> 5, tx = t & 31;
    int gy2 = y0 + ty;
    int gxb2 = x0 + tx * 4;

    if constexpr (!FINAL) {
        int i = gy2 * NXg + gxb2;
        *(float4*)(pn + i) = *(float4*)&spn[ty + 1][4 + tx * 4];
        int ry = t >> 6, rx = t & 63;
        int fy = 2 * ry, fx = 2 * rx;
        float s[4][4];
#pragma unroll
        for (int r = 0; r < 4; r++)
#pragma unroll
            for (int c = 0; c < 4; c++)
                s[r][c] = spn[fy + r][fx + 3 + c];
        float h2[4][2];
#pragma unroll
        for (int r = 0; r < 4; r++) {
            h2[r][0] = s[r][0] + s[r][1] + s[r][2];
            h2[r][1] = s[r][1] + s[r][2] + s[r][3];
        }
        float2 b0 = *(const float2*)(b + (y0 + fy) * NXg + x0 + fx);
        float2 b1 = *(const float2*)(b + (y0 + fy + 1) * NXg + x0 + fx);
        float acc = 0.0f;
        acc += (h2[0][0] + h2[1][0] + h2[2][0] - 9.0f * s[1][1]) * C3 - b0.x;
        acc += (h2[0][1] + h2[1][1] + h2[2][1] - 9.0f * s[1][2]) * C3 - b0.y;
        acc += (h2[1][0] + h2[2][0] + h2[3][0] - 9.0f * s[2][1]) * C3 - b1.x;
        acc += (h2[1][1] + h2[2][1] + h2[3][1] - 9.0f * s[2][2]) * C3 - b1.y;
        rr_pyramid(0.25f * acc, bx, by, t, r1o, r2o, r3o, s1, s2);
    } else {
        int i = gy2 * NXg + gxb2;
        float4 s4 = *(const float4*)(sig + i);
        float4 u4 = *(const float4*)(u2 + i);
        float4 v4 = *(const float4*)(v2 + i);
        float sg[4] = {s4.x, s4.y, s4.z, s4.w};
        float uu[4] = {u4.x, u4.y, u4.z, u4.w};
        float vv[4] = {v4.x, v4.y, v4.z, v4.w};
        float ou[4], ov[4], op[4];
#pragma unroll
        for (int k = 0; k < 4; k++) {
            int c = tx * 4 + k + 4, r = ty + 1;
            float pmm = spn[r-1][c-1], pm0 = spn[r-1][c], pmp = spn[r-1][c+1];
            float p0m = spn[r  ][c-1],                     p0p = spn[r  ][c+1];
            float ppm = spn[r+1][c-1], pp0 = spn[r+1][c], ppp = spn[r+1][c+1];
            float Gx = (-pmm + pmp - 4.0f*p0m + 4.0f*p0p - ppm + ppp) * (C12 * DT);
            float Gy = (-pmm - 4.0f*pm0 - pmp + ppm + 4.0f*pp0 + ppp) * (C12 * DT);
            float damp = 1.0f / (1.0f + DT * sg[k]);
            ou[k] = (uu[k] - Gx) * damp;
            ov[k] = (vv[k] - Gy) * damp;
            op[k] = spn[r][c];
        }
        *(float4*)(out + i)            = make_float4(ou[0], ou[1], ou[2], ou[3]);
        *(float4*)(out + N0 + i)       = make_float4(ov[0], ov[1], ov[2], ov[3]);
        *(float4*)(out + 2 * N0 + i)   = make_float4(op[0], op[1], op[2], op[3]);
    }
}

static float* symaddr(const void* s) {
    void* ptr = nullptr;
    cudaGetSymbolAddress(&ptr, s);
    return (float*)ptr;
}

extern "C" void kernel_launch(void* const* d_in, const int* in_sizes, int n_in,
                              void* d_out, int out_size)
{
    const float* u   = (const float*)d_in[0];
    const float* v   = (const float*)d_in[1];
    const float* p   = (const float*)d_in[2];
    const float* sig = (const float*)d_in[3];
    float* out = (float*)d_out;

    float* u2  = symaddr(g_u2);  float* v2  = symaddr(g_v2);
    float* b   = symaddr(g_b);
    float* pa  = symaddr(g_pa);  float* pb  = symaddr(g_pb);
    float* r1a = symaddr(g_r1a); float* r1b = symaddr(g_r1b);
    float* r2a = symaddr(g_r2a); float* r2b = symaddr(g_r2b);
    float* r3a = symaddr(g_r3a); float* r3b = symaddr(g_r3b);
    float* A5  = symaddr(g_A5);

    cudaLaunchAttribute attrs[1];
    attrs[0].id = cudaLaunchAttributeProgrammaticStreamSerialization;
    attrs[0].val.programmaticStreamSerializationAllowed = 1;

    cudaLaunchConfig_t cfg = {};
    cfg.stream = (cudaStream_t)0;
    cfg.attrs = attrs;
    cfg.numAttrs = 1;

    cfg.gridDim = dim3(16, 128);
    cfg.blockDim = dim3(32, 8);
    cudaLaunchKernelEx(&cfg, k_mom, u, v, p, sig, u2, v2, b, r1a, r2a, r3a);

    const float* pc = p;
    float* pn = pa;
    for (int it = 0; it < 5; it++) {
        bool even = (it & 1) == 0;
        float* r1i = even ? r1a : r1b; float* r1o = even ? r1b : r1a;
        float* r2i = even ? r2a : r2b; float* r2o = even ? r2b : r2a;
        float* r3i = even ? r3a : r3b; float* r3o = even ? r3b : r3a;

        cfg.gridDim = dim3(1, 1, 1);
        cfg.blockDim = dim3(1024, 1, 1);
        cudaLaunchKernelEx(&cfg, k_coarse, (const float*)r3i, A5);

        cfg.gridDim = dim3(16, 128);
        cfg.blockDim = dim3(256, 1, 1);
        if (it < 4) {
            cudaLaunchKernelEx(&cfg, k_up<false>,
                pc, (const float*)b, (const float*)r1i, (const float*)r2i,
                (const float*)r3i, (const float*)A5, pn, r1o, r2o, r3o,
                (const float*)nullptr, (const float*)nullptr,
                (const float*)nullptr, (float*)nullptr);
            pc = pn;
            pn = (pn == pa) ? pb : pa;
        } else {
            cudaLaunchKernelEx(&cfg, k_up<true>,
                pc, (const float*)b, (const float*)r1i, (const float*)r2i,
                (const float*)r3i, (const float*)A5, (float*)nullptr,
                (float*)nullptr, (float*)nullptr, (float*)nullptr,
                (const float*)u2, (const float*)v2, (const float*)sig, out);
        }
    }
}

// round 13
// speedup vs baseline: 1.0687x; 1.0687x over previous
#include <cuda_runtime.h>

constexpr int NYg = 1024;
constexpr int NXg = 2048;
constexpr int N0  = NYg * NXg;
constexpr float DT = 0.1f;
constexpr float NU = 0.01f;
constexpr float UB = 1.0f;
constexpr float C12 = 1.0f / 12.0f;
constexpr float C3  = 1.0f / 3.0f;

__device__ float g_u2[N0];
__device__ float g_v2[N0];
__device__ float g_b [N0];
__device__ float g_pa[N0];
__device__ float g_pb[N0];
__device__ float g_r1a[512 * 1024];
__device__ float g_r1b[512 * 1024];
__device__ float g_r2a[256 * 512];
__device__ float g_r2b[256 * 512];
__device__ float g_r3a[128 * 256];
__device__ float g_r3b[128 * 256];
__device__ float g_A4[64 * 128];

// ---------- boundary-condition loaders ----------
__device__ __forceinline__ float ldU(const float* __restrict__ u, int y, int x) {
    if (y < 0 || y >= NYg) return UB;
    if (x < 0) return UB;
    if (x >= NXg) return u[y * NXg + NXg - 1];
    return u[y * NXg + x];
}
__device__ __forceinline__ float ldV(const float* __restrict__ v, int y, int x) {
    if (x >= NXg) { if (y < 0 || y >= NYg) return 0.0f; return v[y * NXg + NXg - 1]; }
    if (y < 0 || y >= NYg || x < 0) return 0.0f;
    return v[y * NXg + x];
}
__device__ __forceinline__ float ldP(const float* __restrict__ p, int y, int x) {
    if (x >= NXg) return 0.0f;
    int yy = min(max(y, 0), NYg - 1);
    int xx = max(x, 0);
    return p[yy * NXg + xx];
}

// generic prolong S8: sum of 3x3 neighborhood (excl. center) of NN-upsampled A
__device__ __forceinline__ float prolong_S8(const float* __restrict__ A, int stride,
                                            int yb, int xb, int y, int x)
{
    int r0 = ((y - 1) >> 1) - yb;
    int c0 = ((x - 1) >> 1) - xb;
    int py = y & 1, px = x & 1;
    float wr0 = (float)(1 + py), wr1 = (float)(2 - py);
    float wc0 = (float)(1 + px), wc1 = (float)(2 - px);
    const float* row0 = A + r0 * stride + c0;
    const float* row1 = row0 + stride;
    float V00 = row0[0], V01 = row0[1], V10 = row1[0], V11 = row1[1];
    float S9 = wr0 * (wc0 * V00 + wc1 * V01) + wr1 * (wc0 * V10 + wc1 * V11);
    float ctr = py ? (px ? V00 : V01) : (px ? V10 : V11);
    return S9 - ctr;
}

// restriction pyramid from per-thread r1 value
__device__ __forceinline__ void rr_pyramid(float r1v, int bx, int by, int t,
    float* __restrict__ r1o, float* __restrict__ r2o, float* __restrict__ r3o,
    float* __restrict__ s1, float* __restrict__ s2)
{
    int ry = t >> 6, rx = t & 63;
    r1o[(4 * by + ry) * 1024 + 64 * bx + rx] = r1v;
    s1[ry * 64 + rx] = r1v;
    __syncthreads();
    if (t < 64) {
        int ty = t >> 5, tx = t & 31;
        float v = 0.25f * (s1[2*ty*64 + 2*tx] + s1[2*ty*64 + 2*tx + 1]
                         + s1[(2*ty+1)*64 + 2*tx] + s1[(2*ty+1)*64 + 2*tx + 1]);
        r2o[(2 * by + ty) * 512 + 32 * bx + tx] = v;
        s2[ty * 32 + tx] = v;
    }
    __syncthreads();
    if (t < 16) {
        float v = 0.25f * (s2[2*t] + s2[2*t + 1] + s2[32 + 2*t] + s2[32 + 2*t + 1]);
        r3o[by * 256 + 16 * bx + t] = v;
    }
}

// ============ fused momentum + divergence + initial residual pyramid ============
__global__ __launch_bounds__(256) void k_mom(
    const float* __restrict__ u, const float* __restrict__ v,
    const float* __restrict__ p, const float* __restrict__ sig,
    float* __restrict__ u2g, float* __restrict__ v2g, float* __restrict__ bg,
    float* __restrict__ r1o, float* __restrict__ r2o, float* __restrict__ r3o)
{
    __shared__ float su[14][136], sv[14][136], sp[14][136];
    __shared__ float sbu[12][136], sbv[12][136];
    __shared__ float su2[10][136], sv2[10][136];
    float* sb = &sbu[0][0];
    float* s1 = sb + 8 * 130;
    float* s2 = s1 + 256;

    cudaGridDependencySynchronize();

    int x0 = blockIdx.x * 128, y0 = blockIdx.y * 8;
    int t = threadIdx.y * 32 + threadIdx.x;

    for (int idx = t; idx < 14 * 34; idx += 256) {
        int ry = idx / 34, rc = idx - ry * 34;
        int gy = y0 - 3 + ry, gx = x0 - 4 + rc * 4;
        float4 a, bb, c;
        if (gy >= 0 && gy < NYg && gx >= 0 && gx + 3 < NXg) {
            a  = *(const float4*)(u + gy * NXg + gx);
            bb = *(const float4*)(v + gy * NXg + gx);
            c  = *(const float4*)(p + gy * NXg + gx);
        } else {
            a  = make_float4(ldU(u,gy,gx), ldU(u,gy,gx+1), ldU(u,gy,gx+2), ldU(u,gy,gx+3));
            bb = make_float4(ldV(v,gy,gx), ldV(v,gy,gx+1), ldV(v,gy,gx+2), ldV(v,gy,gx+3));
            c  = make_float4(ldP(p,gy,gx), ldP(p,gy,gx+1), ldP(p,gy,gx+2), ldP(p,gy,gx+3));
        }
        *(float4*)&su[ry][rc*4] = a;
        *(float4*)&sv[ry][rc*4] = bb;
        *(float4*)&sp[ry][rc*4] = c;
    }
    __syncthreads();

    for (int idx = t; idx < 12 * 32; idx += 256) {
        int ry = idx >> 5, q = idx & 31;
        int c = 4 + 4 * q;
        int gy = y0 - 2 + ry;
        if (gy < 0 || gy >= NYg) {
            *(float4*)&sbu[ry][c] = make_float4(UB, UB, UB, UB);
            *(float4*)&sbv[ry][c] = make_float4(0.f, 0.f, 0.f, 0.f);
            continue;
        }
        int r = ry + 1;
        float4 vc4 = *(const float4*)&sv[r][c];
        float v00[4] = {vc4.x, vc4.y, vc4.z, vc4.w};
        float u00[4], obu[4], obv[4];
        {
            float R[3][6];
#pragma unroll
            for (int j = 0; j < 3; j++) {
                const float* rp_ = &su[r - 1 + j][0];
                float4 m = *(const float4*)(rp_ + c);
                R[j][0]=rp_[c-1]; R[j][1]=m.x; R[j][2]=m.y; R[j][3]=m.z; R[j][4]=m.w; R[j][5]=rp_[c+4];
            }
#pragma unroll
            for (int k = 0; k < 4; k++) {
                float ADx = (R[0][k+2]-R[0][k] + 4.f*(R[1][k+2]-R[1][k]) + R[2][k+2]-R[2][k]) * C12;
                float ADy = (R[2][k]+4.f*R[2][k+1]+R[2][k+2] - R[0][k]-4.f*R[0][k+1]-R[0][k+2]) * C12;
                float c0 = R[1][k+1];
                float AD2 = (R[0][k]+R[0][k+1]+R[0][k+2]+R[1][k]+R[1][k+2]
                           + R[2][k]+R[2][k+1]+R[2][k+2] - 8.f*c0) * C3;
                u00[k] = c0;
                obu[k] = c0 + 0.5f*(NU*AD2*DT - c0*ADx*DT - v00[k]*ADy*DT);
            }
        }
        {
            float R[3][6];
#pragma unroll
            for (int j = 0; j < 3; j++) {
                const float* rp_ = &sv[r - 1 + j][0];
                float4 m = *(const float4*)(rp_ + c);
                R[j][0]=rp_[c-1]; R[j][1]=m.x; R[j][2]=m.y; R[j][3]=m.z; R[j][4]=m.w; R[j][5]=rp_[c+4];
            }
#pragma unroll
            for (int k = 0; k < 4; k++) {
                float ADx = (R[0][k+2]-R[0][k] + 4.f*(R[1][k+2]-R[1][k]) + R[2][k+2]-R[2][k]) * C12;
                float ADy = (R[2][k]+4.f*R[2][k+1]+R[2][k+2] - R[0][k]-4.f*R[0][k+1]-R[0][k+2]) * C12;
                float c0 = R[1][k+1];
                float AD2 = (R[0][k]+R[0][k+1]+R[0][k+2]+R[1][k]+R[1][k+2]
                           + R[2][k]+R[2][k+1]+R[2][k+2] - 8.f*c0) * C3;
                obv[k] = c0 + 0.5f*(NU*AD2*DT - u00[k]*ADx*DT - c0*ADy*DT);
            }
        }
        {
            float R[3][6];
#pragma unroll
            for (int j = 0; j < 3; j++) {
                const float* rp_ = &sp[r - 1 + j][0];
                float4 m = *(const float4*)(rp_ + c);
                R[j][0]=rp_[c-1]; R[j][1]=m.x; R[j][2]=m.y; R[j][3]=m.z; R[j][4]=m.w; R[j][5]=rp_[c+4];
            }
#pragma unroll
            for (int k = 0; k < 4; k++) {
                float Gx = (R[0][k+2]-R[0][k] + 4.f*(R[1][k+2]-R[1][k]) + R[2][k+2]-R[2][k]) * (C12 * DT);
                float Gy = (R[2][k]+4.f*R[2][k+1]+R[2][k+2] - R[0][k]-4.f*R[0][k+1]-R[0][k+2]) * (C12 * DT);
                obu[k] -= Gx; obv[k] -= Gy;
            }
        }
        float4 sg4 = *(const float4*)(sig + gy * NXg + (x0 - 4 + c));
        float sgv[4] = {sg4.x, sg4.y, sg4.z, sg4.w};
#pragma unroll
        for (int k = 0; k < 4; k++) {
            float damp = 1.0f / (1.0f + DT * sgv[k]);
            obu[k] *= damp; obv[k] *= damp;
        }
        *(float4*)&sbu[ry][c] = make_float4(obu[0], obu[1], obu[2], obu[3]);
        *(float4*)&sbv[ry][c] = make_float4(obv[0], obv[1], obv[2], obv[3]);
    }
    if (t < 48) {
        int ry = t >> 2, ec = t & 3;
        int c = (ec < 2) ? (2 + ec) : (130 + ec);
        int gy = y0 - 2 + ry, gx = x0 - 4 + c;
        if (gy < 0 || gy >= NYg || gx < 0) { sbu[ry][c] = UB; sbv[ry][c] = 0.0f; }
        else if (gx < NXg) {
            int r = ry + 1;
            float umm=su[r-1][c-1], um0=su[r-1][c], ump=su[r-1][c+1];
            float u0m=su[r  ][c-1], u00=su[r  ][c], u0p=su[r  ][c+1];
            float upm=su[r+1][c-1], up0=su[r+1][c], upp=su[r+1][c+1];
            float vmm=sv[r-1][c-1], vm0=sv[r-1][c], vmp=sv[r-1][c+1];
            float v0m=sv[r  ][c-1], v00=sv[r  ][c], v0p=sv[r  ][c+1];
            float vpm=sv[r+1][c-1], vp0=sv[r+1][c], vpp=sv[r+1][c+1];
            float pmm=sp[r-1][c-1], pm0=sp[r-1][c], pmp=sp[r-1][c+1];
            float p0m=sp[r  ][c-1],                  p0p=sp[r  ][c+1];
            float ppm=sp[r+1][c-1], pp0=sp[r+1][c], ppp=sp[r+1][c+1];
            float ADx_u = (-umm + ump - 4.0f*u0m + 4.0f*u0p - upm + upp) * C12;
            float ADy_u = (-umm - 4.0f*um0 - ump + upm + 4.0f*up0 + upp) * C12;
            float AD2_u = (umm + um0 + ump + u0m + u0p + upm + up0 + upp - 8.0f*u00) * C3;
            float ADx_v = (-vmm + vmp - 4.0f*v0m + 4.0f*v0p - vpm + vpp) * C12;
            float ADy_v = (-vmm - 4.0f*vm0 - vmp + vpm + 4.0f*vp0 + vpp) * C12;
            float AD2_v = (vmm + vm0 + vmp + v0m + v0p + vpm + vp0 + vpp - 8.0f*v00) * C3;
            float Gx = (-pmm + pmp - 4.0f*p0m + 4.0f*p0p - ppm + ppp) * (C12 * DT);
            float Gy = (-pmm - 4.0f*pm0 - pmp + ppm + 4.0f*pp0 + ppp) * (C12 * DT);
            float damp = 1.0f / (1.0f + DT * sig[gy * NXg + gx]);
            sbu[ry][c] = (u00 + 0.5f*(NU*AD2_u*DT - u00*ADx_u*DT - v00*ADy_u*DT) - Gx) * damp;
            sbv[ry][c] = (v00 + 0.5f*(NU*AD2_v*DT - u00*ADx_v*DT - v00*ADy_v*DT) - Gy) * damp;
        }
    }
    __syncthreads();
    if (x0 + 128 == NXg && t < 12) { sbu[t][132] = sbu[t][131]; sbv[t][132] = sbv[t][131]; }
    __syncthreads();

    for (int idx = t; idx < 10 * 32; idx += 256) {
        int ry = idx >> 5, q = idx & 31;
        int c = 4 + 4 * q;
        int gy = y0 - 1 + ry;
        if (gy < 0 || gy >= NYg) {
            *(float4*)&su2[ry][c] = make_float4(UB, UB, UB, UB);
            *(float4*)&sv2[ry][c] = make_float4(0.f, 0.f, 0.f, 0.f);
            continue;
        }
        int rb = ry + 1, rp = ry + 2;
        float4 uo4 = *(const float4*)&su[rp][c];
        float4 vo4 = *(const float4*)&sv[rp][c];
        float4 bu4 = *(const float4*)&sbu[rb][c];
        float4 bv4 = *(const float4*)&sbv[rb][c];
        float uo[4] = {uo4.x, uo4.y, uo4.z, uo4.w};
        float vo[4] = {vo4.x, vo4.y, vo4.z, vo4.w};
        float bu0[4] = {bu4.x, bu4.y, bu4.z, bu4.w};
        float bv0[4] = {bv4.x, bv4.y, bv4.z, bv4.w};
        float ou[4], ov[4];
        {
            float R[3][6];
#pragma unroll
            for (int j = 0; j < 3; j++) {
                const float* rp_ = &sbu[rb - 1 + j][0];
                float4 m = *(const float4*)(rp_ + c);
                R[j][0]=rp_[c-1]; R[j][1]=m.x; R[j][2]=m.y; R[j][3]=m.z; R[j][4]=m.w; R[j][5]=rp_[c+4];
            }
#pragma unroll
            for (int k = 0; k < 4; k++) {
                float ADx = (R[0][k+2]-R[0][k] + 4.f*(R[1][k+2]-R[1][k]) + R[2][k+2]-R[2][k]) * C12;
                float ADy = (R[2][k]+4.f*R[2][k+1]+R[2][k+2] - R[0][k]-4.f*R[0][k+1]-R[0][k+2]) * C12;
                float c0 = R[1][k+1];
                float AD2 = (R[0][k]+R[0][k+1]+R[0][k+2]+R[1][k]+R[1][k+2]
                           + R[2][k]+R[2][k+1]+R[2][k+2] - 8.f*c0) * C3;
                ou[k] = uo[k] + NU*AD2*DT - bu0[k]*ADx*DT - bv0[k]*ADy*DT;
            }
        }
        {
            float R[3][6];
#pragma unroll
            for (int j = 0; j < 3; j++) {
                const float* rp_ = &sbv[rb - 1 + j][0];
                float4 m = *(const float4*)(rp_ + c);
                R[j][0]=rp_[c-1]; R[j][1]=m.x; R[j][2]=m.y; R[j][3]=m.z; R[j][4]=m.w; R[j][5]=rp_[c+4];
            }
#pragma unroll
            for (int k = 0; k < 4; k++) {
                float ADx = (R[0][k+2]-R[0][k] + 4.f*(R[1][k+2]-R[1][k]) + R[2][k+2]-R[2][k]) * C12;
                float ADy = (R[2][k]+4.f*R[2][k+1]+R[2][k+2] - R[0][k]-4.f*R[0][k+1]-R[0][k+2]) * C12;
                float c0 = R[1][k+1];
                float AD2 = (R[0][k]+R[0][k+1]+R[0][k+2]+R[1][k]+R[1][k+2]
                           + R[2][k]+R[2][k+1]+R[2][k+2] - 8.f*c0) * C3;
                ov[k] = vo[k] + NU*AD2*DT - bu0[k]*ADx*DT - bv0[k]*ADy*DT;
            }
        }
        {
            float R[3][6];
#pragma unroll
            for (int j = 0; j < 3; j++) {
                const float* rp_ = &sp[rp - 1 + j][0];
                float4 m = *(const float4*)(rp_ + c);
                R[j][0]=rp_[c-1]; R[j][1]=m.x; R[j][2]=m.y; R[j][3]=m.z; R[j][4]=m.w; R[j][5]=rp_[c+4];
            }
#pragma unroll
            for (int k = 0; k < 4; k++) {
                float Gx = (R[0][k+2]-R[0][k] + 4.f*(R[1][k+2]-R[1][k]) + R[2][k+2]-R[2][k]) * (C12 * DT);
                float Gy = (R[2][k]+4.f*R[2][k+1]+R[2][k+2] - R[0][k]-4.f*R[0][k+1]-R[0][k+2]) * (C12 * DT);
                ou[k] -= Gx; ov[k] -= Gy;
            }
        }
        float4 sg4 = *(const float4*)(sig + gy * NXg + (x0 - 4 + c));
        float sgv[4] = {sg4.x, sg4.y, sg4.z, sg4.w};
#pragma unroll
        for (int k = 0; k < 4; k++) {
            float damp = 1.0f / (1.0f + DT * sgv[k]);
            ou[k] *= damp; ov[k] *= damp;
        }
        *(float4*)&su2[ry][c] = make_float4(ou[0], ou[1], ou[2], ou[3]);
        *(float4*)&sv2[ry][c] = make_float4(ov[0], ov[1], ov[2], ov[3]);
    }
    if (t < 20) {
        int ry = t >> 1;
        int c = (t & 1) ? 132 : 3;
        int gy = y0 - 1 + ry, gx = x0 - 4 + c;
        if (gy < 0 || gy >= NYg || gx < 0) { su2[ry][c] = UB; sv2[ry][c] = 0.0f; }
        else if (gx < NXg) {
            int rb = ry + 1, rp = ry + 2;
            float umm=sbu[rb-1][c-1], um0=sbu[rb-1][c], ump=sbu[rb-1][c+1];
            float u0m=sbu[rb  ][c-1], bu0=sbu[rb  ][c], u0p=sbu[rb  ][c+1];
            float upm=sbu[rb+1][c-1], up0=sbu[rb+1][c], upp=sbu[rb+1][c+1];
            float vmm=sbv[rb-1][c-1], vm0=sbv[rb-1][c], vmp=sbv[rb-1][c+1];
            float v0m=sbv[rb  ][c-1], bv0=sbv[rb  ][c], v0p=sbv[rb  ][c+1];
            float vpm=sbv[rb+1][c-1], vp0=sbv[rb+1][c], vpp=sbv[rb+1][c+1];
            float pmm=sp[rp-1][c-1], pm0=sp[rp-1][c], pmp=sp[rp-1][c+1];
            float p0m=sp[rp  ][c-1],                  p0p=sp[rp  ][c+1];
            float ppm=sp[rp+1][c-1], pp0=sp[rp+1][c], ppp=sp[rp+1][c+1];
            float ADx_u = (-umm + ump - 4.0f*u0m + 4.0f*u0p - upm + upp) * C12;
            float ADy_u = (-umm - 4.0f*um0 - ump + upm + 4.0f*up0 + upp) * C12;
            float AD2_u = (umm + um0 + ump + u0m + u0p + upm + up0 + upp - 8.0f*bu0) * C3;
            float ADx_v = (-vmm + vmp - 4.0f*v0m + 4.0f*v0p - vpm + vpp) * C12;
            float ADy_v = (-vmm - 4.0f*vm0 - vmp + vpm + 4.0f*vp0 + vpp) * C12;
            float AD2_v = (vmm + vm0 + vmp + v0m + v0p + vpm + vp0 + vpp - 8.0f*bv0) * C3;
            float Gx = (-pmm + pmp - 4.0f*p0m + 4.0f*p0p - ppm + ppp) * (C12 * DT);
            float Gy = (-pmm - 4.0f*pm0 - pmp + ppm + 4.0f*pp0 + ppp) * (C12 * DT);
            float damp = 1.0f / (1.0f + DT * sig[gy * NXg + gx]);
            su2[ry][c] = (su[rp][c] + NU*AD2_u*DT - bu0*ADx_u*DT - bv0*ADy_u*DT - Gx) * damp;
            sv2[ry][c] = (sv[rp][c] + NU*AD2_v*DT - bu0*ADx_v*DT - bv0*ADy_v*DT - Gy) * damp;
        }
    }
    __syncthreads();
    if (x0 + 128 == NXg && t < 10) { su2[t][132] = su2[t][131]; sv2[t][132] = sv2[t][131]; }
    __syncthreads();

    int ty = t >> 5, tx = t & 31;
    int gy = y0 + ty, gxb = x0 + tx * 4;
    int i = gy * NXg + gxb;
    float ob[4], ou[4], ov[4];
#pragma unroll
    for (int k = 0; k < 4; k++) {
        int c = tx * 4 + k + 4;
        float dudx = (-su2[ty][c-1] + su2[ty][c+1] - 4.0f*su2[ty+1][c-1] + 4.0f*su2[ty+1][c+1]
                      - su2[ty+2][c-1] + su2[ty+2][c+1]) * C12;
        float dvdy = (-sv2[ty][c-1] - 4.0f*sv2[ty][c] - sv2[ty][c+1]
                      + sv2[ty+2][c-1] + 4.0f*sv2[ty+2][c] + sv2[ty+2][c+1]) * C12;
        ob[k] = -(dudx + dvdy) * (1.0f / DT);
        ou[k] = su2[ty+1][c];
        ov[k] = sv2[ty+1][c];
    }
    *(float4*)(bg  + i) = make_float4(ob[0], ob[1], ob[2], ob[3]);
    *(float4*)(u2g + i) = make_float4(ou[0], ou[1], ou[2], ou[3]);
    *(float4*)(v2g + i) = make_float4(ov[0], ov[1], ov[2], ov[3]);
    __syncthreads();
#pragma unroll
    for (int k = 0; k < 4; k++) sb[ty * 130 + tx * 4 + k] = ob[k];
    __syncthreads();

    {
        int ry = t >> 6, rx = t & 63;
        int fy = 2 * ry, fx = 2 * rx;
        float s[4][4];
#pragma unroll
        for (int r = 0; r < 4; r++)
#pragma unroll
            for (int c = 0; c < 4; c++)
                s[r][c] = sp[fy + r + 2][fx + 3 + c];
        float h[4][2];
#pragma unroll
        for (int r = 0; r < 4; r++) {
            h[r][0] = s[r][0] + s[r][1] + s[r][2];
            h[r][1] = s[r][1] + s[r][2] + s[r][3];
        }
        float b00 = sb[fy * 130 + fx],       b01 = sb[fy * 130 + fx + 1];
        float b10 = sb[(fy + 1) * 130 + fx], b11 = sb[(fy + 1) * 130 + fx + 1];
        float acc = 0.0f;
        acc += (h[0][0] + h[1][0] + h[2][0] - 9.0f * s[1][1]) * C3 - b00;
        acc += (h[0][1] + h[1][1] + h[2][1] - 9.0f * s[1][2]) * C3 - b01;
        acc += (h[1][0] + h[2][0] + h[3][0] - 9.0f * s[2][1]) * C3 - b10;
        acc += (h[1][1] + h[2][1] + h[3][1] - 9.0f * s[2][2]) * C3 - b11;
        rr_pyramid(0.25f * acc, blockIdx.x, blockIdx.y, t, r1o, r2o, r3o, s1, s2);
    }
}

// ---------- coarse pyramid: r3 -> ... -> A4 (r4 cached, prolong up-sweep) ----------
__global__ __launch_bounds__(1024) void k_coarse(
    const float* __restrict__ r3, float* __restrict__ A4g)
{
    __shared__ float sr4[64 * 128];                  // cached during r5 pass
    __shared__ float sr5[32 * 64];
    __shared__ float sr6[16 * 32], sr7[8 * 16], sr8[4 * 8], sr9[8];
    __shared__ float sA10[2], sA9[8], sA8[32];
    __shared__ float sA7h[10][18];                   // 8x16 + zero halo, base (-1,-1)
    __shared__ float sA6h[18][34];                   // 16x32 + zero halo
    __shared__ float sA5h[34][66];                   // 32x64 + zero halo
    int t = threadIdx.x;

    // zero the halo arrays fully (cheap; before dependency work)
    for (int i = t; i < 10 * 18; i += 1024) (&sA7h[0][0])[i] = 0.0f;
    for (int i = t; i < 18 * 34; i += 1024) (&sA6h[0][0])[i] = 0.0f;
    for (int i = t; i < 34 * 66; i += 1024) (&sA5h[0][0])[i] = 0.0f;

    cudaTriggerProgrammaticLaunchCompletion();
    cudaGridDependencySynchronize();

    // r5 (and r4 cache) from r3
    for (int i = t; i < 2048; i += 1024) {
        int y = i >> 6, x = i & 63;
        float4 q0 = *(const float4*)(r3 + (4 * y    ) * 256 + 4 * x);
        float4 q1 = *(const float4*)(r3 + (4 * y + 1) * 256 + 4 * x);
        float4 q2 = *(const float4*)(r3 + (4 * y + 2) * 256 + 4 * x);
        float4 q3 = *(const float4*)(r3 + (4 * y + 3) * 256 + 4 * x);
        float a00 = q0.x + q0.y + q1.x + q1.y;
        float a01 = q0.z + q0.w + q1.z + q1.w;
        float a10 = q2.x + q2.y + q3.x + q3.y;
        float a11 = q2.z + q2.w + q3.z + q3.w;
        sr4[(2*y) * 128 + 2*x]     = 0.25f * a00;
        sr4[(2*y) * 128 + 2*x + 1] = 0.25f * a01;
        sr4[(2*y+1) * 128 + 2*x]     = 0.25f * a10;
        sr4[(2*y+1) * 128 + 2*x + 1] = 0.25f * a11;
        sr5[i] = 0.0625f * (a00 + a01 + a10 + a11);
    }
    __syncthreads();

    // redundant down-sweep r6/r7/r8 from sr5 (one sync)
    if (t < 512) {
        int y = t >> 5, x = t & 31;
        sr6[t] = 0.25f * (sr5[(2*y)*64 + 2*x] + sr5[(2*y)*64 + 2*x + 1]
                        + sr5[(2*y+1)*64 + 2*x] + sr5[(2*y+1)*64 + 2*x + 1]);
    } else if (t < 640) {
        int i = t - 512; int y = i >> 4, x = i & 15;
        float s = 0.0f;
#pragma unroll
        for (int dy = 0; dy < 4; dy++)
#pragma unroll
            for (int dx = 0; dx < 4; dx++)
                s += sr5[(4*y + dy)*64 + 4*x + dx];
        sr7[i] = 0.0625f * s;
    } else if (t < 672) {
        int i = t - 640; int y = i >> 3, x = i & 7;
        float s = 0.0f;
        for (int dy = 0; dy < 8; dy++)
#pragma unroll
            for (int dx = 0; dx < 8; dx++)
                s += sr5[(8*y + dy)*64 + 8*x + dx];
        sr8[i] = 0.015625f * s;
    }
    __syncthreads();

    // warp 0: r9, r10, A10, A9, A8
    if (t < 32) {
        if (t < 8) {
            int y = t >> 2, x = t & 3;
            sr9[t] = 0.25f * (sr8[(2*y)*8 + 2*x] + sr8[(2*y)*8 + 2*x + 1]
                            + sr8[(2*y+1)*8 + 2*x] + sr8[(2*y+1)*8 + 2*x + 1]);
        }
        __syncwarp();
        if (t < 2) {
            float r10 = 0.25f * (sr9[2*t] + sr9[2*t + 1] + sr9[4 + 2*t] + sr9[4 + 2*t + 1]);
            sA10[t] = -0.375f * r10;
        }
        __syncwarp();
        if (t < 8) {
            int y = t >> 2, x = t & 3;
            float S = 0.0f;
#pragma unroll
            for (int dy = -1; dy <= 1; dy++)
#pragma unroll
                for (int dx = -1; dx <= 1; dx++) {
                    if (dy == 0 && dx == 0) continue;
                    int yy = y + dy, xx = x + dx;
                    if (yy >= 0 && yy < 2 && xx >= 0 && xx < 4) S += sA10[xx >> 1];
                }
            sA9[t] = 0.125f * S - 0.375f * sr9[t];
        }
        __syncwarp();
        {
            int y = t >> 3, x = t & 7;
            float S = 0.0f;
#pragma unroll
            for (int dy = -1; dy <= 1; dy++)
#pragma unroll
                for (int dx = -1; dx <= 1; dx++) {
                    if (dy == 0 && dx == 0) continue;
                    int yy = y + dy, xx = x + dx;
                    if (yy >= 0 && yy < 4 && xx >= 0 && xx < 8) S += sA9[(yy >> 1) * 4 + (xx >> 1)];
                }
            sA8[t] = 0.125f * S - 0.375f * sr8[t];
        }
    }
    __syncthreads();

    if (t < 128) {   // A7: 8x16, bounds-checked gather over sA8 (cheap), into halo'd array
        int y = t >> 4, x = t & 15;
        float S = 0.0f;
#pragma unroll
        for (int dy = -1; dy <= 1; dy++)
#pragma unroll
            for (int dx = -1; dx <= 1; dx++) {
                if (dy == 0 && dx == 0) continue;
                int yy = y + dy, xx = x + dx;
                if (yy >= 0 && yy < 8 && xx >= 0 && xx < 16) S += sA8[(yy >> 1) * 8 + (xx >> 1)];
            }
        sA7h[1 + y][1 + x] = 0.125f * S - 0.375f * sr7[t];
    }
    __syncthreads();
    if (t < 512) {   // A6: 16x32 via prolong over zero-halo A7
        int y = t >> 5, x = t & 31;
        sA6h[1 + y][1 + x] = 0.125f * prolong_S8(&sA7h[1][1], 18, 0, 0, y, x)
                           - 0.375f * sr6[t];
    }
    __syncthreads();
    for (int i = t; i < 2048; i += 1024) {   // A5: 32x64 via prolong
        int y = i >> 6, x = i & 63;
        sA5h[1 + y][1 + x] = 0.125f * prolong_S8(&sA6h[1][1], 34, 0, 0, y, x)
                           - 0.375f * sr5[i];
    }
    __syncthreads();
    for (int i = t; i < 64 * 128; i += 1024) {   // A4: 64x128 via prolong, r4 from smem
        int y = i >> 7, x = i & 127;
        A4g[i] = 0.125f * prolong_S8(&sA5h[1][1], 66, 0, 0, y, x)
               - 0.375f * sr4[i];
    }
}

// ============ fused up-sweep + fine smooth + (residual pyramid | projection) ============
template<bool FINAL>
__global__ __launch_bounds__(256) void k_up(
    const float* __restrict__ p, const float* __restrict__ b,
    const float* __restrict__ r1, const float* __restrict__ r2,
    const float* __restrict__ r3, const float* __restrict__ A4,
    float* __restrict__ pn,
    float* __restrict__ r1o, float* __restrict__ r2o, float* __restrict__ r3o,
    const float* __restrict__ u2, const float* __restrict__ v2,
    const float* __restrict__ sig, float* __restrict__ out)
{
    __shared__ float sp[12][136];
    __shared__ float spn[10][136];
    __shared__ float sA1[8][68];
    __shared__ float sA2[6][36];
    __shared__ float sA3[5][20];
    __shared__ float sA4[4][12];
    __shared__ float s1[4 * 64];
    __shared__ float s2[2 * 32];

    int bx = blockIdx.x, by = blockIdx.y;
    int x0 = bx * 128, y0 = by * 8;
    int t = threadIdx.x;
    int y4b = (by - 3) >> 1, x4b = 8 * bx - 2;
    int y3b = by - 2,        x3b = 16 * bx - 2;
    int y2b = 2 * by - 2,    x2b = 32 * bx - 2;
    int y1b = 4 * by - 2,    x1b = 64 * bx - 2;

    // ================= PREAMBLE (independent of k_coarse's A4) =================
    for (int idx = t; idx < 12 * 34; idx += 256) {
        int ry = idx / 34, rc = idx - ry * 34;
        int gy = y0 - 2 + ry, gx = x0 - 4 + rc * 4;
        float4 c;
        if (gy >= 0 && gy < NYg && gx >= 0 && gx + 3 < NXg)
            c = *(const float4*)(p + gy * NXg + gx);
        else
            c = make_float4(ldP(p,gy,gx), ldP(p,gy,gx+1), ldP(p,gy,gx+2), ldP(p,gy,gx+3));
        *(float4*)&sp[ry][rc * 4] = c;
    }
    float rv3 = 0.0f, rv2 = 0.0f, rv1[3] = {0.0f, 0.0f, 0.0f};
    if (t < 100) {
        int ly = t / 20, lx = t - ly * 20;
        int y3 = y3b + ly, x3 = x3b + lx;
        if (y3 >= 0 && y3 < 128 && x3 >= 0 && x3 < 256) rv3 = r3[y3 * 256 + x3];
    }
    if (t < 216) {
        int ly = t / 36, lx = t - ly * 36;
        int y2 = y2b + ly, x2 = x2b + lx;
        if (y2 >= 0 && y2 < 256 && x2 >= 0 && x2 < 512) rv2 = r2[y2 * 512 + x2];
    }
#pragma unroll
    for (int j = 0; j < 3; j++) {
        int i = t + j * 256;
        if (i < 8 * 68) {
            int ly = i / 68, lx = i - ly * 68;
            int y1 = y1b + ly, x1 = x1b + lx;
            if (x1 < 1024) {
                int y1c = min(max(y1, 0), 511), x1c = max(x1, 0);
                rv1[j] = r1[y1c * 1024 + x1c];
            }
        }
    }
    __syncthreads();

    // staging: T = 0.125*S8(bc_p(p)) - 0.375*b for all 10 rows (quads)
    for (int idx = t; idx < 320; idx += 256) {
        int ry = idx >> 5, q = idx & 31;
        int gy = y0 - 1 + ry;
        if (gy < 0 || gy >= NYg) continue;
        int r = ry + 1;
        int c = 4 + 4 * q;
        float row[3][6];
#pragma unroll
        for (int j = 0; j < 3; j++) {
            const float* rp_ = &sp[r - 1 + j][0];
            float4 m = *(const float4*)(rp_ + c);
            row[j][0] = rp_[c - 1];
            row[j][1] = m.x; row[j][2] = m.y; row[j][3] = m.z; row[j][4] = m.w;
            row[j][5] = rp_[c + 4];
        }
        float h[6];
#pragma unroll
        for (int j = 0; j < 6; j++) h[j] = row[0][j] + row[1][j] + row[2][j];
        float4 b4 = *(const float4*)(b + gy * NXg + x0 + 4 * q);
        float bb[4] = {b4.x, b4.y, b4.z, b4.w};
        float T[4];
#pragma unroll
        for (int k = 0; k < 4; k++) {
            float S8 = h[k] + h[k + 1] + h[k + 2] - row[1][k + 1];
            T[k] = 0.125f * S8 - 0.375f * bb[k];
        }
        *(float4*)&spn[ry][c] = make_float4(T[0], T[1], T[2], T[3]);
    }
    if (t < 20) {
        int ry = t >> 1;
        int c = (t & 1) ? 132 : 3;
        int gy = y0 - 1 + ry, gx = x0 - 4 + c;
        if (gy >= 0 && gy < NYg && gx >= 0 && gx < NXg) {
            int r = ry + 1;
            float S = sp[r-1][c-1] + sp[r-1][c] + sp[r-1][c+1]
                    + sp[r  ][c-1] +              sp[r  ][c+1]
                    + sp[r+1][c-1] + sp[r+1][c] + sp[r+1][c+1];
            spn[ry][c] = 0.125f * S - 0.375f * b[gy * NXg + gx];
        }
    }

    // ================= wait for k_coarse (A4) =================
    cudaGridDependencySynchronize();

    if (t < 48) {
        int ly = t / 12, lx = t - ly * 12;
        int y4 = y4b + ly, x4 = x4b + lx;
        sA4[ly][lx] = (y4 >= 0 && y4 < 64 && x4 >= 0 && x4 < 128) ? A4[y4 * 128 + x4] : 0.0f;
    }
    __syncthreads();

    if (t < 100) {
        int ly = t / 20, lx = t - ly * 20;
        int y3 = y3b + ly, x3 = x3b + lx;
        float val = 0.0f;
        if (y3 >= 0 && y3 < 128 && x3 >= 0 && x3 < 256)
            val = 0.125f * prolong_S8(&sA4[0][0], 12, y4b, x4b, y3, x3) - 0.375f * rv3;
        sA3[ly][lx] = val;
    }
    __syncthreads();
    if (t < 216) {
        int ly = t / 36, lx = t - ly * 36;
        int y2 = y2b + ly, x2 = x2b + lx;
        float val = 0.0f;
        if (y2 >= 0 && y2 < 256 && x2 >= 0 && x2 < 512)
            val = 0.125f * prolong_S8(&sA3[0][0], 20, y3b, x3b, y2, x2) - 0.375f * rv2;
        sA2[ly][lx] = val;
    }
    __syncthreads();
#pragma unroll
    for (int j = 0; j < 3; j++) {
        int i = t + j * 256;
        if (i < 8 * 68) {
            int ly = i / 68, lx = i - ly * 68;
            int y1 = y1b + ly, x1 = x1b + lx;
            float val = 0.0f;
            if (x1 < 1024) {
                int y1c = min(max(y1, 0), 511), x1c = max(x1, 0);
                val = 0.125f * prolong_S8(&sA2[0][0], 36, y2b, x2b, y1c, x1c) - 0.375f * rv1[j];
            }
            sA1[ly][lx] = val;
        }
    }
    __syncthreads();

    // finalize: pn = T - 0.125*Sa
    for (int idx = t; idx < 320; idx += 256) {
        int ry = idx >> 5, q = idx & 31;
        int gy = y0 - 1 + ry;
        if (gy < 0 || gy >= NYg) continue;
        int c = 4 + 4 * q;
        int gxb = x0 + 4 * q;
        float4 tv = *(const float4*)&spn[ry][c];
        float T[4] = {tv.x, tv.y, tv.z, tv.w};
        int py = gy & 1;
        int r0 = ((gy - 1) >> 1) - y1b;
        int C  = (gxb >> 1) - x1b;
        const float* R0 = &sA1[r0][0];
        const float* R1 = &sA1[r0 + 1][0];
        const float* Rc = py ? R0 : R1;
        float w0 = py ? 2.0f : 1.0f, w1 = 3.0f - w0;
        float rs[4];
#pragma unroll
        for (int j = 0; j < 4; j++) rs[j] = w0 * R0[C - 1 + j] + w1 * R1[C - 1 + j];
        float Sa[4];
        Sa[0] = rs[0] + 2.0f * rs[1] - Rc[C];
        Sa[1] = 2.0f * rs[1] + rs[2] - Rc[C];
        Sa[2] = rs[1] + 2.0f * rs[2] - Rc[C + 1];
        Sa[3] = 2.0f * rs[2] + rs[3] - Rc[C + 1];
        *(float4*)&spn[ry][c] = make_float4(T[0] - 0.125f * Sa[0], T[1] - 0.125f * Sa[1],
                                            T[2] - 0.125f * Sa[2], T[3] - 0.125f * Sa[3]);
    }
    if (t < 20) {
        int ry = t >> 1;
        int c = (t & 1) ? 132 : 3;
        int gy = y0 - 1 + ry, gx = x0 - 4 + c;
        if (gy >= 0 && gy < NYg && gx >= 0 && gx < NXg) {
            float Sa = prolong_S8(&sA1[0][0], 68, y1b, x1b, gy, gx);
            spn[ry][c] -= 0.125f * Sa;
        }
    }
    __syncthreads();
    if (t < 10) {
        if (bx == 0) {
            int src = (by == 0 && t == 0) ? 1 : ((by == 127 && t == 9) ? 8 : t);
            spn[t][3] = spn[src][4];
        }
        if (bx == 15) spn[t][132] = 0.0f;
    }
    if (by == 0) {
        for (int c = t; c < 130; c += 256) {
            float v;
            if (c == 0 && bx == 0)         v = spn[1][4];
            else if (c == 129 && bx == 15) v = 0.0f;
            else                           v = spn[1][c + 3];
            spn[0][c + 3] = v;
        }
    }
    if (by == 127) {
        for (int c = t; c < 130; c += 256) {
            float v;
            if (c == 0 && bx == 0)         v = spn[8][4];
            else if (c == 129 && bx == 15) v = 0.0f;
            else                           v = spn[8][c + 3];
            spn[9][c + 3] = v;
        }
    }
    __syncthreads();

    int ty = t >> 5, tx = t & 31;
    int gy2 = y0 + ty;
    int gxb2 = x0 + tx * 4;

    if constexpr (!FINAL) {
        int i = gy2 * NXg + gxb2;
        *(float4*)(pn + i) = *(float4*)&spn[ty + 1][4 + tx * 4];
        int ry = t >> 6, rx = t & 63;
        int fy = 2 * ry, fx = 2 * rx;
        float s[4][4];
#pragma unroll
        for (int r = 0; r < 4; r++)
#pragma unroll
            for (int c = 0; c < 4; c++)
                s[r][c] = spn[fy + r][fx + 3 + c];
        float h2[4][2];
#pragma unroll
        for (int r = 0; r < 4; r++) {
            h2[r][0] = s[r][0] + s[r][1] + s[r][2];
            h2[r][1] = s[r][1] + s[r][2] + s[r][3];
        }
        float2 b0 = *(const float2*)(b + (y0 + fy) * NXg + x0 + fx);
        float2 b1 = *(const float2*)(b + (y0 + fy + 1) * NXg + x0 + fx);
        float acc = 0.0f;
        acc += (h2[0][0] + h2[1][0] + h2[2][0] - 9.0f * s[1][1]) * C3 - b0.x;
        acc += (h2[0][1] + h2[1][1] + h2[2][1] - 9.0f * s[1][2]) * C3 - b0.y;
        acc += (h2[1][0] + h2[2][0] + h2[3][0] - 9.0f * s[2][1]) * C3 - b1.x;
        acc += (h2[1][1] + h2[2][1] + h2[3][1] - 9.0f * s[2][2]) * C3 - b1.y;
        rr_pyramid(0.25f * acc, bx, by, t, r1o, r2o, r3o, s1, s2);
    } else {
        int i = gy2 * NXg + gxb2;
        float4 s4 = *(const float4*)(sig + i);
        float4 u4 = *(const float4*)(u2 + i);
        float4 v4 = *(const float4*)(v2 + i);
        float sg[4] = {s4.x, s4.y, s4.z, s4.w};
        float uu[4] = {u4.x, u4.y, u4.z, u4.w};
        float vv[4] = {v4.x, v4.y, v4.z, v4.w};
        float ou[4], ov[4], op[4];
#pragma unroll
        for (int k = 0; k < 4; k++) {
            int c = tx * 4 + k + 4, r = ty + 1;
            float pmm = spn[r-1][c-1], pm0 = spn[r-1][c], pmp = spn[r-1][c+1];
            float p0m = spn[r  ][c-1],                     p0p = spn[r  ][c+1];
            float ppm = spn[r+1][c-1], pp0 = spn[r+1][c], ppp = spn[r+1][c+1];
            float Gx = (-pmm + pmp - 4.0f*p0m + 4.0f*p0p - ppm + ppp) * (C12 * DT);
            float Gy = (-pmm - 4.0f*pm0 - pmp + ppm + 4.0f*pp0 + ppp) * (C12 * DT);
            float damp = 1.0f / (1.0f + DT * sg[k]);
            ou[k] = (uu[k] - Gx) * damp;
            ov[k] = (vv[k] - Gy) * damp;
            op[k] = spn[r][c];
        }
        *(float4*)(out + i)            = make_float4(ou[0], ou[1], ou[2], ou[3]);
        *(float4*)(out + N0 + i)       = make_float4(ov[0], ov[1], ov[2], ov[3]);
        *(float4*)(out + 2 * N0 + i)   = make_float4(op[0], op[1], op[2], op[3]);
    }
}

static float* symaddr(const void* s) {
    void* ptr = nullptr;
    cudaGetSymbolAddress(&ptr, s);
    return (float*)ptr;
}

extern "C" void kernel_launch(void* const* d_in, const int* in_sizes, int n_in,
                              void* d_out, int out_size)
{
    const float* u   = (const float*)d_in[0];
    const float* v   = (const float*)d_in[1];
    const float* p   = (const float*)d_in[2];
    const float* sig = (const float*)d_in[3];
    float* out = (float*)d_out;

    float* u2  = symaddr(g_u2);  float* v2  = symaddr(g_v2);
    float* b   = symaddr(g_b);
    float* pa  = symaddr(g_pa);  float* pb  = symaddr(g_pb);
    float* r1a = symaddr(g_r1a); float* r1b = symaddr(g_r1b);
    float* r2a = symaddr(g_r2a); float* r2b = symaddr(g_r2b);
    float* r3a = symaddr(g_r3a); float* r3b = symaddr(g_r3b);
    float* A4  = symaddr(g_A4);

    cudaLaunchAttribute attrs[1];
    attrs[0].id = cudaLaunchAttributeProgrammaticStreamSerialization;
    attrs[0].val.programmaticStreamSerializationAllowed = 1;

    cudaLaunchConfig_t cfg = {};
    cfg.stream = (cudaStream_t)0;
    cfg.attrs = attrs;
    cfg.numAttrs = 1;

    cfg.gridDim = dim3(16, 128);
    cfg.blockDim = dim3(32, 8);
    cudaLaunchKernelEx(&cfg, k_mom, u, v, p, sig, u2, v2, b, r1a, r2a, r3a);

    const float* pc = p;
    float* pn = pa;
    for (int it = 0; it < 5; it++) {
        bool even = (it & 1) == 0;
        float* r1i = even ? r1a : r1b; float* r1o = even ? r1b : r1a;
        float* r2i = even ? r2a : r2b; float* r2o = even ? r2b : r2a;
        float* r3i = even ? r3a : r3b; float* r3o = even ? r3b : r3a;

        cfg.gridDim = dim3(1, 1, 1);
        cfg.blockDim = dim3(1024, 1, 1);
        cudaLaunchKernelEx(&cfg, k_coarse, (const float*)r3i, A4);

        cfg.gridDim = dim3(16, 128);
        cfg.blockDim = dim3(256, 1, 1);
        if (it < 4) {
            cudaLaunchKernelEx(&cfg, k_up<false>,
                pc, (const float*)b, (const float*)r1i, (const float*)r2i,
                (const float*)r3i, (const float*)A4, pn, r1o, r2o, r3o,
                (const float*)nullptr, (const float*)nullptr,
                (const float*)nullptr, (float*)nullptr);
            pc = pn;
            pn = (pn == pa) ? pb : pa;
        } else {
            cudaLaunchKernelEx(&cfg, k_up<true>,
                pc, (const float*)b, (const float*)r1i, (const float*)r2i,
                (const float*)r3i, (const float*)A4, (float*)nullptr,
                (float*)nullptr, (float*)nullptr, (float*)nullptr,
                (const float*)u2, (const float*)v2, (const float*)sig, out);
        }
    }
}

// round 14
// speedup vs baseline: 1.1200x; 1.0480x over previous
#include <cuda_runtime.h>

constexpr int NYg = 1024;
constexpr int NXg = 2048;
constexpr int N0  = NYg * NXg;
constexpr float DT = 0.1f;
constexpr float NU = 0.01f;
constexpr float UB = 1.0f;
constexpr float C12 = 1.0f / 12.0f;
constexpr float C3  = 1.0f / 3.0f;

__device__ float g_u2[N0];
__device__ float g_v2[N0];
__device__ float g_b [N0];
__device__ float g_pa[N0];
__device__ float g_pb[N0];
__device__ float g_r1a[512 * 1024];
__device__ float g_r1b[512 * 1024];
__device__ float g_r2a[256 * 512];
__device__ float g_r2b[256 * 512];
__device__ float g_r3a[128 * 256];
__device__ float g_r3b[128 * 256];
__device__ float g_A4[64 * 128];

// ---------- boundary-condition loaders ----------
__device__ __forceinline__ float ldU(const float* __restrict__ u, int y, int x) {
    if (y < 0 || y >= NYg) return UB;
    if (x < 0) return UB;
    if (x >= NXg) return u[y * NXg + NXg - 1];
    return u[y * NXg + x];
}
__device__ __forceinline__ float ldV(const float* __restrict__ v, int y, int x) {
    if (x >= NXg) { if (y < 0 || y >= NYg) return 0.0f; return v[y * NXg + NXg - 1]; }
    if (y < 0 || y >= NYg || x < 0) return 0.0f;
    return v[y * NXg + x];
}
__device__ __forceinline__ float ldP(const float* __restrict__ p, int y, int x) {
    if (x >= NXg) return 0.0f;
    int yy = min(max(y, 0), NYg - 1);
    int xx = max(x, 0);
    return p[yy * NXg + xx];
}

// generic prolong S8: sum of 3x3 neighborhood (excl. center) of NN-upsampled A
__device__ __forceinline__ float prolong_S8(const float* __restrict__ A, int stride,
                                            int yb, int xb, int y, int x)
{
    int r0 = ((y - 1) >> 1) - yb;
    int c0 = ((x - 1) >> 1) - xb;
    int py = y & 1, px = x & 1;
    float wr0 = (float)(1 + py), wr1 = (float)(2 - py);
    float wc0 = (float)(1 + px), wc1 = (float)(2 - px);
    const float* row0 = A + r0 * stride + c0;
    const float* row1 = row0 + stride;
    float V00 = row0[0], V01 = row0[1], V10 = row1[0], V11 = row1[1];
    float S9 = wr0 * (wc0 * V00 + wc1 * V01) + wr1 * (wc0 * V10 + wc1 * V11);
    float ctr = py ? (px ? V00 : V01) : (px ? V10 : V11);
    return S9 - ctr;
}

// ============ fused momentum + divergence + initial residual pyramid ============
__global__ __launch_bounds__(256) void k_mom(
    const float* __restrict__ u, const float* __restrict__ v,
    const float* __restrict__ p, const float* __restrict__ sig,
    float* __restrict__ u2g, float* __restrict__ v2g, float* __restrict__ bg,
    float* __restrict__ r1o, float* __restrict__ r2o, float* __restrict__ r3o)
{
    __shared__ float su[14][136], sv[14][136], sp[14][136];
    __shared__ float sbu[12][136], sbv[12][136];
    __shared__ float su2[10][136], sv2[10][136];
    float* sb = &sbu[0][0];
    float* s1 = sb + 8 * 130;
    float* s2 = s1 + 256;

    cudaGridDependencySynchronize();

    int x0 = blockIdx.x * 128, y0 = blockIdx.y * 8;
    int t = threadIdx.y * 32 + threadIdx.x;

    for (int idx = t; idx < 14 * 34; idx += 256) {
        int ry = idx / 34, rc = idx - ry * 34;
        int gy = y0 - 3 + ry, gx = x0 - 4 + rc * 4;
        float4 a, bb, c;
        if (gy >= 0 && gy < NYg && gx >= 0 && gx + 3 < NXg) {
            a  = *(const float4*)(u + gy * NXg + gx);
            bb = *(const float4*)(v + gy * NXg + gx);
            c  = *(const float4*)(p + gy * NXg + gx);
        } else {
            a  = make_float4(ldU(u,gy,gx), ldU(u,gy,gx+1), ldU(u,gy,gx+2), ldU(u,gy,gx+3));
            bb = make_float4(ldV(v,gy,gx), ldV(v,gy,gx+1), ldV(v,gy,gx+2), ldV(v,gy,gx+3));
            c  = make_float4(ldP(p,gy,gx), ldP(p,gy,gx+1), ldP(p,gy,gx+2), ldP(p,gy,gx+3));
        }
        *(float4*)&su[ry][rc*4] = a;
        *(float4*)&sv[ry][rc*4] = bb;
        *(float4*)&sp[ry][rc*4] = c;
    }
    __syncthreads();

    for (int idx = t; idx < 12 * 32; idx += 256) {
        int ry = idx >> 5, q = idx & 31;
        int c = 4 + 4 * q;
        int gy = y0 - 2 + ry;
        if (gy < 0 || gy >= NYg) {
            *(float4*)&sbu[ry][c] = make_float4(UB, UB, UB, UB);
            *(float4*)&sbv[ry][c] = make_float4(0.f, 0.f, 0.f, 0.f);
            continue;
        }
        int r = ry + 1;
        float4 vc4 = *(const float4*)&sv[r][c];
        float v00[4] = {vc4.x, vc4.y, vc4.z, vc4.w};
        float u00[4], obu[4], obv[4];
        {
            float R[3][6];
#pragma unroll
            for (int j = 0; j < 3; j++) {
                const float* rp_ = &su[r - 1 + j][0];
                float4 m = *(const float4*)(rp_ + c);
                R[j][0]=rp_[c-1]; R[j][1]=m.x; R[j][2]=m.y; R[j][3]=m.z; R[j][4]=m.w; R[j][5]=rp_[c+4];
            }
#pragma unroll
            for (int k = 0; k < 4; k++) {
                float ADx = (R[0][k+2]-R[0][k] + 4.f*(R[1][k+2]-R[1][k]) + R[2][k+2]-R[2][k]) * C12;
                float ADy = (R[2][k]+4.f*R[2][k+1]+R[2][k+2] - R[0][k]-4.f*R[0][k+1]-R[0][k+2]) * C12;
                float c0 = R[1][k+1];
                float AD2 = (R[0][k]+R[0][k+1]+R[0][k+2]+R[1][k]+R[1][k+2]
                           + R[2][k]+R[2][k+1]+R[2][k+2] - 8.f*c0) * C3;
                u00[k] = c0;
                obu[k] = c0 + 0.5f*(NU*AD2*DT - c0*ADx*DT - v00[k]*ADy*DT);
            }
        }
        {
            float R[3][6];
#pragma unroll
            for (int j = 0; j < 3; j++) {
                const float* rp_ = &sv[r - 1 + j][0];
                float4 m = *(const float4*)(rp_ + c);
                R[j][0]=rp_[c-1]; R[j][1]=m.x; R[j][2]=m.y; R[j][3]=m.z; R[j][4]=m.w; R[j][5]=rp_[c+4];
            }
#pragma unroll
            for (int k = 0; k < 4; k++) {
                float ADx = (R[0][k+2]-R[0][k] + 4.f*(R[1][k+2]-R[1][k]) + R[2][k+2]-R[2][k]) * C12;
                float ADy = (R[2][k]+4.f*R[2][k+1]+R[2][k+2] - R[0][k]-4.f*R[0][k+1]-R[0][k+2]) * C12;
                float c0 = R[1][k+1];
                float AD2 = (R[0][k]+R[0][k+1]+R[0][k+2]+R[1][k]+R[1][k+2]
                           + R[2][k]+R[2][k+1]+R[2][k+2] - 8.f*c0) * C3;
                obv[k] = c0 + 0.5f*(NU*AD2*DT - u00[k]*ADx*DT - c0*ADy*DT);
            }
        }
        {
            float R[3][6];
#pragma unroll
            for (int j = 0; j < 3; j++) {
                const float* rp_ = &sp[r - 1 + j][0];
                float4 m = *(const float4*)(rp_ + c);
                R[j][0]=rp_[c-1]; R[j][1]=m.x; R[j][2]=m.y; R[j][3]=m.z; R[j][4]=m.w; R[j][5]=rp_[c+4];
            }
#pragma unroll
            for (int k = 0; k < 4; k++) {
                float Gx = (R[0][k+2]-R[0][k] + 4.f*(R[1][k+2]-R[1][k]) + R[2][k+2]-R[2][k]) * (C12 * DT);
                float Gy = (R[2][k]+4.f*R[2][k+1]+R[2][k+2] - R[0][k]-4.f*R[0][k+1]-R[0][k+2]) * (C12 * DT);
                obu[k] -= Gx; obv[k] -= Gy;
            }
        }
        float4 sg4 = *(const float4*)(sig + gy * NXg + (x0 - 4 + c));
        float sgv[4] = {sg4.x, sg4.y, sg4.z, sg4.w};
#pragma unroll
        for (int k = 0; k < 4; k++) {
            float damp = 1.0f / (1.0f + DT * sgv[k]);
            obu[k] *= damp; obv[k] *= damp;
        }
        *(float4*)&sbu[ry][c] = make_float4(obu[0], obu[1], obu[2], obu[3]);
        *(float4*)&sbv[ry][c] = make_float4(obv[0], obv[1], obv[2], obv[3]);
    }
    if (t < 48) {
        int ry = t >> 2, ec = t & 3;
        int c = (ec < 2) ? (2 + ec) : (130 + ec);
        int gy = y0 - 2 + ry, gx = x0 - 4 + c;
        if (gy < 0 || gy >= NYg || gx < 0) { sbu[ry][c] = UB; sbv[ry][c] = 0.0f; }
        else if (gx < NXg) {
            int r = ry + 1;
            float umm=su[r-1][c-1], um0=su[r-1][c], ump=su[r-1][c+1];
            float u0m=su[r  ][c-1], u00=su[r  ][c], u0p=su[r  ][c+1];
            float upm=su[r+1][c-1], up0=su[r+1][c], upp=su[r+1][c+1];
            float vmm=sv[r-1][c-1], vm0=sv[r-1][c], vmp=sv[r-1][c+1];
            float v0m=sv[r  ][c-1], v00=sv[r  ][c], v0p=sv[r  ][c+1];
            float vpm=sv[r+1][c-1], vp0=sv[r+1][c], vpp=sv[r+1][c+1];
            float pmm=sp[r-1][c-1], pm0=sp[r-1][c], pmp=sp[r-1][c+1];
            float p0m=sp[r  ][c-1],                  p0p=sp[r  ][c+1];
            float ppm=sp[r+1][c-1], pp0=sp[r+1][c], ppp=sp[r+1][c+1];
            float ADx_u = (-umm + ump - 4.0f*u0m + 4.0f*u0p - upm + upp) * C12;
            float ADy_u = (-umm - 4.0f*um0 - ump + upm + 4.0f*up0 + upp) * C12;
            float AD2_u = (umm + um0 + ump + u0m + u0p + upm + up0 + upp - 8.0f*u00) * C3;
            float ADx_v = (-vmm + vmp - 4.0f*v0m + 4.0f*v0p - vpm + vpp) * C12;
            float ADy_v = (-vmm - 4.0f*vm0 - vmp + vpm + 4.0f*vp0 + vpp) * C12;
            float AD2_v = (vmm + vm0 + vmp + v0m + v0p + vpm + vp0 + vpp - 8.0f*v00) * C3;
            float Gx = (-pmm + pmp - 4.0f*p0m + 4.0f*p0p - ppm + ppp) * (C12 * DT);
            float Gy = (-pmm - 4.0f*pm0 - pmp + ppm + 4.0f*pp0 + ppp) * (C12 * DT);
            float damp = 1.0f / (1.0f + DT * sig[gy * NXg + gx]);
            sbu[ry][c] = (u00 + 0.5f*(NU*AD2_u*DT - u00*ADx_u*DT - v00*ADy_u*DT) - Gx) * damp;
            sbv[ry][c] = (v00 + 0.5f*(NU*AD2_v*DT - u00*ADx_v*DT - v00*ADy_v*DT) - Gy) * damp;
        }
    }
    __syncthreads();
    if (x0 + 128 == NXg && t < 12) { sbu[t][132] = sbu[t][131]; sbv[t][132] = sbv[t][131]; }
    __syncthreads();

    for (int idx = t; idx < 10 * 32; idx += 256) {
        int ry = idx >> 5, q = idx & 31;
        int c = 4 + 4 * q;
        int gy = y0 - 1 + ry;
        if (gy < 0 || gy >= NYg) {
            *(float4*)&su2[ry][c] = make_float4(UB, UB, UB, UB);
            *(float4*)&sv2[ry][c] = make_float4(0.f, 0.f, 0.f, 0.f);
            continue;
        }
        int rb = ry + 1, rp = ry + 2;
        float4 uo4 = *(const float4*)&su[rp][c];
        float4 vo4 = *(const float4*)&sv[rp][c];
        float4 bu4 = *(const float4*)&sbu[rb][c];
        float4 bv4 = *(const float4*)&sbv[rb][c];
        float uo[4] = {uo4.x, uo4.y, uo4.z, uo4.w};
        float vo[4] = {vo4.x, vo4.y, vo4.z, vo4.w};
        float bu0[4] = {bu4.x, bu4.y, bu4.z, bu4.w};
        float bv0[4] = {bv4.x, bv4.y, bv4.z, bv4.w};
        float ou[4], ov[4];
        {
            float R[3][6];
#pragma unroll
            for (int j = 0; j < 3; j++) {
                const float* rp_ = &sbu[rb - 1 + j][0];
                float4 m = *(const float4*)(rp_ + c);
                R[j][0]=rp_[c-1]; R[j][1]=m.x; R[j][2]=m.y; R[j][3]=m.z; R[j][4]=m.w; R[j][5]=rp_[c+4];
            }
#pragma unroll
            for (int k = 0; k < 4; k++) {
                float ADx = (R[0][k+2]-R[0][k] + 4.f*(R[1][k+2]-R[1][k]) + R[2][k+2]-R[2][k]) * C12;
                float ADy = (R[2][k]+4.f*R[2][k+1]+R[2][k+2] - R[0][k]-4.f*R[0][k+1]-R[0][k+2]) * C12;
                float c0 = R[1][k+1];
                float AD2 = (R[0][k]+R[0][k+1]+R[0][k+2]+R[1][k]+R[1][k+2]
                           + R[2][k]+R[2][k+1]+R[2][k+2] - 8.f*c0) * C3;
                ou[k] = uo[k] + NU*AD2*DT - bu0[k]*ADx*DT - bv0[k]*ADy*DT;
            }
        }
        {
            float R[3][6];
#pragma unroll
            for (int j = 0; j < 3; j++) {
                const float* rp_ = &sbv[rb - 1 + j][0];
                float4 m = *(const float4*)(rp_ + c);
                R[j][0]=rp_[c-1]; R[j][1]=m.x; R[j][2]=m.y; R[j][3]=m.z; R[j][4]=m.w; R[j][5]=rp_[c+4];
            }
#pragma unroll
            for (int k = 0; k < 4; k++) {
                float ADx = (R[0][k+2]-R[0][k] + 4.f*(R[1][k+2]-R[1][k]) + R[2][k+2]-R[2][k]) * C12;
                float ADy = (R[2][k]+4.f*R[2][k+1]+R[2][k+2] - R[0][k]-4.f*R[0][k+1]-R[0][k+2]) * C12;
                float c0 = R[1][k+1];
                float AD2 = (R[0][k]+R[0][k+1]+R[0][k+2]+R[1][k]+R[1][k+2]
                           + R[2][k]+R[2][k+1]+R[2][k+2] - 8.f*c0) * C3;
                ov[k] = vo[k] + NU*AD2*DT - bu0[k]*ADx*DT - bv0[k]*ADy*DT;
            }
        }
        {
            float R[3][6];
#pragma unroll
            for (int j = 0; j < 3; j++) {
                const float* rp_ = &sp[rp - 1 + j][0];
                float4 m = *(const float4*)(rp_ + c);
                R[j][0]=rp_[c-1]; R[j][1]=m.x; R[j][2]=m.y; R[j][3]=m.z; R[j][4]=m.w; R[j][5]=rp_[c+4];
            }
#pragma unroll
            for (int k = 0; k < 4; k++) {
                float Gx = (R[0][k+2]-R[0][k] + 4.f*(R[1][k+2]-R[1][k]) + R[2][k+2]-R[2][k]) * (C12 * DT);
                float Gy = (R[2][k]+4.f*R[2][k+1]+R[2][k+2] - R[0][k]-4.f*R[0][k+1]-R[0][k+2]) * (C12 * DT);
                ou[k] -= Gx; ov[k] -= Gy;
            }
        }
        float4 sg4 = *(const float4*)(sig + gy * NXg + (x0 - 4 + c));
        float sgv[4] = {sg4.x, sg4.y, sg4.z, sg4.w};
#pragma unroll
        for (int k = 0; k < 4; k++) {
            float damp = 1.0f / (1.0f + DT * sgv[k]);
            ou[k] *= damp; ov[k] *= damp;
        }
        *(float4*)&su2[ry][c] = make_float4(ou[0], ou[1], ou[2], ou[3]);
        *(float4*)&sv2[ry][c] = make_float4(ov[0], ov[1], ov[2], ov[3]);
    }
    if (t < 20) {
        int ry = t >> 1;
        int c = (t & 1) ? 132 : 3;
        int gy = y0 - 1 + ry, gx = x0 - 4 + c;
        if (gy < 0 || gy >= NYg || gx < 0) { su2[ry][c] = UB; sv2[ry][c] = 0.0f; }
        else if (gx < NXg) {
            int rb = ry + 1, rp = ry + 2;
            float umm=sbu[rb-1][c-1], um0=sbu[rb-1][c], ump=sbu[rb-1][c+1];
            float u0m=sbu[rb  ][c-1], bu0=sbu[rb  ][c], u0p=sbu[rb  ][c+1];
            float upm=sbu[rb+1][c-1], up0=sbu[rb+1][c], upp=sbu[rb+1][c+1];
            float vmm=sbv[rb-1][c-1], vm0=sbv[rb-1][c], vmp=sbv[rb-1][c+1];
            float v0m=sbv[rb  ][c-1], bv0=sbv[rb  ][c], v0p=sbv[rb  ][c+1];
            float vpm=sbv[rb+1][c-1], vp0=sbv[rb+1][c], vpp=sbv[rb+1][c+1];
            float pmm=sp[rp-1][c-1], pm0=sp[rp-1][c], pmp=sp[rp-1][c+1];
            float p0m=sp[rp  ][c-1],                  p0p=sp[rp  ][c+1];
            float ppm=sp[rp+1][c-1], pp0=sp[rp+1][c], ppp=sp[rp+1][c+1];
            float ADx_u = (-umm + ump - 4.0f*u0m + 4.0f*u0p - upm + upp) * C12;
            float ADy_u = (-umm - 4.0f*um0 - ump + upm + 4.0f*up0 + upp) * C12;
            float AD2_u = (umm + um0 + ump + u0m + u0p + upm + up0 + upp - 8.0f*bu0) * C3;
            float ADx_v = (-vmm + vmp - 4.0f*v0m + 4.0f*v0p - vpm + vpp) * C12;
            float ADy_v = (-vmm - 4.0f*vm0 - vmp + vpm + 4.0f*vp0 + vpp) * C12;
            float AD2_v = (vmm + vm0 + vmp + v0m + v0p + vpm + vp0 + vpp - 8.0f*bv0) * C3;
            float Gx = (-pmm + pmp - 4.0f*p0m + 4.0f*p0p - ppm + ppp) * (C12 * DT);
            float Gy = (-pmm - 4.0f*pm0 - pmp + ppm + 4.0f*pp0 + ppp) * (C12 * DT);
            float damp = 1.0f / (1.0f + DT * sig[gy * NXg + gx]);
            su2[ry][c] = (su[rp][c] + NU*AD2_u*DT - bu0*ADx_u*DT - bv0*ADy_u*DT - Gx) * damp;
            sv2[ry][c] = (sv[rp][c] + NU*AD2_v*DT - bu0*ADx_v*DT - bv0*ADy_v*DT - Gy) * damp;
        }
    }
    __syncthreads();
    if (x0 + 128 == NXg && t < 10) { su2[t][132] = su2[t][131]; sv2[t][132] = sv2[t][131]; }
    __syncthreads();

    int ty = t >> 5, tx = t & 31;
    int gy = y0 + ty, gxb = x0 + tx * 4;
    int i = gy * NXg + gxb;
    float ob[4], ou[4], ov[4];
#pragma unroll
    for (int k = 0; k < 4; k++) {
        int c = tx * 4 + k + 4;
        float dudx = (-su2[ty][c-1] + su2[ty][c+1] - 4.0f*su2[ty+1][c-1] + 4.0f*su2[ty+1][c+1]
                      - su2[ty+2][c-1] + su2[ty+2][c+1]) * C12;
        float dvdy = (-sv2[ty][c-1] - 4.0f*sv2[ty][c] - sv2[ty][c+1]
                      + sv2[ty+2][c-1] + 4.0f*sv2[ty+2][c] + sv2[ty+2][c+1]) * C12;
        ob[k] = -(dudx + dvdy) * (1.0f / DT);
        ou[k] = su2[ty+1][c];
        ov[k] = sv2[ty+1][c];
    }
    *(float4*)(bg  + i) = make_float4(ob[0], ob[1], ob[2], ob[3]);
    *(float4*)(u2g + i) = make_float4(ou[0], ou[1], ou[2], ou[3]);
    *(float4*)(v2g + i) = make_float4(ov[0], ov[1], ov[2], ov[3]);
    __syncthreads();
#pragma unroll
    for (int k = 0; k < 4; k++) sb[ty * 130 + tx * 4 + k] = ob[k];
    __syncthreads();

    {
        int ry = t >> 6, rx = t & 63;
        int fy = 2 * ry, fx = 2 * rx;
        float s[4][4];
#pragma unroll
        for (int r = 0; r < 4; r++)
#pragma unroll
            for (int c = 0; c < 4; c++)
                s[r][c] = sp[fy + r + 2][fx + 3 + c];
        float h[4][2];
#pragma unroll
        for (int r = 0; r < 4; r++) {
            h[r][0] = s[r][0] + s[r][1] + s[r][2];
            h[r][1] = s[r][1] + s[r][2] + s[r][3];
        }
        float b00 = sb[fy * 130 + fx],       b01 = sb[fy * 130 + fx + 1];
        float b10 = sb[(fy + 1) * 130 + fx], b11 = sb[(fy + 1) * 130 + fx + 1];
        float acc = 0.0f;
        acc += (h[0][0] + h[1][0] + h[2][0] - 9.0f * s[1][1]) * C3 - b00;
        acc += (h[0][1] + h[1][1] + h[2][1] - 9.0f * s[1][2]) * C3 - b01;
        acc += (h[1][0] + h[2][0] + h[3][0] - 9.0f * s[2][1]) * C3 - b10;
        acc += (h[1][1] + h[2][1] + h[3][1] - 9.0f * s[2][2]) * C3 - b11;
        float r1v = 0.25f * acc;
        int bx = blockIdx.x, by = blockIdx.y;
        r1o[(4 * by + ry) * 1024 + 64 * bx + rx] = r1v;
        s1[ry * 64 + rx] = r1v;
        __syncthreads();
        if (t < 64) {
            int ty2 = t >> 5, tx2 = t & 31;
            float v = 0.25f * (s1[2*ty2*64 + 2*tx2] + s1[2*ty2*64 + 2*tx2 + 1]
                             + s1[(2*ty2+1)*64 + 2*tx2] + s1[(2*ty2+1)*64 + 2*tx2 + 1]);
            r2o[(2 * by + ty2) * 512 + 32 * bx + tx2] = v;
            s2[ty2 * 32 + tx2] = v;
        }
        __syncthreads();
        if (t < 16) {
            float v = 0.25f * (s2[2*t] + s2[2*t + 1] + s2[32 + 2*t] + s2[32 + 2*t + 1]);
            r3o[by * 256 + 16 * bx + t] = v;
        }
    }
}

// ---------- coarse pyramid: r3 -> ... -> A4 (r4 cached, prolong up-sweep) ----------
__global__ __launch_bounds__(1024) void k_coarse(
    const float* __restrict__ r3, float* __restrict__ A4g)
{
    __shared__ float sr4[64 * 128];
    __shared__ float sr5[32 * 64];
    __shared__ float sr6[16 * 32], sr7[8 * 16], sr8[4 * 8], sr9[8];
    __shared__ float sA10[2], sA9[8], sA8[32];
    __shared__ float sA7h[10][18];
    __shared__ float sA6h[18][34];
    __shared__ float sA5h[34][66];
    int t = threadIdx.x;

    for (int i = t; i < 10 * 18; i += 1024) (&sA7h[0][0])[i] = 0.0f;
    for (int i = t; i < 18 * 34; i += 1024) (&sA6h[0][0])[i] = 0.0f;
    for (int i = t; i < 34 * 66; i += 1024) (&sA5h[0][0])[i] = 0.0f;

    cudaTriggerProgrammaticLaunchCompletion();
    cudaGridDependencySynchronize();

    for (int i = t; i < 2048; i += 1024) {
        int y = i >> 6, x = i & 63;
        float4 q0 = *(const float4*)(r3 + (4 * y    ) * 256 + 4 * x);
        float4 q1 = *(const float4*)(r3 + (4 * y + 1) * 256 + 4 * x);
        float4 q2 = *(const float4*)(r3 + (4 * y + 2) * 256 + 4 * x);
        float4 q3 = *(const float4*)(r3 + (4 * y + 3) * 256 + 4 * x);
        float a00 = q0.x + q0.y + q1.x + q1.y;
        float a01 = q0.z + q0.w + q1.z + q1.w;
        float a10 = q2.x + q2.y + q3.x + q3.y;
        float a11 = q2.z + q2.w + q3.z + q3.w;
        sr4[(2*y) * 128 + 2*x]     = 0.25f * a00;
        sr4[(2*y) * 128 + 2*x + 1] = 0.25f * a01;
        sr4[(2*y+1) * 128 + 2*x]     = 0.25f * a10;
        sr4[(2*y+1) * 128 + 2*x + 1] = 0.25f * a11;
        sr5[i] = 0.0625f * (a00 + a01 + a10 + a11);
    }
    __syncthreads();

    if (t < 512) {
        int y = t >> 5, x = t & 31;
        sr6[t] = 0.25f * (sr5[(2*y)*64 + 2*x] + sr5[(2*y)*64 + 2*x + 1]
                        + sr5[(2*y+1)*64 + 2*x] + sr5[(2*y+1)*64 + 2*x + 1]);
    } else if (t < 640) {
        int i = t - 512; int y = i >> 4, x = i & 15;
        float s = 0.0f;
#pragma unroll
        for (int dy = 0; dy < 4; dy++)
#pragma unroll
            for (int dx = 0; dx < 4; dx++)
                s += sr5[(4*y + dy)*64 + 4*x + dx];
        sr7[i] = 0.0625f * s;
    } else if (t < 672) {
        int i = t - 640; int y = i >> 3, x = i & 7;
        float s = 0.0f;
        for (int dy = 0; dy < 8; dy++)
#pragma unroll
            for (int dx = 0; dx < 8; dx++)
                s += sr5[(8*y + dy)*64 + 8*x + dx];
        sr8[i] = 0.015625f * s;
    }
    __syncthreads();

    if (t < 32) {
        if (t < 8) {
            int y = t >> 2, x = t & 3;
            sr9[t] = 0.25f * (sr8[(2*y)*8 + 2*x] + sr8[(2*y)*8 + 2*x + 1]
                            + sr8[(2*y+1)*8 + 2*x] + sr8[(2*y+1)*8 + 2*x + 1]);
        }
        __syncwarp();
        if (t < 2) {
            float r10 = 0.25f * (sr9[2*t] + sr9[2*t + 1] + sr9[4 + 2*t] + sr9[4 + 2*t + 1]);
            sA10[t] = -0.375f * r10;
        }
        __syncwarp();
        if (t < 8) {
            int y = t >> 2, x = t & 3;
            float S = 0.0f;
#pragma unroll
            for (int dy = -1; dy <= 1; dy++)
#pragma unroll
                for (int dx = -1; dx <= 1; dx++) {
                    if (dy == 0 && dx == 0) continue;
                    int yy = y + dy, xx = x + dx;
                    if (yy >= 0 && yy < 2 && xx >= 0 && xx < 4) S += sA10[xx >> 1];
                }
            sA9[t] = 0.125f * S - 0.375f * sr9[t];
        }
        __syncwarp();
        {
            int y = t >> 3, x = t & 7;
            float S = 0.0f;
#pragma unroll
            for (int dy = -1; dy <= 1; dy++)
#pragma unroll
                for (int dx = -1; dx <= 1; dx++) {
                    if (dy == 0 && dx == 0) continue;
                    int yy = y + dy, xx = x + dx;
                    if (yy >= 0 && yy < 4 && xx >= 0 && xx < 8) S += sA9[(yy >> 1) * 4 + (xx >> 1)];
                }
            sA8[t] = 0.125f * S - 0.375f * sr8[t];
        }
    }
    __syncthreads();

    if (t < 128) {
        int y = t >> 4, x = t & 15;
        float S = 0.0f;
#pragma unroll
        for (int dy = -1; dy <= 1; dy++)
#pragma unroll
            for (int dx = -1; dx <= 1; dx++) {
                if (dy == 0 && dx == 0) continue;
                int yy = y + dy, xx = x + dx;
                if (yy >= 0 && yy < 8 && xx >= 0 && xx < 16) S += sA8[(yy >> 1) * 8 + (xx >> 1)];
            }
        sA7h[1 + y][1 + x] = 0.125f * S - 0.375f * sr7[t];
    }
    __syncthreads();
    if (t < 512) {
        int y = t >> 5, x = t & 31;
        sA6h[1 + y][1 + x] = 0.125f * prolong_S8(&sA7h[1][1], 18, 0, 0, y, x)
                           - 0.375f * sr6[t];
    }
    __syncthreads();
    for (int i = t; i < 2048; i += 1024) {
        int y = i >> 6, x = i & 63;
        sA5h[1 + y][1 + x] = 0.125f * prolong_S8(&sA6h[1][1], 34, 0, 0, y, x)
                           - 0.375f * sr5[i];
    }
    __syncthreads();
    for (int i = t; i < 64 * 128; i += 1024) {
        int y = i >> 7, x = i & 127;
        A4g[i] = 0.125f * prolong_S8(&sA5h[1][1], 66, 0, 0, y, x)
               - 0.375f * sr4[i];
    }
}

// ============ fused up-sweep + fine smooth + (residual pyramid | projection) ============
// 128x16 tile (grid 16x64) -> single wave across the chip.
template<bool FINAL>
__global__ __launch_bounds__(256) void k_up(
    const float* __restrict__ p, const float* __restrict__ b,
    const float* __restrict__ r1, const float* __restrict__ r2,
    const float* __restrict__ r3, const float* __restrict__ A4,
    float* __restrict__ pn,
    float* __restrict__ r1o, float* __restrict__ r2o, float* __restrict__ r3o,
    const float* __restrict__ u2, const float* __restrict__ v2,
    const float* __restrict__ sig, float* __restrict__ out)
{
    __shared__ float sp[20][136];     // base (y0-2, x0-4)
    __shared__ float spn[18][136];    // base (y0-1, x0-4)
    __shared__ float sA1[12][68];     // base (8by-2, 64bx-2)
    __shared__ float sA2[8][36];      // base (4by-2, 32bx-2)
    __shared__ float sA3[6][20];      // base (2by-2, 16bx-2)
    __shared__ float sA4[5][12];      // base (by-2,  8bx-2)
    __shared__ float s1[8 * 64];
    __shared__ float s2[4 * 32];

    int bx = blockIdx.x, by = blockIdx.y;
    int x0 = bx * 128, y0 = by * 16;
    int t = threadIdx.x;
    int y4b = by - 2,     x4b = 8 * bx - 2;
    int y3b = 2 * by - 2, x3b = 16 * bx - 2;
    int y2b = 4 * by - 2, x2b = 32 * bx - 2;
    int y1b = 8 * by - 2, x1b = 64 * bx - 2;

    // ================= PREAMBLE =================
    for (int idx = t; idx < 20 * 34; idx += 256) {
        int ry = idx / 34, rc = idx - ry * 34;
        int gy = y0 - 2 + ry, gx = x0 - 4 + rc * 4;
        float4 c;
        if (gy >= 0 && gy < NYg && gx >= 0 && gx + 3 < NXg)
            c = *(const float4*)(p + gy * NXg + gx);
        else
            c = make_float4(ldP(p,gy,gx), ldP(p,gy,gx+1), ldP(p,gy,gx+2), ldP(p,gy,gx+3));
        *(float4*)&sp[ry][rc * 4] = c;
    }
    float rv3 = 0.0f, rv2[2] = {0.0f, 0.0f}, rv1[4] = {0.0f, 0.0f, 0.0f, 0.0f};
    if (t < 120) {
        int ly = t / 20, lx = t - ly * 20;
        int y3 = y3b + ly, x3 = x3b + lx;
        if (y3 >= 0 && y3 < 128 && x3 >= 0 && x3 < 256) rv3 = r3[y3 * 256 + x3];
    }
#pragma unroll
    for (int j = 0; j < 2; j++) {
        int i = t + j * 256;
        if (i < 8 * 36) {
            int ly = i / 36, lx = i - ly * 36;
            int y2 = y2b + ly, x2 = x2b + lx;
            if (y2 >= 0 && y2 < 256 && x2 >= 0 && x2 < 512) rv2[j] = r2[y2 * 512 + x2];
        }
    }
#pragma unroll
    for (int j = 0; j < 4; j++) {
        int i = t + j * 256;
        if (i < 12 * 68) {
            int ly = i / 68, lx = i - ly * 68;
            int y1 = y1b + ly, x1 = x1b + lx;
            if (x1 < 1024) {
                int y1c = min(max(y1, 0), 511), x1c = max(x1, 0);
                rv1[j] = r1[y1c * 1024 + x1c];
            }
        }
    }
    __syncthreads();

    // staging: T = 0.125*S8(bc_p(p)) - 0.375*b for all 18 rows
    for (int idx = t; idx < 18 * 32; idx += 256) {
        int ry = idx >> 5, q = idx & 31;
        int gy = y0 - 1 + ry;
        if (gy < 0 || gy >= NYg) continue;
        int r = ry + 1;
        int c = 4 + 4 * q;
        float row[3][6];
#pragma unroll
        for (int j = 0; j < 3; j++) {
            const float* rp_ = &sp[r - 1 + j][0];
            float4 m = *(const float4*)(rp_ + c);
            row[j][0] = rp_[c - 1];
            row[j][1] = m.x; row[j][2] = m.y; row[j][3] = m.z; row[j][4] = m.w;
            row[j][5] = rp_[c + 4];
        }
        float h[6];
#pragma unroll
        for (int j = 0; j < 6; j++) h[j] = row[0][j] + row[1][j] + row[2][j];
        float4 b4 = *(const float4*)(b + gy * NXg + x0 + 4 * q);
        float bb[4] = {b4.x, b4.y, b4.z, b4.w};
        float T[4];
#pragma unroll
        for (int k = 0; k < 4; k++) {
            float S8 = h[k] + h[k + 1] + h[k + 2] - row[1][k + 1];
            T[k] = 0.125f * S8 - 0.375f * bb[k];
        }
        *(float4*)&spn[ry][c] = make_float4(T[0], T[1], T[2], T[3]);
    }
    if (t < 36) {
        int ry = t >> 1;
        int c = (t & 1) ? 132 : 3;
        int gy = y0 - 1 + ry, gx = x0 - 4 + c;
        if (gy >= 0 && gy < NYg && gx >= 0 && gx < NXg) {
            int r = ry + 1;
            float S = sp[r-1][c-1] + sp[r-1][c] + sp[r-1][c+1]
                    + sp[r  ][c-1] +              sp[r  ][c+1]
                    + sp[r+1][c-1] + sp[r+1][c] + sp[r+1][c+1];
            spn[ry][c] = 0.125f * S - 0.375f * b[gy * NXg + gx];
        }
    }

    // ================= wait for k_coarse (A4) =================
    cudaGridDependencySynchronize();

    if (t < 60) {
        int ly = t / 12, lx = t - ly * 12;
        int y4 = y4b + ly, x4 = x4b + lx;
        sA4[ly][lx] = (y4 >= 0 && y4 < 64 && x4 >= 0 && x4 < 128) ? A4[y4 * 128 + x4] : 0.0f;
    }
    __syncthreads();

    if (t < 120) {
        int ly = t / 20, lx = t - ly * 20;
        int y3 = y3b + ly, x3 = x3b + lx;
        float val = 0.0f;
        if (y3 >= 0 && y3 < 128 && x3 >= 0 && x3 < 256)
            val = 0.125f * prolong_S8(&sA4[0][0], 12, y4b, x4b, y3, x3) - 0.375f * rv3;
        sA3[ly][lx] = val;
    }
    __syncthreads();
#pragma unroll
    for (int j = 0; j < 2; j++) {
        int i = t + j * 256;
        if (i < 8 * 36) {
            int ly = i / 36, lx = i - ly * 36;
            int y2 = y2b + ly, x2 = x2b + lx;
            float val = 0.0f;
            if (y2 >= 0 && y2 < 256 && x2 >= 0 && x2 < 512)
                val = 0.125f * prolong_S8(&sA3[0][0], 20, y3b, x3b, y2, x2) - 0.375f * rv2[j];
            sA2[ly][lx] = val;
        }
    }
    __syncthreads();
#pragma unroll
    for (int j = 0; j < 4; j++) {
        int i = t + j * 256;
        if (i < 12 * 68) {
            int ly = i / 68, lx = i - ly * 68;
            int y1 = y1b + ly, x1 = x1b + lx;
            float val = 0.0f;
            if (x1 < 1024) {
                int y1c = min(max(y1, 0), 511), x1c = max(x1, 0);
                val = 0.125f * prolong_S8(&sA2[0][0], 36, y2b, x2b, y1c, x1c) - 0.375f * rv1[j];
            }
            sA1[ly][lx] = val;
        }
    }
    __syncthreads();

    // finalize: pn = T - 0.125*Sa
    for (int idx = t; idx < 18 * 32; idx += 256) {
        int ry = idx >> 5, q = idx & 31;
        int gy = y0 - 1 + ry;
        if (gy < 0 || gy >= NYg) continue;
        int c = 4 + 4 * q;
        int gxb = x0 + 4 * q;
        float4 tv = *(const float4*)&spn[ry][c];
        float T[4] = {tv.x, tv.y, tv.z, tv.w};
        int py = gy & 1;
        int r0 = ((gy - 1) >> 1) - y1b;
        int C  = (gxb >> 1) - x1b;
        const float* R0 = &sA1[r0][0];
        const float* R1 = &sA1[r0 + 1][0];
        const float* Rc = py ? R0 : R1;
        float w0 = py ? 2.0f : 1.0f, w1 = 3.0f - w0;
        float rs[4];
#pragma unroll
        for (int j = 0; j < 4; j++) rs[j] = w0 * R0[C - 1 + j] + w1 * R1[C - 1 + j];
        float Sa[4];
        Sa[0] = rs[0] + 2.0f * rs[1] - Rc[C];
        Sa[1] = 2.0f * rs[1] + rs[2] - Rc[C];
        Sa[2] = rs[1] + 2.0f * rs[2] - Rc[C + 1];
        Sa[3] = 2.0f * rs[2] + rs[3] - Rc[C + 1];
        *(float4*)&spn[ry][c] = make_float4(T[0] - 0.125f * Sa[0], T[1] - 0.125f * Sa[1],
                                            T[2] - 0.125f * Sa[2], T[3] - 0.125f * Sa[3]);
    }
    if (t < 36) {
        int ry = t >> 1;
        int c = (t & 1) ? 132 : 3;
        int gy = y0 - 1 + ry, gx = x0 - 4 + c;
        if (gy >= 0 && gy < NYg && gx >= 0 && gx < NXg) {
            float Sa = prolong_S8(&sA1[0][0], 68, y1b, x1b, gy, gx);
            spn[ry][c] -= 0.125f * Sa;
        }
    }
    __syncthreads();
    if (t < 18) {
        if (bx == 0) {
            int src = (by == 0 && t == 0) ? 1 : ((by == 63 && t == 17) ? 16 : t);
            spn[t][3] = spn[src][4];
        }
        if (bx == 15) spn[t][132] = 0.0f;
    }
    if (by == 0) {
        for (int c = t; c < 130; c += 256) {
            float v;
            if (c == 0 && bx == 0)         v = spn[1][4];
            else if (c == 129 && bx == 15) v = 0.0f;
            else                           v = spn[1][c + 3];
            spn[0][c + 3] = v;
        }
    }
    if (by == 63) {
        for (int c = t; c < 130; c += 256) {
            float v;
            if (c == 0 && bx == 0)         v = spn[16][4];
            else if (c == 129 && bx == 15) v = 0.0f;
            else                           v = spn[16][c + 3];
            spn[17][c + 3] = v;
        }
    }
    __syncthreads();

    if constexpr (!FINAL) {
        // write pn (16 rows x 32 quads)
        for (int idx = t; idx < 512; idx += 256) {
            int ry = idx >> 5, q = idx & 31;
            int i = (y0 + ry) * NXg + x0 + 4 * q;
            *(float4*)(pn + i) = *(float4*)&spn[ry + 1][4 + 4 * q];
        }
        // residual of pn + restriction: r1 tile 8x64 (2 per thread)
#pragma unroll
        for (int j = 0; j < 2; j++) {
            int idx = t + j * 256;
            int ry = idx >> 6, rx = idx & 63;
            int fy = 2 * ry, fx = 2 * rx;
            float s[4][4];
#pragma unroll
            for (int r = 0; r < 4; r++)
#pragma unroll
                for (int c = 0; c < 4; c++)
                    s[r][c] = spn[fy + r][fx + 3 + c];
            float h2[4][2];
#pragma unroll
            for (int r = 0; r < 4; r++) {
                h2[r][0] = s[r][0] + s[r][1] + s[r][2];
                h2[r][1] = s[r][1] + s[r][2] + s[r][3];
            }
            float2 b0 = *(const float2*)(b + (y0 + fy) * NXg + x0 + fx);
            float2 b1 = *(const float2*)(b + (y0 + fy + 1) * NXg + x0 + fx);
            float acc = 0.0f;
            acc += (h2[0][0] + h2[1][0] + h2[2][0] - 9.0f * s[1][1]) * C3 - b0.x;
            acc += (h2[0][1] + h2[1][1] + h2[2][1] - 9.0f * s[1][2]) * C3 - b0.y;
            acc += (h2[1][0] + h2[2][0] + h2[3][0] - 9.0f * s[2][1]) * C3 - b1.x;
            acc += (h2[1][1] + h2[2][1] + h2[3][1] - 9.0f * s[2][2]) * C3 - b1.y;
            float r1v = 0.25f * acc;
            r1o[(8 * by + ry) * 1024 + 64 * bx + rx] = r1v;
            s1[ry * 64 + rx] = r1v;
        }
        __syncthreads();
        if (t < 128) {
            int ty2 = t >> 5, tx2 = t & 31;
            float v = 0.25f * (s1[2*ty2*64 + 2*tx2] + s1[2*ty2*64 + 2*tx2 + 1]
                             + s1[(2*ty2+1)*64 + 2*tx2] + s1[(2*ty2+1)*64 + 2*tx2 + 1]);
            r2o[(4 * by + ty2) * 512 + 32 * bx + tx2] = v;
            s2[ty2 * 32 + tx2] = v;
        }
        __syncthreads();
        if (t < 32) {
            int yy = t >> 4, xx = t & 15;
            float v = 0.25f * (s2[2*yy*32 + 2*xx] + s2[2*yy*32 + 2*xx + 1]
                             + s2[(2*yy+1)*32 + 2*xx] + s2[(2*yy+1)*32 + 2*xx + 1]);
            r3o[(2 * by + yy) * 256 + 16 * bx + xx] = v;
        }
    } else {
        for (int idx = t; idx < 512; idx += 256) {
            int ry = idx >> 5, q = idx & 31;
            int gy = y0 + ry;
            int gxb = x0 + 4 * q;
            int i = gy * NXg + gxb;
            float4 s4 = *(const float4*)(sig + i);
            float4 u4 = *(const float4*)(u2 + i);
            float4 v4 = *(const float4*)(v2 + i);
            float sg[4] = {s4.x, s4.y, s4.z, s4.w};
            float uu[4] = {u4.x, u4.y, u4.z, u4.w};
            float vv[4] = {v4.x, v4.y, v4.z, v4.w};
            float ou[4], ov[4], op[4];
#pragma unroll
            for (int k = 0; k < 4; k++) {
                int c = 4 * q + k + 4, r = ry + 1;
                float pmm = spn[r-1][c-1], pm0 = spn[r-1][c], pmp = spn[r-1][c+1];
                float p0m = spn[r  ][c-1],                     p0p = spn[r  ][c+1];
                float ppm = spn[r+1][c-1], pp0 = spn[r+1][c], ppp = spn[r+1][c+1];
                float Gx = (-pmm + pmp - 4.0f*p0m + 4.0f*p0p - ppm + ppp) * (C12 * DT);
                float Gy = (-pmm - 4.0f*pm0 - pmp + ppm + 4.0f*pp0 + ppp) * (C12 * DT);
                float damp = 1.0f / (1.0f + DT * sg[k]);
                ou[k] = (uu[k] - Gx) * damp;
                ov[k] = (vv[k] - Gy) * damp;
                op[k] = spn[r][c];
            }
            *(float4*)(out + i)            = make_float4(ou[0], ou[1], ou[2], ou[3]);
            *(float4*)(out + N0 + i)       = make_float4(ov[0], ov[1], ov[2], ov[3]);
            *(float4*)(out + 2 * N0 + i)   = make_float4(op[0], op[1], op[2], op[3]);
        }
    }
}

static float* symaddr(const void* s) {
    void* ptr = nullptr;
    cudaGetSymbolAddress(&ptr, s);
    return (float*)ptr;
}

extern "C" void kernel_launch(void* const* d_in, const int* in_sizes, int n_in,
                              void* d_out, int out_size)
{
    const float* u   = (const float*)d_in[0];
    const float* v   = (const float*)d_in[1];
    const float* p   = (const float*)d_in[2];
    const float* sig = (const float*)d_in[3];
    float* out = (float*)d_out;

    float* u2  = symaddr(g_u2);  float* v2  = symaddr(g_v2);
    float* b   = symaddr(g_b);
    float* pa  = symaddr(g_pa);  float* pb  = symaddr(g_pb);
    float* r1a = symaddr(g_r1a); float* r1b = symaddr(g_r1b);
    float* r2a = symaddr(g_r2a); float* r2b = symaddr(g_r2b);
    float* r3a = symaddr(g_r3a); float* r3b = symaddr(g_r3b);
    float* A4  = symaddr(g_A4);

    cudaLaunchAttribute attrs[1];
    attrs[0].id = cudaLaunchAttributeProgrammaticStreamSerialization;
    attrs[0].val.programmaticStreamSerializationAllowed = 1;

    cudaLaunchConfig_t cfg = {};
    cfg.stream = (cudaStream_t)0;
    cfg.attrs = attrs;
    cfg.numAttrs = 1;

    cfg.gridDim = dim3(16, 128);
    cfg.blockDim = dim3(32, 8);
    cudaLaunchKernelEx(&cfg, k_mom, u, v, p, sig, u2, v2, b, r1a, r2a, r3a);

    const float* pc = p;
    float* pn = pa;
    for (int it = 0; it < 5; it++) {
        bool even = (it & 1) == 0;
        float* r1i = even ? r1a : r1b; float* r1o = even ? r1b : r1a;
        float* r2i = even ? r2a : r2b; float* r2o = even ? r2b : r2a;
        float* r3i = even ? r3a : r3b; float* r3o = even ? r3b : r3a;

        cfg.gridDim = dim3(1, 1, 1);
        cfg.blockDim = dim3(1024, 1, 1);
        cudaLaunchKernelEx(&cfg, k_coarse, (const float*)r3i, A4);

        cfg.gridDim = dim3(16, 64);
        cfg.blockDim = dim3(256, 1, 1);
        if (it < 4) {
            cudaLaunchKernelEx(&cfg, k_up<false>,
                pc, (const float*)b, (const float*)r1i, (const float*)r2i,
                (const float*)r3i, (const float*)A4, pn, r1o, r2o, r3o,
                (const float*)nullptr, (const float*)nullptr,
                (const float*)nullptr, (float*)nullptr);
            pc = pn;
            pn = (pn == pa) ? pb : pa;
        } else {
            cudaLaunchKernelEx(&cfg, k_up<true>,
                pc, (const float*)b, (const float*)r1i, (const float*)r2i,
                (const float*)r3i, (const float*)A4, (float*)nullptr,
                (float*)nullptr, (float*)nullptr, (float*)nullptr,
                (const float*)u2, (const float*)v2, (const float*)sig, out);
        }
    }
}

// round 15
// speedup vs baseline: 1.1241x; 1.0037x over previous
#include <cuda_runtime.h>

constexpr int NYg = 1024;
constexpr int NXg = 2048;
constexpr int N0  = NYg * NXg;
constexpr float DT = 0.1f;
constexpr float NU = 0.01f;
constexpr float UB = 1.0f;
constexpr float C12 = 1.0f / 12.0f;
constexpr float C3  = 1.0f / 3.0f;

__device__ float g_u2[N0];
__device__ float g_v2[N0];
__device__ float g_b [N0];
__device__ float g_pa[N0];
__device__ float g_pb[N0];
__device__ float g_r1a[512 * 1024];
__device__ float g_r1b[512 * 1024];
__device__ float g_r2a[256 * 512];
__device__ float g_r2b[256 * 512];
__device__ float g_r3a[128 * 256];
__device__ float g_r3b[128 * 256];
__device__ float g_A4[64 * 128];

// ---------- boundary-condition loaders ----------
__device__ __forceinline__ float ldU(const float* __restrict__ u, int y, int x) {
    if (y < 0 || y >= NYg) return UB;
    if (x < 0) return UB;
    if (x >= NXg) return u[y * NXg + NXg - 1];
    return u[y * NXg + x];
}
__device__ __forceinline__ float ldV(const float* __restrict__ v, int y, int x) {
    if (x >= NXg) { if (y < 0 || y >= NYg) return 0.0f; return v[y * NXg + NXg - 1]; }
    if (y < 0 || y >= NYg || x < 0) return 0.0f;
    return v[y * NXg + x];
}
__device__ __forceinline__ float ldP(const float* __restrict__ p, int y, int x) {
    if (x >= NXg) return 0.0f;
    int yy = min(max(y, 0), NYg - 1);
    int xx = max(x, 0);
    return p[yy * NXg + xx];
}

// generic prolong S8: sum of 3x3 neighborhood (excl. center) of NN-upsampled A
__device__ __forceinline__ float prolong_S8(const float* __restrict__ A, int stride,
                                            int yb, int xb, int y, int x)
{
    int r0 = ((y - 1) >> 1) - yb;
    int c0 = ((x - 1) >> 1) - xb;
    int py = y & 1, px = x & 1;
    float wr0 = (float)(1 + py), wr1 = (float)(2 - py);
    float wc0 = (float)(1 + px), wc1 = (float)(2 - px);
    const float* row0 = A + r0 * stride + c0;
    const float* row1 = row0 + stride;
    float V00 = row0[0], V01 = row0[1], V10 = row1[0], V11 = row1[1];
    float S9 = wr0 * (wc0 * V00 + wc1 * V01) + wr1 * (wc0 * V10 + wc1 * V11);
    float ctr = py ? (px ? V00 : V01) : (px ? V10 : V11);
    return S9 - ctr;
}

// ============ fused momentum + divergence + initial residual pyramid ============
__global__ __launch_bounds__(256) void k_mom(
    const float* __restrict__ u, const float* __restrict__ v,
    const float* __restrict__ p, const float* __restrict__ sig,
    float* __restrict__ u2g, float* __restrict__ v2g, float* __restrict__ bg,
    float* __restrict__ r1o, float* __restrict__ r2o, float* __restrict__ r3o)
{
    __shared__ float su[14][136], sv[14][136], sp[14][136];
    __shared__ float sbu[12][136], sbv[12][136];
    __shared__ float su2[10][136], sv2[10][136];
    float* sb = &sbu[0][0];
    float* s1 = sb + 8 * 130;
    float* s2 = s1 + 256;

    cudaGridDependencySynchronize();

    int x0 = blockIdx.x * 128, y0 = blockIdx.y * 8;
    int t = threadIdx.y * 32 + threadIdx.x;

    for (int idx = t; idx < 14 * 34; idx += 256) {
        int ry = idx / 34, rc = idx - ry * 34;
        int gy = y0 - 3 + ry, gx = x0 - 4 + rc * 4;
        float4 a, bb, c;
        if (gy >= 0 && gy < NYg && gx >= 0 && gx + 3 < NXg) {
            a  = *(const float4*)(u + gy * NXg + gx);
            bb = *(const float4*)(v + gy * NXg + gx);
            c  = *(const float4*)(p + gy * NXg + gx);
        } else {
            a  = make_float4(ldU(u,gy,gx), ldU(u,gy,gx+1), ldU(u,gy,gx+2), ldU(u,gy,gx+3));
            bb = make_float4(ldV(v,gy,gx), ldV(v,gy,gx+1), ldV(v,gy,gx+2), ldV(v,gy,gx+3));
            c  = make_float4(ldP(p,gy,gx), ldP(p,gy,gx+1), ldP(p,gy,gx+2), ldP(p,gy,gx+3));
        }
        *(float4*)&su[ry][rc*4] = a;
        *(float4*)&sv[ry][rc*4] = bb;
        *(float4*)&sp[ry][rc*4] = c;
    }
    __syncthreads();

    for (int idx = t; idx < 12 * 32; idx += 256) {
        int ry = idx >> 5, q = idx & 31;
        int c = 4 + 4 * q;
        int gy = y0 - 2 + ry;
        if (gy < 0 || gy >= NYg) {
            *(float4*)&sbu[ry][c] = make_float4(UB, UB, UB, UB);
            *(float4*)&sbv[ry][c] = make_float4(0.f, 0.f, 0.f, 0.f);
            continue;
        }
        int r = ry + 1;
        float4 vc4 = *(const float4*)&sv[r][c];
        float v00[4] = {vc4.x, vc4.y, vc4.z, vc4.w};
        float u00[4], obu[4], obv[4];
        {
            float R[3][6];
#pragma unroll
            for (int j = 0; j < 3; j++) {
                const float* rp_ = &su[r - 1 + j][0];
                float4 m = *(const float4*)(rp_ + c);
                R[j][0]=rp_[c-1]; R[j][1]=m.x; R[j][2]=m.y; R[j][3]=m.z; R[j][4]=m.w; R[j][5]=rp_[c+4];
            }
#pragma unroll
            for (int k = 0; k < 4; k++) {
                float ADx = (R[0][k+2]-R[0][k] + 4.f*(R[1][k+2]-R[1][k]) + R[2][k+2]-R[2][k]) * C12;
                float ADy = (R[2][k]+4.f*R[2][k+1]+R[2][k+2] - R[0][k]-4.f*R[0][k+1]-R[0][k+2]) * C12;
                float c0 = R[1][k+1];
                float AD2 = (R[0][k]+R[0][k+1]+R[0][k+2]+R[1][k]+R[1][k+2]
                           + R[2][k]+R[2][k+1]+R[2][k+2] - 8.f*c0) * C3;
                u00[k] = c0;
                obu[k] = c0 + 0.5f*(NU*AD2*DT - c0*ADx*DT - v00[k]*ADy*DT);
            }
        }
        {
            float R[3][6];
#pragma unroll
            for (int j = 0; j < 3; j++) {
                const float* rp_ = &sv[r - 1 + j][0];
                float4 m = *(const float4*)(rp_ + c);
                R[j][0]=rp_[c-1]; R[j][1]=m.x; R[j][2]=m.y; R[j][3]=m.z; R[j][4]=m.w; R[j][5]=rp_[c+4];
            }
#pragma unroll
            for (int k = 0; k < 4; k++) {
                float ADx = (R[0][k+2]-R[0][k] + 4.f*(R[1][k+2]-R[1][k]) + R[2][k+2]-R[2][k]) * C12;
                float ADy = (R[2][k]+4.f*R[2][k+1]+R[2][k+2] - R[0][k]-4.f*R[0][k+1]-R[0][k+2]) * C12;
                float c0 = R[1][k+1];
                float AD2 = (R[0][k]+R[0][k+1]+R[0][k+2]+R[1][k]+R[1][k+2]
                           + R[2][k]+R[2][k+1]+R[2][k+2] - 8.f*c0) * C3;
                obv[k] = c0 + 0.5f*(NU*AD2*DT - u00[k]*ADx*DT - c0*ADy*DT);
            }
        }
        {
            float R[3][6];
#pragma unroll
            for (int j = 0; j < 3; j++) {
                const float* rp_ = &sp[r - 1 + j][0];
                float4 m = *(const float4*)(rp_ + c);
                R[j][0]=rp_[c-1]; R[j][1]=m.x; R[j][2]=m.y; R[j][3]=m.z; R[j][4]=m.w; R[j][5]=rp_[c+4];
            }
#pragma unroll
            for (int k = 0; k < 4; k++) {
                float Gx = (R[0][k+2]-R[0][k] + 4.f*(R[1][k+2]-R[1][k]) + R[2][k+2]-R[2][k]) * (C12 * DT);
                float Gy = (R[2][k]+4.f*R[2][k+1]+R[2][k+2] - R[0][k]-4.f*R[0][k+1]-R[0][k+2]) * (C12 * DT);
                obu[k] -= Gx; obv[k] -= Gy;
            }
        }
        float4 sg4 = *(const float4*)(sig + gy * NXg + (x0 - 4 + c));
        float sgv[4] = {sg4.x, sg4.y, sg4.z, sg4.w};
#pragma unroll
        for (int k = 0; k < 4; k++) {
            float damp = 1.0f / (1.0f + DT * sgv[k]);
            obu[k] *= damp; obv[k] *= damp;
        }
        *(float4*)&sbu[ry][c] = make_float4(obu[0], obu[1], obu[2], obu[3]);
        *(float4*)&sbv[ry][c] = make_float4(obv[0], obv[1], obv[2], obv[3]);
    }
    if (t < 48) {
        int ry = t >> 2, ec = t & 3;
        int c = (ec < 2) ? (2 + ec) : (130 + ec);
        int gy = y0 - 2 + ry, gx = x0 - 4 + c;
        if (gy < 0 || gy >= NYg || gx < 0) { sbu[ry][c] = UB; sbv[ry][c] = 0.0f; }
        else if (gx < NXg) {
            int r = ry + 1;
            float umm=su[r-1][c-1], um0=su[r-1][c], ump=su[r-1][c+1];
            float u0m=su[r  ][c-1], u00=su[r  ][c], u0p=su[r  ][c+1];
            float upm=su[r+1][c-1], up0=su[r+1][c], upp=su[r+1][c+1];
            float vmm=sv[r-1][c-1], vm0=sv[r-1][c], vmp=sv[r-1][c+1];
            float v0m=sv[r  ][c-1], v00=sv[r  ][c], v0p=sv[r  ][c+1];
            float vpm=sv[r+1][c-1], vp0=sv[r+1][c], vpp=sv[r+1][c+1];
            float pmm=sp[r-1][c-1], pm0=sp[r-1][c], pmp=sp[r-1][c+1];
            float p0m=sp[r  ][c-1],                  p0p=sp[r  ][c+1];
            float ppm=sp[r+1][c-1], pp0=sp[r+1][c], ppp=sp[r+1][c+1];
            float ADx_u = (-umm + ump - 4.0f*u0m + 4.0f*u0p - upm + upp) * C12;
            float ADy_u = (-umm - 4.0f*um0 - ump + upm + 4.0f*up0 + upp) * C12;
            float AD2_u = (umm + um0 + ump + u0m + u0p + upm + up0 + upp - 8.0f*u00) * C3;
            float ADx_v = (-vmm + vmp - 4.0f*v0m + 4.0f*v0p - vpm + vpp) * C12;
            float ADy_v = (-vmm - 4.0f*vm0 - vmp + vpm + 4.0f*vp0 + vpp) * C12;
            float AD2_v = (vmm + vm0 + vmp + v0m + v0p + vpm + vp0 + vpp - 8.0f*v00) * C3;
            float Gx = (-pmm + pmp - 4.0f*p0m + 4.0f*p0p - ppm + ppp) * (C12 * DT);
            float Gy = (-pmm - 4.0f*pm0 - pmp + ppm + 4.0f*pp0 + ppp) * (C12 * DT);
            float damp = 1.0f / (1.0f + DT * sig[gy * NXg + gx]);
            sbu[ry][c] = (u00 + 0.5f*(NU*AD2_u*DT - u00*ADx_u*DT - v00*ADy_u*DT) - Gx) * damp;
            sbv[ry][c] = (v00 + 0.5f*(NU*AD2_v*DT - u00*ADx_v*DT - v00*ADy_v*DT) - Gy) * damp;
        }
    }
    __syncthreads();
    if (x0 + 128 == NXg && t < 12) { sbu[t][132] = sbu[t][131]; sbv[t][132] = sbv[t][131]; }
    __syncthreads();

    for (int idx = t; idx < 10 * 32; idx += 256) {
        int ry = idx >> 5, q = idx & 31;
        int c = 4 + 4 * q;
        int gy = y0 - 1 + ry;
        if (gy < 0 || gy >= NYg) {
            *(float4*)&su2[ry][c] = make_float4(UB, UB, UB, UB);
            *(float4*)&sv2[ry][c] = make_float4(0.f, 0.f, 0.f, 0.f);
            continue;
        }
        int rb = ry + 1, rp = ry + 2;
        float4 uo4 = *(const float4*)&su[rp][c];
        float4 vo4 = *(const float4*)&sv[rp][c];
        float4 bu4 = *(const float4*)&sbu[rb][c];
        float4 bv4 = *(const float4*)&sbv[rb][c];
        float uo[4] = {uo4.x, uo4.y, uo4.z, uo4.w};
        float vo[4] = {vo4.x, vo4.y, vo4.z, vo4.w};
        float bu0[4] = {bu4.x, bu4.y, bu4.z, bu4.w};
        float bv0[4] = {bv4.x, bv4.y, bv4.z, bv4.w};
        float ou[4], ov[4];
        {
            float R[3][6];
#pragma unroll
            for (int j = 0; j < 3; j++) {
                const float* rp_ = &sbu[rb - 1 + j][0];
                float4 m = *(const float4*)(rp_ + c);
                R[j][0]=rp_[c-1]; R[j][1]=m.x; R[j][2]=m.y; R[j][3]=m.z; R[j][4]=m.w; R[j][5]=rp_[c+4];
            }
#pragma unroll
            for (int k = 0; k < 4; k++) {
                float ADx = (R[0][k+2]-R[0][k] + 4.f*(R[1][k+2]-R[1][k]) + R[2][k+2]-R[2][k]) * C12;
                float ADy = (R[2][k]+4.f*R[2][k+1]+R[2][k+2] - R[0][k]-4.f*R[0][k+1]-R[0][k+2]) * C12;
                float c0 = R[1][k+1];
                float AD2 = (R[0][k]+R[0][k+1]+R[0][k+2]+R[1][k]+R[1][k+2]
                           + R[2][k]+R[2][k+1]+R[2][k+2] - 8.f*c0) * C3;
                ou[k] = uo[k] + NU*AD2*DT - bu0[k]*ADx*DT - bv0[k]*ADy*DT;
            }
        }
        {
            float R[3][6];
#pragma unroll
            for (int j = 0; j < 3; j++) {
                const float* rp_ = &sbv[rb - 1 + j][0];
                float4 m = *(const float4*)(rp_ + c);
                R[j][0]=rp_[c-1]; R[j][1]=m.x; R[j][2]=m.y; R[j][3]=m.z; R[j][4]=m.w; R[j][5]=rp_[c+4];
            }
#pragma unroll
            for (int k = 0; k < 4; k++) {
                float ADx = (R[0][k+2]-R[0][k] + 4.f*(R[1][k+2]-R[1][k]) + R[2][k+2]-R[2][k]) * C12;
                float ADy = (R[2][k]+4.f*R[2][k+1]+R[2][k+2] - R[0][k]-4.f*R[0][k+1]-R[0][k+2]) * C12;
                float c0 = R[1][k+1];
                float AD2 = (R[0][k]+R[0][k+1]+R[0][k+2]+R[1][k]+R[1][k+2]
                           + R[2][k]+R[2][k+1]+R[2][k+2] - 8.f*c0) * C3;
                ov[k] = vo[k] + NU*AD2*DT - bu0[k]*ADx*DT - bv0[k]*ADy*DT;
            }
        }
        {
            float R[3][6];
#pragma unroll
            for (int j = 0; j < 3; j++) {
                const float* rp_ = &sp[rp - 1 + j][0];
                float4 m = *(const float4*)(rp_ + c);
                R[j][0]=rp_[c-1]; R[j][1]=m.x; R[j][2]=m.y; R[j][3]=m.z; R[j][4]=m.w; R[j][5]=rp_[c+4];
            }
#pragma unroll
            for (int k = 0; k < 4; k++) {
                float Gx = (R[0][k+2]-R[0][k] + 4.f*(R[1][k+2]-R[1][k]) + R[2][k+2]-R[2][k]) * (C12 * DT);
                float Gy = (R[2][k]+4.f*R[2][k+1]+R[2][k+2] - R[0][k]-4.f*R[0][k+1]-R[0][k+2]) * (C12 * DT);
                ou[k] -= Gx; ov[k] -= Gy;
            }
        }
        float4 sg4 = *(const float4*)(sig + gy * NXg + (x0 - 4 + c));
        float sgv[4] = {sg4.x, sg4.y, sg4.z, sg4.w};
#pragma unroll
        for (int k = 0; k < 4; k++) {
            float damp = 1.0f / (1.0f + DT * sgv[k]);
            ou[k] *= damp; ov[k] *= damp;
        }
        *(float4*)&su2[ry][c] = make_float4(ou[0], ou[1], ou[2], ou[3]);
        *(float4*)&sv2[ry][c] = make_float4(ov[0], ov[1], ov[2], ov[3]);
    }
    if (t < 20) {
        int ry = t >> 1;
        int c = (t & 1) ? 132 : 3;
        int gy = y0 - 1 + ry, gx = x0 - 4 + c;
        if (gy < 0 || gy >= NYg || gx < 0) { su2[ry][c] = UB; sv2[ry][c] = 0.0f; }
        else if (gx < NXg) {
            int rb = ry + 1, rp = ry + 2;
            float umm=sbu[rb-1][c-1], um0=sbu[rb-1][c], ump=sbu[rb-1][c+1];
            float u0m=sbu[rb  ][c-1], bu0=sbu[rb  ][c], u0p=sbu[rb  ][c+1];
            float upm=sbu[rb+1][c-1], up0=sbu[rb+1][c], upp=sbu[rb+1][c+1];
            float vmm=sbv[rb-1][c-1], vm0=sbv[rb-1][c], vmp=sbv[rb-1][c+1];
            float v0m=sbv[rb  ][c-1], bv0=sbv[rb  ][c], v0p=sbv[rb  ][c+1];
            float vpm=sbv[rb+1][c-1], vp0=sbv[rb+1][c], vpp=sbv[rb+1][c+1];
            float pmm=sp[rp-1][c-1], pm0=sp[rp-1][c], pmp=sp[rp-1][c+1];
            float p0m=sp[rp  ][c-1],                  p0p=sp[rp  ][c+1];
            float ppm=sp[rp+1][c-1], pp0=sp[rp+1][c], ppp=sp[rp+1][c+1];
            float ADx_u = (-umm + ump - 4.0f*u0m + 4.0f*u0p - upm + upp) * C12;
            float ADy_u = (-umm - 4.0f*um0 - ump + upm + 4.0f*up0 + upp) * C12;
            float AD2_u = (umm + um0 + ump + u0m + u0p + upm + up0 + upp - 8.0f*bu0) * C3;
            float ADx_v = (-vmm + vmp - 4.0f*v0m + 4.0f*v0p - vpm + vpp) * C12;
            float ADy_v = (-vmm - 4.0f*vm0 - vmp + vpm + 4.0f*vp0 + vpp) * C12;
            float AD2_v = (vmm + vm0 + vmp + v0m + v0p + vpm + vp0 + vpp - 8.0f*bv0) * C3;
            float Gx = (-pmm + pmp - 4.0f*p0m + 4.0f*p0p - ppm + ppp) * (C12 * DT);
            float Gy = (-pmm - 4.0f*pm0 - pmp + ppm + 4.0f*pp0 + ppp) * (C12 * DT);
            float damp = 1.0f / (1.0f + DT * sig[gy * NXg + gx]);
            su2[ry][c] = (su[rp][c] + NU*AD2_u*DT - bu0*ADx_u*DT - bv0*ADy_u*DT - Gx) * damp;
            sv2[ry][c] = (sv[rp][c] + NU*AD2_v*DT - bu0*ADx_v*DT - bv0*ADy_v*DT - Gy) * damp;
        }
    }
    __syncthreads();
    if (x0 + 128 == NXg && t < 10) { su2[t][132] = su2[t][131]; sv2[t][132] = sv2[t][131]; }
    __syncthreads();

    int ty = t >> 5, tx = t & 31;
    int gy = y0 + ty, gxb = x0 + tx * 4;
    int i = gy * NXg + gxb;
    float ob[4], ou[4], ov[4];
#pragma unroll
    for (int k = 0; k < 4; k++) {
        int c = tx * 4 + k + 4;
        float dudx = (-su2[ty][c-1] + su2[ty][c+1] - 4.0f*su2[ty+1][c-1] + 4.0f*su2[ty+1][c+1]
                      - su2[ty+2][c-1] + su2[ty+2][c+1]) * C12;
        float dvdy = (-sv2[ty][c-1] - 4.0f*sv2[ty][c] - sv2[ty][c+1]
                      + sv2[ty+2][c-1] + 4.0f*sv2[ty+2][c] + sv2[ty+2][c+1]) * C12;
        ob[k] = -(dudx + dvdy) * (1.0f / DT);
        ou[k] = su2[ty+1][c];
        ov[k] = sv2[ty+1][c];
    }
    *(float4*)(bg  + i) = make_float4(ob[0], ob[1], ob[2], ob[3]);
    *(float4*)(u2g + i) = make_float4(ou[0], ou[1], ou[2], ou[3]);
    *(float4*)(v2g + i) = make_float4(ov[0], ov[1], ov[2], ov[3]);
    __syncthreads();
#pragma unroll
    for (int k = 0; k < 4; k++) sb[ty * 130 + tx * 4 + k] = ob[k];
    __syncthreads();

    {
        int ry = t >> 6, rx = t & 63;
        int fy = 2 * ry, fx = 2 * rx;
        float s[4][4];
#pragma unroll
        for (int r = 0; r < 4; r++)
#pragma unroll
            for (int c = 0; c < 4; c++)
                s[r][c] = sp[fy + r + 2][fx + 3 + c];
        float h[4][2];
#pragma unroll
        for (int r = 0; r < 4; r++) {
            h[r][0] = s[r][0] + s[r][1] + s[r][2];
            h[r][1] = s[r][1] + s[r][2] + s[r][3];
        }
        float b00 = sb[fy * 130 + fx],       b01 = sb[fy * 130 + fx + 1];
        float b10 = sb[(fy + 1) * 130 + fx], b11 = sb[(fy + 1) * 130 + fx + 1];
        float acc = 0.0f;
        acc += (h[0][0] + h[1][0] + h[2][0] - 9.0f * s[1][1]) * C3 - b00;
        acc += (h[0][1] + h[1][1] + h[2][1] - 9.0f * s[1][2]) * C3 - b01;
        acc += (h[1][0] + h[2][0] + h[3][0] - 9.0f * s[2][1]) * C3 - b10;
        acc += (h[1][1] + h[2][1] + h[3][1] - 9.0f * s[2][2]) * C3 - b11;
        float r1v = 0.25f * acc;
        int bx = blockIdx.x, by = blockIdx.y;
        r1o[(4 * by + ry) * 1024 + 64 * bx + rx] = r1v;
        s1[ry * 64 + rx] = r1v;
        __syncthreads();
        if (t < 64) {
            int ty2 = t >> 5, tx2 = t & 31;
            float v = 0.25f * (s1[2*ty2*64 + 2*tx2] + s1[2*ty2*64 + 2*tx2 + 1]
                             + s1[(2*ty2+1)*64 + 2*tx2] + s1[(2*ty2+1)*64 + 2*tx2 + 1]);
            r2o[(2 * by + ty2) * 512 + 32 * bx + tx2] = v;
            s2[ty2 * 32 + tx2] = v;
        }
        __syncthreads();
        if (t < 16) {
            float v = 0.25f * (s2[2*t] + s2[2*t + 1] + s2[32 + 2*t] + s2[32 + 2*t + 1]);
            r3o[by * 256 + 16 * bx + t] = v;
        }
    }
}

// ---------- coarse pyramid: r3 -> ... -> A4 (r4 cached, prolong up-sweep) ----------
__global__ __launch_bounds__(1024) void k_coarse(
    const float* __restrict__ r3, float* __restrict__ A4g)
{
    __shared__ float sr4[64 * 128];
    __shared__ float sr5[32 * 64];
    __shared__ float sr6[16 * 32], sr7[8 * 16], sr8[4 * 8], sr9[8];
    __shared__ float sA10[2], sA9[8], sA8[32];
    __shared__ float sA7h[10][18];
    __shared__ float sA6h[18][34];
    __shared__ float sA5h[34][66];
    int t = threadIdx.x;

    for (int i = t; i < 10 * 18; i += 1024) (&sA7h[0][0])[i] = 0.0f;
    for (int i = t; i < 18 * 34; i += 1024) (&sA6h[0][0])[i] = 0.0f;
    for (int i = t; i < 34 * 66; i += 1024) (&sA5h[0][0])[i] = 0.0f;

    cudaTriggerProgrammaticLaunchCompletion();
    cudaGridDependencySynchronize();

    for (int i = t; i < 2048; i += 1024) {
        int y = i >> 6, x = i & 63;
        float4 q0 = *(const float4*)(r3 + (4 * y    ) * 256 + 4 * x);
        float4 q1 = *(const float4*)(r3 + (4 * y + 1) * 256 + 4 * x);
        float4 q2 = *(const float4*)(r3 + (4 * y + 2) * 256 + 4 * x);
        float4 q3 = *(const float4*)(r3 + (4 * y + 3) * 256 + 4 * x);
        float a00 = q0.x + q0.y + q1.x + q1.y;
        float a01 = q0.z + q0.w + q1.z + q1.w;
        float a10 = q2.x + q2.y + q3.x + q3.y;
        float a11 = q2.z + q2.w + q3.z + q3.w;
        sr4[(2*y) * 128 + 2*x]     = 0.25f * a00;
        sr4[(2*y) * 128 + 2*x + 1] = 0.25f * a01;
        sr4[(2*y+1) * 128 + 2*x]     = 0.25f * a10;
        sr4[(2*y+1) * 128 + 2*x + 1] = 0.25f * a11;
        sr5[i] = 0.0625f * (a00 + a01 + a10 + a11);
    }
    __syncthreads();

    if (t < 512) {
        int y = t >> 5, x = t & 31;
        sr6[t] = 0.25f * (sr5[(2*y)*64 + 2*x] + sr5[(2*y)*64 + 2*x + 1]
                        + sr5[(2*y+1)*64 + 2*x] + sr5[(2*y+1)*64 + 2*x + 1]);
    } else if (t < 640) {
        int i = t - 512; int y = i >> 4, x = i & 15;
        float s = 0.0f;
#pragma unroll
        for (int dy = 0; dy < 4; dy++)
#pragma unroll
            for (int dx = 0; dx < 4; dx++)
                s += sr5[(4*y + dy)*64 + 4*x + dx];
        sr7[i] = 0.0625f * s;
    } else if (t < 672) {
        int i = t - 640; int y = i >> 3, x = i & 7;
        float s = 0.0f;
        for (int dy = 0; dy < 8; dy++)
#pragma unroll
            for (int dx = 0; dx < 8; dx++)
                s += sr5[(8*y + dy)*64 + 8*x + dx];
        sr8[i] = 0.015625f * s;
    }
    __syncthreads();

    if (t < 32) {
        if (t < 8) {
            int y = t >> 2, x = t & 3;
            sr9[t] = 0.25f * (sr8[(2*y)*8 + 2*x] + sr8[(2*y)*8 + 2*x + 1]
                            + sr8[(2*y+1)*8 + 2*x] + sr8[(2*y+1)*8 + 2*x + 1]);
        }
        __syncwarp();
        if (t < 2) {
            float r10 = 0.25f * (sr9[2*t] + sr9[2*t + 1] + sr9[4 + 2*t] + sr9[4 + 2*t + 1]);
            sA10[t] = -0.375f * r10;
        }
        __syncwarp();
        if (t < 8) {
            int y = t >> 2, x = t & 3;
            float S = 0.0f;
#pragma unroll
            for (int dy = -1; dy <= 1; dy++)
#pragma unroll
                for (int dx = -1; dx <= 1; dx++) {
                    if (dy == 0 && dx == 0) continue;
                    int yy = y + dy, xx = x + dx;
                    if (yy >= 0 && yy < 2 && xx >= 0 && xx < 4) S += sA10[xx >> 1];
                }
            sA9[t] = 0.125f * S - 0.375f * sr9[t];
        }
        __syncwarp();
        {
            int y = t >> 3, x = t & 7;
            float S = 0.0f;
#pragma unroll
            for (int dy = -1; dy <= 1; dy++)
#pragma unroll
                for (int dx = -1; dx <= 1; dx++) {
                    if (dy == 0 && dx == 0) continue;
                    int yy = y + dy, xx = x + dx;
                    if (yy >= 0 && yy < 4 && xx >= 0 && xx < 8) S += sA9[(yy >> 1) * 4 + (xx >> 1)];
                }
            sA8[t] = 0.125f * S - 0.375f * sr8[t];
        }
    }
    __syncthreads();

    if (t < 128) {
        int y = t >> 4, x = t & 15;
        float S = 0.0f;
#pragma unroll
        for (int dy = -1; dy <= 1; dy++)
#pragma unroll
            for (int dx = -1; dx <= 1; dx++) {
                if (dy == 0 && dx == 0) continue;
                int yy = y + dy, xx = x + dx;
                if (yy >= 0 && yy < 8 && xx >= 0 && xx < 16) S += sA8[(yy >> 1) * 8 + (xx >> 1)];
            }
        sA7h[1 + y][1 + x] = 0.125f * S - 0.375f * sr7[t];
    }
    __syncthreads();
    if (t < 512) {
        int y = t >> 5, x = t & 31;
        sA6h[1 + y][1 + x] = 0.125f * prolong_S8(&sA7h[1][1], 18, 0, 0, y, x)
                           - 0.375f * sr6[t];
    }
    __syncthreads();
    for (int i = t; i < 2048; i += 1024) {
        int y = i >> 6, x = i & 63;
        sA5h[1 + y][1 + x] = 0.125f * prolong_S8(&sA6h[1][1], 34, 0, 0, y, x)
                           - 0.375f * sr5[i];
    }
    __syncthreads();
    for (int i = t; i < 64 * 128; i += 1024) {
        int y = i >> 7, x = i & 127;
        A4g[i] = 0.125f * prolong_S8(&sA5h[1][1], 66, 0, 0, y, x)
               - 0.375f * sr4[i];
    }
}

// ============ fused up-sweep + fine smooth + (residual pyramid | projection) ============
// 128x16 tile (grid 16x64), single wave. A3 computed directly from global A4
// (removes sA4 staging + one barrier from the post-sync tail).
template<bool FINAL>
__global__ __launch_bounds__(256) void k_up(
    const float* __restrict__ p, const float* __restrict__ b,
    const float* __restrict__ r1, const float* __restrict__ r2,
    const float* __restrict__ r3, const float* __restrict__ A4,
    float* __restrict__ pn,
    float* __restrict__ r1o, float* __restrict__ r2o, float* __restrict__ r3o,
    const float* __restrict__ u2, const float* __restrict__ v2,
    const float* __restrict__ sig, float* __restrict__ out)
{
    __shared__ float sp[20][136];
    __shared__ float spn[18][136];
    __shared__ float sA1[12][68];
    __shared__ float sA2[8][36];
    __shared__ float sA3[6][20];
    __shared__ float s1[8 * 64];
    __shared__ float s2[4 * 32];

    int bx = blockIdx.x, by = blockIdx.y;
    int x0 = bx * 128, y0 = by * 16;
    int t = threadIdx.x;
    int y3b = 2 * by - 2, x3b = 16 * bx - 2;
    int y2b = 4 * by - 2, x2b = 32 * bx - 2;
    int y1b = 8 * by - 2, x1b = 64 * bx - 2;

    // ================= PREAMBLE =================
    for (int idx = t; idx < 20 * 34; idx += 256) {
        int ry = idx / 34, rc = idx - ry * 34;
        int gy = y0 - 2 + ry, gx = x0 - 4 + rc * 4;
        float4 c;
        if (gy >= 0 && gy < NYg && gx >= 0 && gx + 3 < NXg)
            c = *(const float4*)(p + gy * NXg + gx);
        else
            c = make_float4(ldP(p,gy,gx), ldP(p,gy,gx+1), ldP(p,gy,gx+2), ldP(p,gy,gx+3));
        *(float4*)&sp[ry][rc * 4] = c;
    }
    float rv3 = 0.0f, rv2[2] = {0.0f, 0.0f}, rv1[4] = {0.0f, 0.0f, 0.0f, 0.0f};
    if (t < 120) {
        int ly = t / 20, lx = t - ly * 20;
        int y3 = y3b + ly, x3 = x3b + lx;
        if (y3 >= 0 && y3 < 128 && x3 >= 0 && x3 < 256) rv3 = r3[y3 * 256 + x3];
    }
#pragma unroll
    for (int j = 0; j < 2; j++) {
        int i = t + j * 256;
        if (i < 8 * 36) {
            int ly = i / 36, lx = i - ly * 36;
            int y2 = y2b + ly, x2 = x2b + lx;
            if (y2 >= 0 && y2 < 256 && x2 >= 0 && x2 < 512) rv2[j] = r2[y2 * 512 + x2];
        }
    }
#pragma unroll
    for (int j = 0; j < 4; j++) {
        int i = t + j * 256;
        if (i < 12 * 68) {
            int ly = i / 68, lx = i - ly * 68;
            int y1 = y1b + ly, x1 = x1b + lx;
            if (x1 < 1024) {
                int y1c = min(max(y1, 0), 511), x1c = max(x1, 0);
                rv1[j] = r1[y1c * 1024 + x1c];
            }
        }
    }
    __syncthreads();

    // staging: T = 0.125*S8(bc_p(p)) - 0.375*b for all 18 rows
    for (int idx = t; idx < 18 * 32; idx += 256) {
        int ry = idx >> 5, q = idx & 31;
        int gy = y0 - 1 + ry;
        if (gy < 0 || gy >= NYg) continue;
        int r = ry + 1;
        int c = 4 + 4 * q;
        float row[3][6];
#pragma unroll
        for (int j = 0; j < 3; j++) {
            const float* rp_ = &sp[r - 1 + j][0];
            float4 m = *(const float4*)(rp_ + c);
            row[j][0] = rp_[c - 1];
            row[j][1] = m.x; row[j][2] = m.y; row[j][3] = m.z; row[j][4] = m.w;
            row[j][5] = rp_[c + 4];
        }
        float h[6];
#pragma unroll
        for (int j = 0; j < 6; j++) h[j] = row[0][j] + row[1][j] + row[2][j];
        float4 b4 = *(const float4*)(b + gy * NXg + x0 + 4 * q);
        float bb[4] = {b4.x, b4.y, b4.z, b4.w};
        float T[4];
#pragma unroll
        for (int k = 0; k < 4; k++) {
            float S8 = h[k] + h[k + 1] + h[k + 2] - row[1][k + 1];
            T[k] = 0.125f * S8 - 0.375f * bb[k];
        }
        *(float4*)&spn[ry][c] = make_float4(T[0], T[1], T[2], T[3]);
    }
    if (t < 36) {
        int ry = t >> 1;
        int c = (t & 1) ? 132 : 3;
        int gy = y0 - 1 + ry, gx = x0 - 4 + c;
        if (gy >= 0 && gy < NYg && gx >= 0 && gx < NXg) {
            int r = ry + 1;
            float S = sp[r-1][c-1] + sp[r-1][c] + sp[r-1][c+1]
                    + sp[r  ][c-1] +              sp[r  ][c+1]
                    + sp[r+1][c-1] + sp[r+1][c] + sp[r+1][c+1];
            spn[ry][c] = 0.125f * S - 0.375f * b[gy * NXg + gx];
        }
    }

    // ================= wait for k_coarse (A4) =================
    cudaGridDependencySynchronize();

    // A3 directly from global A4 (zero-pad outside [0,64)x[0,128))
    if (t < 120) {
        int ly = t / 20, lx = t - ly * 20;
        int y3 = y3b + ly, x3 = x3b + lx;
        float val = 0.0f;
        if (y3 >= 0 && y3 < 128 && x3 >= 0 && x3 < 256) {
            int yc = (y3 - 1) >> 1, xc = (x3 - 1) >> 1;
            int py = y3 & 1, px = x3 & 1;
            float V00 = (yc >= 0 && xc >= 0)          ? A4[yc * 128 + xc]           : 0.0f;
            float V01 = (yc >= 0 && xc + 1 < 128)     ? A4[yc * 128 + xc + 1]       : 0.0f;
            float V10 = (yc + 1 < 64 && xc >= 0)      ? A4[(yc + 1) * 128 + xc]     : 0.0f;
            float V11 = (yc + 1 < 64 && xc + 1 < 128) ? A4[(yc + 1) * 128 + xc + 1] : 0.0f;
            float wr0 = (float)(1 + py), wr1 = (float)(2 - py);
            float wc0 = (float)(1 + px), wc1 = (float)(2 - px);
            float S9 = wr0 * (wc0 * V00 + wc1 * V01) + wr1 * (wc0 * V10 + wc1 * V11);
            float ctr = py ? (px ? V00 : V01) : (px ? V10 : V11);
            val = 0.125f * (S9 - ctr) - 0.375f * rv3;
        }
        sA3[ly][lx] = val;
    }
    __syncthreads();
#pragma unroll
    for (int j = 0; j < 2; j++) {
        int i = t + j * 256;
        if (i < 8 * 36) {
            int ly = i / 36, lx = i - ly * 36;
            int y2 = y2b + ly, x2 = x2b + lx;
            float val = 0.0f;
            if (y2 >= 0 && y2 < 256 && x2 >= 0 && x2 < 512)
                val = 0.125f * prolong_S8(&sA3[0][0], 20, y3b, x3b, y2, x2) - 0.375f * rv2[j];
            sA2[ly][lx] = val;
        }
    }
    __syncthreads();
#pragma unroll
    for (int j = 0; j < 4; j++) {
        int i = t + j * 256;
        if (i < 12 * 68) {
            int ly = i / 68, lx = i - ly * 68;
            int y1 = y1b + ly, x1 = x1b + lx;
            float val = 0.0f;
            if (x1 < 1024) {
                int y1c = min(max(y1, 0), 511), x1c = max(x1, 0);
                val = 0.125f * prolong_S8(&sA2[0][0], 36, y2b, x2b, y1c, x1c) - 0.375f * rv1[j];
            }
            sA1[ly][lx] = val;
        }
    }
    __syncthreads();

    // finalize: pn = T - 0.125*Sa
    for (int idx = t; idx < 18 * 32; idx += 256) {
        int ry = idx >> 5, q = idx & 31;
        int gy = y0 - 1 + ry;
        if (gy < 0 || gy >= NYg) continue;
        int c = 4 + 4 * q;
        int gxb = x0 + 4 * q;
        float4 tv = *(const float4*)&spn[ry][c];
        float T[4] = {tv.x, tv.y, tv.z, tv.w};
        int py = gy & 1;
        int r0 = ((gy - 1) >> 1) - y1b;
        int C  = (gxb >> 1) - x1b;
        const float* R0 = &sA1[r0][0];
        const float* R1 = &sA1[r0 + 1][0];
        const float* Rc = py ? R0 : R1;
        float w0 = py ? 2.0f : 1.0f, w1 = 3.0f - w0;
        float rs[4];
#pragma unroll
        for (int j = 0; j < 4; j++) rs[j] = w0 * R0[C - 1 + j] + w1 * R1[C - 1 + j];
        float Sa[4];
        Sa[0] = rs[0] + 2.0f * rs[1] - Rc[C];
        Sa[1] = 2.0f * rs[1] + rs[2] - Rc[C];
        Sa[2] = rs[1] + 2.0f * rs[2] - Rc[C + 1];
        Sa[3] = 2.0f * rs[2] + rs[3] - Rc[C + 1];
        *(float4*)&spn[ry][c] = make_float4(T[0] - 0.125f * Sa[0], T[1] - 0.125f * Sa[1],
                                            T[2] - 0.125f * Sa[2], T[3] - 0.125f * Sa[3]);
    }
    if (t < 36) {
        int ry = t >> 1;
        int c = (t & 1) ? 132 : 3;
        int gy = y0 - 1 + ry, gx = x0 - 4 + c;
        if (gy >= 0 && gy < NYg && gx >= 0 && gx < NXg) {
            float Sa = prolong_S8(&sA1[0][0], 68, y1b, x1b, gy, gx);
            spn[ry][c] -= 0.125f * Sa;
        }
    }
    __syncthreads();
    if (t < 18) {
        if (bx == 0) {
            int src = (by == 0 && t == 0) ? 1 : ((by == 63 && t == 17) ? 16 : t);
            spn[t][3] = spn[src][4];
        }
        if (bx == 15) spn[t][132] = 0.0f;
    }
    if (by == 0) {
        for (int c = t; c < 130; c += 256) {
            float v;
            if (c == 0 && bx == 0)         v = spn[1][4];
            else if (c == 129 && bx == 15) v = 0.0f;
            else                           v = spn[1][c + 3];
            spn[0][c + 3] = v;
        }
    }
    if (by == 63) {
        for (int c = t; c < 130; c += 256) {
            float v;
            if (c == 0 && bx == 0)         v = spn[16][4];
            else if (c == 129 && bx == 15) v = 0.0f;
            else                           v = spn[16][c + 3];
            spn[17][c + 3] = v;
        }
    }
    __syncthreads();

    if constexpr (!FINAL) {
        for (int idx = t; idx < 512; idx += 256) {
            int ry = idx >> 5, q = idx & 31;
            int i = (y0 + ry) * NXg + x0 + 4 * q;
            *(float4*)(pn + i) = *(float4*)&spn[ry + 1][4 + 4 * q];
        }
#pragma unroll
        for (int j = 0; j < 2; j++) {
            int idx = t + j * 256;
            int ry = idx >> 6, rx = idx & 63;
            int fy = 2 * ry, fx = 2 * rx;
            float s[4][4];
#pragma unroll
            for (int r = 0; r < 4; r++)
#pragma unroll
                for (int c = 0; c < 4; c++)
                    s[r][c] = spn[fy + r][fx + 3 + c];
            float h2[4][2];
#pragma unroll
            for (int r = 0; r < 4; r++) {
                h2[r][0] = s[r][0] + s[r][1] + s[r][2];
                h2[r][1] = s[r][1] + s[r][2] + s[r][3];
            }
            float2 b0 = *(const float2*)(b + (y0 + fy) * NXg + x0 + fx);
            float2 b1 = *(const float2*)(b + (y0 + fy + 1) * NXg + x0 + fx);
            float acc = 0.0f;
            acc += (h2[0][0] + h2[1][0] + h2[2][0] - 9.0f * s[1][1]) * C3 - b0.x;
            acc += (h2[0][1] + h2[1][1] + h2[2][1] - 9.0f * s[1][2]) * C3 - b0.y;
            acc += (h2[1][0] + h2[2][0] + h2[3][0] - 9.0f * s[2][1]) * C3 - b1.x;
            acc += (h2[1][1] + h2[2][1] + h2[3][1] - 9.0f * s[2][2]) * C3 - b1.y;
            float r1v = 0.25f * acc;
            r1o[(8 * by + ry) * 1024 + 64 * bx + rx] = r1v;
            s1[ry * 64 + rx] = r1v;
        }
        __syncthreads();
        if (t < 128) {
            int ty2 = t >> 5, tx2 = t & 31;
            float v = 0.25f * (s1[2*ty2*64 + 2*tx2] + s1[2*ty2*64 + 2*tx2 + 1]
                             + s1[(2*ty2+1)*64 + 2*tx2] + s1[(2*ty2+1)*64 + 2*tx2 + 1]);
            r2o[(4 * by + ty2) * 512 + 32 * bx + tx2] = v;
            s2[ty2 * 32 + tx2] = v;
        }
        __syncthreads();
        if (t < 32) {
            int yy = t >> 4, xx = t & 15;
            float v = 0.25f * (s2[2*yy*32 + 2*xx] + s2[2*yy*32 + 2*xx + 1]
                             + s2[(2*yy+1)*32 + 2*xx] + s2[(2*yy+1)*32 + 2*xx + 1]);
            r3o[(2 * by + yy) * 256 + 16 * bx + xx] = v;
        }
    } else {
        for (int idx = t; idx < 512; idx += 256) {
            int ry = idx >> 5, q = idx & 31;
            int gy = y0 + ry;
            int gxb = x0 + 4 * q;
            int i = gy * NXg + gxb;
            float4 s4 = *(const float4*)(sig + i);
            float4 u4 = *(const float4*)(u2 + i);
            float4 v4 = *(const float4*)(v2 + i);
            float sg[4] = {s4.x, s4.y, s4.z, s4.w};
            float uu[4] = {u4.x, u4.y, u4.z, u4.w};
            float vv[4] = {v4.x, v4.y, v4.z, v4.w};
            float ou[4], ov[4], op[4];
#pragma unroll
            for (int k = 0; k < 4; k++) {
                int c = 4 * q + k + 4, r = ry + 1;
                float pmm = spn[r-1][c-1], pm0 = spn[r-1][c], pmp = spn[r-1][c+1];
                float p0m = spn[r  ][c-1],                     p0p = spn[r  ][c+1];
                float ppm = spn[r+1][c-1], pp0 = spn[r+1][c], ppp = spn[r+1][c+1];
                float Gx = (-pmm + pmp - 4.0f*p0m + 4.0f*p0p - ppm + ppp) * (C12 * DT);
                float Gy = (-pmm - 4.0f*pm0 - pmp + ppm + 4.0f*pp0 + ppp) * (C12 * DT);
                float damp = 1.0f / (1.0f + DT * sg[k]);
                ou[k] = (uu[k] - Gx) * damp;
                ov[k] = (vv[k] - Gy) * damp;
                op[k] = spn[r][c];
            }
            *(float4*)(out + i)            = make_float4(ou[0], ou[1], ou[2], ou[3]);
            *(float4*)(out + N0 + i)       = make_float4(ov[0], ov[1], ov[2], ov[3]);
            *(float4*)(out + 2 * N0 + i)   = make_float4(op[0], op[1], op[2], op[3]);
        }
    }
}

static float* symaddr(const void* s) {
    void* ptr = nullptr;
    cudaGetSymbolAddress(&ptr, s);
    return (float*)ptr;
}

extern "C" void kernel_launch(void* const* d_in, const int* in_sizes, int n_in,
                              void* d_out, int out_size)
{
    const float* u   = (const float*)d_in[0];
    const float* v   = (const float*)d_in[1];
    const float* p   = (const float*)d_in[2];
    const float* sig = (const float*)d_in[3];
    float* out = (float*)d_out;

    float* u2  = symaddr(g_u2);  float* v2  = symaddr(g_v2);
    float* b   = symaddr(g_b);
    float* pa  = symaddr(g_pa);  float* pb  = symaddr(g_pb);
    float* r1a = symaddr(g_r1a); float* r1b = symaddr(g_r1b);
    float* r2a = symaddr(g_r2a); float* r2b = symaddr(g_r2b);
    float* r3a = symaddr(g_r3a); float* r3b = symaddr(g_r3b);
    float* A4  = symaddr(g_A4);

    cudaLaunchAttribute attrs[1];
    attrs[0].id = cudaLaunchAttributeProgrammaticStreamSerialization;
    attrs[0].val.programmaticStreamSerializationAllowed = 1;

    cudaLaunchConfig_t cfg = {};
    cfg.stream = (cudaStream_t)0;
    cfg.attrs = attrs;
    cfg.numAttrs = 1;

    cfg.gridDim = dim3(16, 128);
    cfg.blockDim = dim3(32, 8);
    cudaLaunchKernelEx(&cfg, k_mom, u, v, p, sig, u2, v2, b, r1a, r2a, r3a);

    const float* pc = p;
    float* pn = pa;
    for (int it = 0; it < 5; it++) {
        bool even = (it & 1) == 0;
        float* r1i = even ? r1a : r1b; float* r1o = even ? r1b : r1a;
        float* r2i = even ? r2a : r2b; float* r2o = even ? r2b : r2a;
        float* r3i = even ? r3a : r3b; float* r3o = even ? r3b : r3a;

        cfg.gridDim = dim3(1, 1, 1);
        cfg.blockDim = dim3(1024, 1, 1);
        cudaLaunchKernelEx(&cfg, k_coarse, (const float*)r3i, A4);

        cfg.gridDim = dim3(16, 64);
        cfg.blockDim = dim3(256, 1, 1);
        if (it < 4) {
            cudaLaunchKernelEx(&cfg, k_up<false>,
                pc, (const float*)b, (const float*)r1i, (const float*)r2i,
                (const float*)r3i, (const float*)A4, pn, r1o, r2o, r3o,
                (const float*)nullptr, (const float*)nullptr,
                (const float*)nullptr, (float*)nullptr);
            pc = pn;
            pn = (pn == pa) ? pb : pa;
        } else {
            cudaLaunchKernelEx(&cfg, k_up<true>,
                pc, (const float*)b, (const float*)r1i, (const float*)r2i,
                (const float*)r3i, (const float*)A4, (float*)nullptr,
                (float*)nullptr, (float*)nullptr, (float*)nullptr,
                (const float*)u2, (const float*)v2, (const float*)sig, out);
        }
    }
}

// round 16
// speedup vs baseline: 1.1340x; 1.0088x over previous
#include <cuda_runtime.h>

constexpr int NYg = 1024;
constexpr int NXg = 2048;
constexpr int N0  = NYg * NXg;
constexpr float DT = 0.1f;
constexpr float NU = 0.01f;
constexpr float UB = 1.0f;
constexpr float C12 = 1.0f / 12.0f;
constexpr float C3  = 1.0f / 3.0f;

__device__ float g_u2[N0];
__device__ float g_v2[N0];
__device__ float g_b [N0];
__device__ float g_pa[N0];
__device__ float g_pb[N0];
__device__ float g_r1a[512 * 1024];
__device__ float g_r1b[512 * 1024];
__device__ float g_r2a[256 * 512];
__device__ float g_r2b[256 * 512];
__device__ float g_r3a[128 * 256];
__device__ float g_r3b[128 * 256];
__device__ float g_A4[64 * 128];

// ---------- boundary-condition loaders ----------
__device__ __forceinline__ float ldU(const float* __restrict__ u, int y, int x) {
    if (y < 0 || y >= NYg) return UB;
    if (x < 0) return UB;
    if (x >= NXg) return u[y * NXg + NXg - 1];
    return u[y * NXg + x];
}
__device__ __forceinline__ float ldV(const float* __restrict__ v, int y, int x) {
    if (x >= NXg) { if (y < 0 || y >= NYg) return 0.0f; return v[y * NXg + NXg - 1]; }
    if (y < 0 || y >= NYg || x < 0) return 0.0f;
    return v[y * NXg + x];
}
__device__ __forceinline__ float ldP(const float* __restrict__ p, int y, int x) {
    if (x >= NXg) return 0.0f;
    int yy = min(max(y, 0), NYg - 1);
    int xx = max(x, 0);
    return p[yy * NXg + xx];
}

// generic prolong S8: sum of 3x3 neighborhood (excl. center) of NN-upsampled A
__device__ __forceinline__ float prolong_S8(const float* __restrict__ A, int stride,
                                            int yb, int xb, int y, int x)
{
    int r0 = ((y - 1) >> 1) - yb;
    int c0 = ((x - 1) >> 1) - xb;
    int py = y & 1, px = x & 1;
    float wr0 = (float)(1 + py), wr1 = (float)(2 - py);
    float wc0 = (float)(1 + px), wc1 = (float)(2 - px);
    const float* row0 = A + r0 * stride + c0;
    const float* row1 = row0 + stride;
    float V00 = row0[0], V01 = row0[1], V10 = row1[0], V11 = row1[1];
    float S9 = wr0 * (wc0 * V00 + wc1 * V01) + wr1 * (wc0 * V10 + wc1 * V11);
    float ctr = py ? (px ? V00 : V01) : (px ? V10 : V11);
    return S9 - ctr;
}

// ============ fused momentum + divergence + initial residual pyramid ============
__global__ __launch_bounds__(256) void k_mom(
    const float* __restrict__ u, const float* __restrict__ v,
    const float* __restrict__ p, const float* __restrict__ sig,
    float* __restrict__ u2g, float* __restrict__ v2g, float* __restrict__ bg,
    float* __restrict__ r1o, float* __restrict__ r2o, float* __restrict__ r3o)
{
    __shared__ float su[14][136], sv[14][136], sp[14][136];
    __shared__ float sbu[12][136], sbv[12][136];
    __shared__ float su2[10][136], sv2[10][136];
    float* sb = &sbu[0][0];
    float* s1 = sb + 8 * 130;
    float* s2 = s1 + 256;

    cudaGridDependencySynchronize();

    int x0 = blockIdx.x * 128, y0 = blockIdx.y * 8;
    int t = threadIdx.y * 32 + threadIdx.x;

    for (int idx = t; idx < 14 * 34; idx += 256) {
        int ry = idx / 34, rc = idx - ry * 34;
        int gy = y0 - 3 + ry, gx = x0 - 4 + rc * 4;
        float4 a, bb, c;
        if (gy >= 0 && gy < NYg && gx >= 0 && gx + 3 < NXg) {
            a  = *(const float4*)(u + gy * NXg + gx);
            bb = *(const float4*)(v + gy * NXg + gx);
            c  = *(const float4*)(p + gy * NXg + gx);
        } else {
            a  = make_float4(ldU(u,gy,gx), ldU(u,gy,gx+1), ldU(u,gy,gx+2), ldU(u,gy,gx+3));
            bb = make_float4(ldV(v,gy,gx), ldV(v,gy,gx+1), ldV(v,gy,gx+2), ldV(v,gy,gx+3));
            c  = make_float4(ldP(p,gy,gx), ldP(p,gy,gx+1), ldP(p,gy,gx+2), ldP(p,gy,gx+3));
        }
        *(float4*)&su[ry][rc*4] = a;
        *(float4*)&sv[ry][rc*4] = bb;
        *(float4*)&sp[ry][rc*4] = c;
    }
    __syncthreads();

    for (int idx = t; idx < 12 * 32; idx += 256) {
        int ry = idx >> 5, q = idx & 31;
        int c = 4 + 4 * q;
        int gy = y0 - 2 + ry;
        if (gy < 0 || gy >= NYg) {
            *(float4*)&sbu[ry][c] = make_float4(UB, UB, UB, UB);
            *(float4*)&sbv[ry][c] = make_float4(0.f, 0.f, 0.f, 0.f);
            continue;
        }
        int r = ry + 1;
        float4 vc4 = *(const float4*)&sv[r][c];
        float v00[4] = {vc4.x, vc4.y, vc4.z, vc4.w};
        float u00[4], obu[4], obv[4];
        {
            float R[3][6];
#pragma unroll
            for (int j = 0; j < 3; j++) {
                const float* rp_ = &su[r - 1 + j][0];
                float4 m = *(const float4*)(rp_ + c);
                R[j][0]=rp_[c-1]; R[j][1]=m.x; R[j][2]=m.y; R[j][3]=m.z; R[j][4]=m.w; R[j][5]=rp_[c+4];
            }
#pragma unroll
            for (int k = 0; k < 4; k++) {
                float ADx = (R[0][k+2]-R[0][k] + 4.f*(R[1][k+2]-R[1][k]) + R[2][k+2]-R[2][k]) * C12;
                float ADy = (R[2][k]+4.f*R[2][k+1]+R[2][k+2] - R[0][k]-4.f*R[0][k+1]-R[0][k+2]) * C12;
                float c0 = R[1][k+1];
                float AD2 = (R[0][k]+R[0][k+1]+R[0][k+2]+R[1][k]+R[1][k+2]
                           + R[2][k]+R[2][k+1]+R[2][k+2] - 8.f*c0) * C3;
                u00[k] = c0;
                obu[k] = c0 + 0.5f*(NU*AD2*DT - c0*ADx*DT - v00[k]*ADy*DT);
            }
        }
        {
            float R[3][6];
#pragma unroll
            for (int j = 0; j < 3; j++) {
                const float* rp_ = &sv[r - 1 + j][0];
                float4 m = *(const float4*)(rp_ + c);
                R[j][0]=rp_[c-1]; R[j][1]=m.x; R[j][2]=m.y; R[j][3]=m.z; R[j][4]=m.w; R[j][5]=rp_[c+4];
            }
#pragma unroll
            for (int k = 0; k < 4; k++) {
                float ADx = (R[0][k+2]-R[0][k] + 4.f*(R[1][k+2]-R[1][k]) + R[2][k+2]-R[2][k]) * C12;
                float ADy = (R[2][k]+4.f*R[2][k+1]+R[2][k+2] - R[0][k]-4.f*R[0][k+1]-R[0][k+2]) * C12;
                float c0 = R[1][k+1];
                float AD2 = (R[0][k]+R[0][k+1]+R[0][k+2]+R[1][k]+R[1][k+2]
                           + R[2][k]+R[2][k+1]+R[2][k+2] - 8.f*c0) * C3;
                obv[k] = c0 + 0.5f*(NU*AD2*DT - u00[k]*ADx*DT - c0*ADy*DT);
            }
        }
        {
            float R[3][6];
#pragma unroll
            for (int j = 0; j < 3; j++) {
                const float* rp_ = &sp[r - 1 + j][0];
                float4 m = *(const float4*)(rp_ + c);
                R[j][0]=rp_[c-1]; R[j][1]=m.x; R[j][2]=m.y; R[j][3]=m.z; R[j][4]=m.w; R[j][5]=rp_[c+4];
            }
#pragma unroll
            for (int k = 0; k < 4; k++) {
                float Gx = (R[0][k+2]-R[0][k] + 4.f*(R[1][k+2]-R[1][k]) + R[2][k+2]-R[2][k]) * (C12 * DT);
                float Gy = (R[2][k]+4.f*R[2][k+1]+R[2][k+2] - R[0][k]-4.f*R[0][k+1]-R[0][k+2]) * (C12 * DT);
                obu[k] -= Gx; obv[k] -= Gy;
            }
        }
        float4 sg4 = *(const float4*)(sig + gy * NXg + (x0 - 4 + c));
        float sgv[4] = {sg4.x, sg4.y, sg4.z, sg4.w};
#pragma unroll
        for (int k = 0; k < 4; k++) {
            float damp = 1.0f / (1.0f + DT * sgv[k]);
            obu[k] *= damp; obv[k] *= damp;
        }
        *(float4*)&sbu[ry][c] = make_float4(obu[0], obu[1], obu[2], obu[3]);
        *(float4*)&sbv[ry][c] = make_float4(obv[0], obv[1], obv[2], obv[3]);
    }
    if (t < 48) {
        int ry = t >> 2, ec = t & 3;
        int c = (ec < 2) ? (2 + ec) : (130 + ec);
        int gy = y0 - 2 + ry, gx = x0 - 4 + c;
        if (gy < 0 || gy >= NYg || gx < 0) { sbu[ry][c] = UB; sbv[ry][c] = 0.0f; }
        else if (gx < NXg) {
            int r = ry + 1;
            float umm=su[r-1][c-1], um0=su[r-1][c], ump=su[r-1][c+1];
            float u0m=su[r  ][c-1], u00=su[r  ][c], u0p=su[r  ][c+1];
            float upm=su[r+1][c-1], up0=su[r+1][c], upp=su[r+1][c+1];
            float vmm=sv[r-1][c-1], vm0=sv[r-1][c], vmp=sv[r-1][c+1];
            float v0m=sv[r  ][c-1], v00=sv[r  ][c], v0p=sv[r  ][c+1];
            float vpm=sv[r+1][c-1], vp0=sv[r+1][c], vpp=sv[r+1][c+1];
            float pmm=sp[r-1][c-1], pm0=sp[r-1][c], pmp=sp[r-1][c+1];
            float p0m=sp[r  ][c-1],                  p0p=sp[r  ][c+1];
            float ppm=sp[r+1][c-1], pp0=sp[r+1][c], ppp=sp[r+1][c+1];
            float ADx_u = (-umm + ump - 4.0f*u0m + 4.0f*u0p - upm + upp) * C12;
            float ADy_u = (-umm - 4.0f*um0 - ump + upm + 4.0f*up0 + upp) * C12;
            float AD2_u = (umm + um0 + ump + u0m + u0p + upm + up0 + upp - 8.0f*u00) * C3;
            float ADx_v = (-vmm + vmp - 4.0f*v0m + 4.0f*v0p - vpm + vpp) * C12;
            float ADy_v = (-vmm - 4.0f*vm0 - vmp + vpm + 4.0f*vp0 + vpp) * C12;
            float AD2_v = (vmm + vm0 + vmp + v0m + v0p + vpm + vp0 + vpp - 8.0f*v00) * C3;
            float Gx = (-pmm + pmp - 4.0f*p0m + 4.0f*p0p - ppm + ppp) * (C12 * DT);
            float Gy = (-pmm - 4.0f*pm0 - pmp + ppm + 4.0f*pp0 + ppp) * (C12 * DT);
            float damp = 1.0f / (1.0f + DT * sig[gy * NXg + gx]);
            sbu[ry][c] = (u00 + 0.5f*(NU*AD2_u*DT - u00*ADx_u*DT - v00*ADy_u*DT) - Gx) * damp;
            sbv[ry][c] = (v00 + 0.5f*(NU*AD2_v*DT - u00*ADx_v*DT - v00*ADy_v*DT) - Gy) * damp;
        }
    }
    __syncthreads();
    if (x0 + 128 == NXg && t < 12) { sbu[t][132] = sbu[t][131]; sbv[t][132] = sbv[t][131]; }
    __syncthreads();

    for (int idx = t; idx < 10 * 32; idx += 256) {
        int ry = idx >> 5, q = idx & 31;
        int c = 4 + 4 * q;
        int gy = y0 - 1 + ry;
        if (gy < 0 || gy >= NYg) {
            *(float4*)&su2[ry][c] = make_float4(UB, UB, UB, UB);
            *(float4*)&sv2[ry][c] = make_float4(0.f, 0.f, 0.f, 0.f);
            continue;
        }
        int rb = ry + 1, rp = ry + 2;
        float4 uo4 = *(const float4*)&su[rp][c];
        float4 vo4 = *(const float4*)&sv[rp][c];
        float4 bu4 = *(const float4*)&sbu[rb][c];
        float4 bv4 = *(const float4*)&sbv[rb][c];
        float uo[4] = {uo4.x, uo4.y, uo4.z, uo4.w};
        float vo[4] = {vo4.x, vo4.y, vo4.z, vo4.w};
        float bu0[4] = {bu4.x, bu4.y, bu4.z, bu4.w};
        float bv0[4] = {bv4.x, bv4.y, bv4.z, bv4.w};
        float ou[4], ov[4];
        {
            float R[3][6];
#pragma unroll
            for (int j = 0; j < 3; j++) {
                const float* rp_ = &sbu[rb - 1 + j][0];
                float4 m = *(const float4*)(rp_ + c);
                R[j][0]=rp_[c-1]; R[j][1]=m.x; R[j][2]=m.y; R[j][3]=m.z; R[j][4]=m.w; R[j][5]=rp_[c+4];
            }
#pragma unroll
            for (int k = 0; k < 4; k++) {
                float ADx = (R[0][k+2]-R[0][k] + 4.f*(R[1][k+2]-R[1][k]) + R[2][k+2]-R[2][k]) * C12;
                float ADy = (R[2][k]+4.f*R[2][k+1]+R[2][k+2] - R[0][k]-4.f*R[0][k+1]-R[0][k+2]) * C12;
                float c0 = R[1][k+1];
                float AD2 = (R[0][k]+R[0][k+1]+R[0][k+2]+R[1][k]+R[1][k+2]
                           + R[2][k]+R[2][k+1]+R[2][k+2] - 8.f*c0) * C3;
                ou[k] = uo[k] + NU*AD2*DT - bu0[k]*ADx*DT - bv0[k]*ADy*DT;
            }
        }
        {
            float R[3][6];
#pragma unroll
            for (int j = 0; j < 3; j++) {
                const float* rp_ = &sbv[rb - 1 + j][0];
                float4 m = *(const float4*)(rp_ + c);
                R[j][0]=rp_[c-1]; R[j][1]=m.x; R[j][2]=m.y; R[j][3]=m.z; R[j][4]=m.w; R[j][5]=rp_[c+4];
            }
#pragma unroll
            for (int k = 0; k < 4; k++) {
                float ADx = (R[0][k+2]-R[0][k] + 4.f*(R[1][k+2]-R[1][k]) + R[2][k+2]-R[2][k]) * C12;
                float ADy = (R[2][k]+4.f*R[2][k+1]+R[2][k+2] - R[0][k]-4.f*R[0][k+1]-R[0][k+2]) * C12;
                float c0 = R[1][k+1];
                float AD2 = (R[0][k]+R[0][k+1]+R[0][k+2]+R[1][k]+R[1][k+2]
                           + R[2][k]+R[2][k+1]+R[2][k+2] - 8.f*c0) * C3;
                ov[k] = vo[k] + NU*AD2*DT - bu0[k]*ADx*DT - bv0[k]*ADy*DT;
            }
        }
        {
            float R[3][6];
#pragma unroll
            for (int j = 0; j < 3; j++) {
                const float* rp_ = &sp[rp - 1 + j][0];
                float4 m = *(const float4*)(rp_ + c);
                R[j][0]=rp_[c-1]; R[j][1]=m.x; R[j][2]=m.y; R[j][3]=m.z; R[j][4]=m.w; R[j][5]=rp_[c+4];
            }
#pragma unroll
            for (int k = 0; k < 4; k++) {
                float Gx = (R[0][k+2]-R[0][k] + 4.f*(R[1][k+2]-R[1][k]) + R[2][k+2]-R[2][k]) * (C12 * DT);
                float Gy = (R[2][k]+4.f*R[2][k+1]+R[2][k+2] - R[0][k]-4.f*R[0][k+1]-R[0][k+2]) * (C12 * DT);
                ou[k] -= Gx; ov[k] -= Gy;
            }
        }
        float4 sg4 = *(const float4*)(sig + gy * NXg + (x0 - 4 + c));
        float sgv[4] = {sg4.x, sg4.y, sg4.z, sg4.w};
#pragma unroll
        for (int k = 0; k < 4; k++) {
            float damp = 1.0f / (1.0f + DT * sgv[k]);
            ou[k] *= damp; ov[k] *= damp;
        }
        *(float4*)&su2[ry][c] = make_float4(ou[0], ou[1], ou[2], ou[3]);
        *(float4*)&sv2[ry][c] = make_float4(ov[0], ov[1], ov[2], ov[3]);
    }
    if (t < 20) {
        int ry = t >> 1;
        int c = (t & 1) ? 132 : 3;
        int gy = y0 - 1 + ry, gx = x0 - 4 + c;
        if (gy < 0 || gy >= NYg || gx < 0) { su2[ry][c] = UB; sv2[ry][c] = 0.0f; }
        else if (gx < NXg) {
            int rb = ry + 1, rp = ry + 2;
            float umm=sbu[rb-1][c-1], um0=sbu[rb-1][c], ump=sbu[rb-1][c+1];
            float u0m=sbu[rb  ][c-1], bu0=sbu[rb  ][c], u0p=sbu[rb  ][c+1];
            float upm=sbu[rb+1][c-1], up0=sbu[rb+1][c], upp=sbu[rb+1][c+1];
            float vmm=sbv[rb-1][c-1], vm0=sbv[rb-1][c], vmp=sbv[rb-1][c+1];
            float v0m=sbv[rb  ][c-1], bv0=sbv[rb  ][c], v0p=sbv[rb  ][c+1];
            float vpm=sbv[rb+1][c-1], vp0=sbv[rb+1][c], vpp=sbv[rb+1][c+1];
            float pmm=sp[rp-1][c-1], pm0=sp[rp-1][c], pmp=sp[rp-1][c+1];
            float p0m=sp[rp  ][c-1],                  p0p=sp[rp  ][c+1];
            float ppm=sp[rp+1][c-1], pp0=sp[rp+1][c], ppp=sp[rp+1][c+1];
            float ADx_u = (-umm + ump - 4.0f*u0m + 4.0f*u0p - upm + upp) * C12;
            float ADy_u = (-umm - 4.0f*um0 - ump + upm + 4.0f*up0 + upp) * C12;
            float AD2_u = (umm + um0 + ump + u0m + u0p + upm + up0 + upp - 8.0f*bu0) * C3;
            float ADx_v = (-vmm + vmp - 4.0f*v0m + 4.0f*v0p - vpm + vpp) * C12;
            float ADy_v = (-vmm - 4.0f*vm0 - vmp + vpm + 4.0f*vp0 + vpp) * C12;
            float AD2_v = (vmm + vm0 + vmp + v0m + v0p + vpm + vp0 + vpp - 8.0f*bv0) * C3;
            float Gx = (-pmm + pmp - 4.0f*p0m + 4.0f*p0p - ppm + ppp) * (C12 * DT);
            float Gy = (-pmm - 4.0f*pm0 - pmp + ppm + 4.0f*pp0 + ppp) * (C12 * DT);
            float damp = 1.0f / (1.0f + DT * sig[gy * NXg + gx]);
            su2[ry][c] = (su[rp][c] + NU*AD2_u*DT - bu0*ADx_u*DT - bv0*ADy_u*DT - Gx) * damp;
            sv2[ry][c] = (sv[rp][c] + NU*AD2_v*DT - bu0*ADx_v*DT - bv0*ADy_v*DT - Gy) * damp;
        }
    }
    __syncthreads();
    if (x0 + 128 == NXg && t < 10) { su2[t][132] = su2[t][131]; sv2[t][132] = sv2[t][131]; }
    __syncthreads();

    int ty = t >> 5, tx = t & 31;
    int gy = y0 + ty, gxb = x0 + tx * 4;
    int i = gy * NXg + gxb;
    float ob[4], ou[4], ov[4];
#pragma unroll
    for (int k = 0; k < 4; k++) {
        int c = tx * 4 + k + 4;
        float dudx = (-su2[ty][c-1] + su2[ty][c+1] - 4.0f*su2[ty+1][c-1] + 4.0f*su2[ty+1][c+1]
                      - su2[ty+2][c-1] + su2[ty+2][c+1]) * C12;
        float dvdy = (-sv2[ty][c-1] - 4.0f*sv2[ty][c] - sv2[ty][c+1]
                      + sv2[ty+2][c-1] + 4.0f*sv2[ty+2][c] + sv2[ty+2][c+1]) * C12;
        ob[k] = -(dudx + dvdy) * (1.0f / DT);
        ou[k] = su2[ty+1][c];
        ov[k] = sv2[ty+1][c];
    }
    *(float4*)(bg  + i) = make_float4(ob[0], ob[1], ob[2], ob[3]);
    *(float4*)(u2g + i) = make_float4(ou[0], ou[1], ou[2], ou[3]);
    *(float4*)(v2g + i) = make_float4(ov[0], ov[1], ov[2], ov[3]);
    __syncthreads();
#pragma unroll
    for (int k = 0; k < 4; k++) sb[ty * 130 + tx * 4 + k] = ob[k];
    __syncthreads();

    {
        int ry = t >> 6, rx = t & 63;
        int fy = 2 * ry, fx = 2 * rx;
        float s[4][4];
#pragma unroll
        for (int r = 0; r < 4; r++)
#pragma unroll
            for (int c = 0; c < 4; c++)
                s[r][c] = sp[fy + r + 2][fx + 3 + c];
        float h[4][2];
#pragma unroll
        for (int r = 0; r < 4; r++) {
            h[r][0] = s[r][0] + s[r][1] + s[r][2];
            h[r][1] = s[r][1] + s[r][2] + s[r][3];
        }
        float b00 = sb[fy * 130 + fx],       b01 = sb[fy * 130 + fx + 1];
        float b10 = sb[(fy + 1) * 130 + fx], b11 = sb[(fy + 1) * 130 + fx + 1];
        float acc = 0.0f;
        acc += (h[0][0] + h[1][0] + h[2][0] - 9.0f * s[1][1]) * C3 - b00;
        acc += (h[0][1] + h[1][1] + h[2][1] - 9.0f * s[1][2]) * C3 - b01;
        acc += (h[1][0] + h[2][0] + h[3][0] - 9.0f * s[2][1]) * C3 - b10;
        acc += (h[1][1] + h[2][1] + h[3][1] - 9.0f * s[2][2]) * C3 - b11;
        float r1v = 0.25f * acc;
        int bx = blockIdx.x, by = blockIdx.y;
        r1o[(4 * by + ry) * 1024 + 64 * bx + rx] = r1v;
        s1[ry * 64 + rx] = r1v;
        __syncthreads();
        if (t < 64) {
            int ty2 = t >> 5, tx2 = t & 31;
            float v = 0.25f * (s1[2*ty2*64 + 2*tx2] + s1[2*ty2*64 + 2*tx2 + 1]
                             + s1[(2*ty2+1)*64 + 2*tx2] + s1[(2*ty2+1)*64 + 2*tx2 + 1]);
            r2o[(2 * by + ty2) * 512 + 32 * bx + tx2] = v;
            s2[ty2 * 32 + tx2] = v;
        }
        __syncthreads();
        if (t < 16) {
            float v = 0.25f * (s2[2*t] + s2[2*t + 1] + s2[32 + 2*t] + s2[32 + 2*t + 1]);
            r3o[by * 256 + 16 * bx + t] = v;
        }
    }
}

// ---------- coarse pyramid: r3 -> ... -> A4 (r4 cached, prolong up-sweep) ----------
__global__ __launch_bounds__(1024) void k_coarse(
    const float* __restrict__ r3, float* __restrict__ A4g)
{
    __shared__ float sr4[64 * 128];
    __shared__ float sr5[32 * 64];
    __shared__ float sr6[16 * 32], sr7[8 * 16], sr8[4 * 8], sr9[8];
    __shared__ float sA10[2], sA9[8], sA8[32];
    __shared__ float sA7h[10][18];
    __shared__ float sA6h[18][34];
    __shared__ float sA5h[34][66];
    int t = threadIdx.x;

    for (int i = t; i < 10 * 18; i += 1024) (&sA7h[0][0])[i] = 0.0f;
    for (int i = t; i < 18 * 34; i += 1024) (&sA6h[0][0])[i] = 0.0f;
    for (int i = t; i < 34 * 66; i += 1024) (&sA5h[0][0])[i] = 0.0f;

    cudaTriggerProgrammaticLaunchCompletion();
    cudaGridDependencySynchronize();

    for (int i = t; i < 2048; i += 1024) {
        int y = i >> 6, x = i & 63;
        float4 q0 = *(const float4*)(r3 + (4 * y    ) * 256 + 4 * x);
        float4 q1 = *(const float4*)(r3 + (4 * y + 1) * 256 + 4 * x);
        float4 q2 = *(const float4*)(r3 + (4 * y + 2) * 256 + 4 * x);
        float4 q3 = *(const float4*)(r3 + (4 * y + 3) * 256 + 4 * x);
        float a00 = q0.x + q0.y + q1.x + q1.y;
        float a01 = q0.z + q0.w + q1.z + q1.w;
        float a10 = q2.x + q2.y + q3.x + q3.y;
        float a11 = q2.z + q2.w + q3.z + q3.w;
        sr4[(2*y) * 128 + 2*x]     = 0.25f * a00;
        sr4[(2*y) * 128 + 2*x + 1] = 0.25f * a01;
        sr4[(2*y+1) * 128 + 2*x]     = 0.25f * a10;
        sr4[(2*y+1) * 128 + 2*x + 1] = 0.25f * a11;
        sr5[i] = 0.0625f * (a00 + a01 + a10 + a11);
    }
    __syncthreads();

    if (t < 512) {
        int y = t >> 5, x = t & 31;
        sr6[t] = 0.25f * (sr5[(2*y)*64 + 2*x] + sr5[(2*y)*64 + 2*x + 1]
                        + sr5[(2*y+1)*64 + 2*x] + sr5[(2*y+1)*64 + 2*x + 1]);
    } else if (t < 640) {
        int i = t - 512; int y = i >> 4, x = i & 15;
        float s = 0.0f;
#pragma unroll
        for (int dy = 0; dy < 4; dy++)
#pragma unroll
            for (int dx = 0; dx < 4; dx++)
                s += sr5[(4*y + dy)*64 + 4*x + dx];
        sr7[i] = 0.0625f * s;
    } else if (t < 672) {
        int i = t - 640; int y = i >> 3, x = i & 7;
        float s = 0.0f;
        for (int dy = 0; dy < 8; dy++)
#pragma unroll
            for (int dx = 0; dx < 8; dx++)
                s += sr5[(8*y + dy)*64 + 8*x + dx];
        sr8[i] = 0.015625f * s;
    }
    __syncthreads();

    if (t < 32) {
        if (t < 8) {
            int y = t >> 2, x = t & 3;
            sr9[t] = 0.25f * (sr8[(2*y)*8 + 2*x] + sr8[(2*y)*8 + 2*x + 1]
                            + sr8[(2*y+1)*8 + 2*x] + sr8[(2*y+1)*8 + 2*x + 1]);
        }
        __syncwarp();
        if (t < 2) {
            float r10 = 0.25f * (sr9[2*t] + sr9[2*t + 1] + sr9[4 + 2*t] + sr9[4 + 2*t + 1]);
            sA10[t] = -0.375f * r10;
        }
        __syncwarp();
        if (t < 8) {
            int y = t >> 2, x = t & 3;
            float S = 0.0f;
#pragma unroll
            for (int dy = -1; dy <= 1; dy++)
#pragma unroll
                for (int dx = -1; dx <= 1; dx++) {
                    if (dy == 0 && dx == 0) continue;
                    int yy = y + dy, xx = x + dx;
                    if (yy >= 0 && yy < 2 && xx >= 0 && xx < 4) S += sA10[xx >> 1];
                }
            sA9[t] = 0.125f * S - 0.375f * sr9[t];
        }
        __syncwarp();
        {
            int y = t >> 3, x = t & 7;
            float S = 0.0f;
#pragma unroll
            for (int dy = -1; dy <= 1; dy++)
#pragma unroll
                for (int dx = -1; dx <= 1; dx++) {
                    if (dy == 0 && dx == 0) continue;
                    int yy = y + dy, xx = x + dx;
                    if (yy >= 0 && yy < 4 && xx >= 0 && xx < 8) S += sA9[(yy >> 1) * 4 + (xx >> 1)];
                }
            sA8[t] = 0.125f * S - 0.375f * sr8[t];
        }
    }
    __syncthreads();

    if (t < 128) {
        int y = t >> 4, x = t & 15;
        float S = 0.0f;
#pragma unroll
        for (int dy = -1; dy <= 1; dy++)
#pragma unroll
            for (int dx = -1; dx <= 1; dx++) {
                if (dy == 0 && dx == 0) continue;
                int yy = y + dy, xx = x + dx;
                if (yy >= 0 && yy < 8 && xx >= 0 && xx < 16) S += sA8[(yy >> 1) * 8 + (xx >> 1)];
            }
        sA7h[1 + y][1 + x] = 0.125f * S - 0.375f * sr7[t];
    }
    __syncthreads();
    if (t < 512) {
        int y = t >> 5, x = t & 31;
        sA6h[1 + y][1 + x] = 0.125f * prolong_S8(&sA7h[1][1], 18, 0, 0, y, x)
                           - 0.375f * sr6[t];
    }
    __syncthreads();
    for (int i = t; i < 2048; i += 1024) {
        int y = i >> 6, x = i & 63;
        sA5h[1 + y][1 + x] = 0.125f * prolong_S8(&sA6h[1][1], 34, 0, 0, y, x)
                           - 0.375f * sr5[i];
    }
    __syncthreads();
    for (int i = t; i < 64 * 128; i += 1024) {
        int y = i >> 7, x = i & 127;
        A4g[i] = 0.125f * prolong_S8(&sA5h[1][1], 66, 0, 0, y, x)
               - 0.375f * sr4[i];
    }
}

// ============ fused up-sweep + fine smooth + (residual pyramid | projection) ============
// 128x16 tile (grid 16x64), single wave. pn streamed directly from finalize regs.
template<bool FINAL>
__global__ __launch_bounds__(256) void k_up(
    const float* __restrict__ p, const float* __restrict__ b,
    const float* __restrict__ r1, const float* __restrict__ r2,
    const float* __restrict__ r3, const float* __restrict__ A4,
    float* __restrict__ pn,
    float* __restrict__ r1o, float* __restrict__ r2o, float* __restrict__ r3o,
    const float* __restrict__ u2, const float* __restrict__ v2,
    const float* __restrict__ sig, float* __restrict__ out)
{
    __shared__ float sp[20][136];
    __shared__ float spn[18][136];
    __shared__ float sA1[12][68];
    __shared__ float sA2[8][36];
    __shared__ float sA3[6][20];
    __shared__ float s1[8 * 64];
    __shared__ float s2[4 * 32];

    int bx = blockIdx.x, by = blockIdx.y;
    int x0 = bx * 128, y0 = by * 16;
    int t = threadIdx.x;
    int y3b = 2 * by - 2, x3b = 16 * bx - 2;
    int y2b = 4 * by - 2, x2b = 32 * bx - 2;
    int y1b = 8 * by - 2, x1b = 64 * bx - 2;

    // ================= PREAMBLE =================
    for (int idx = t; idx < 20 * 34; idx += 256) {
        int ry = idx / 34, rc = idx - ry * 34;
        int gy = y0 - 2 + ry, gx = x0 - 4 + rc * 4;
        float4 c;
        if (gy >= 0 && gy < NYg && gx >= 0 && gx + 3 < NXg)
            c = *(const float4*)(p + gy * NXg + gx);
        else
            c = make_float4(ldP(p,gy,gx), ldP(p,gy,gx+1), ldP(p,gy,gx+2), ldP(p,gy,gx+3));
        *(float4*)&sp[ry][rc * 4] = c;
    }
    float rv3 = 0.0f, rv2[2] = {0.0f, 0.0f}, rv1[4] = {0.0f, 0.0f, 0.0f, 0.0f};
    if (t < 120) {
        int ly = t / 20, lx = t - ly * 20;
        int y3 = y3b + ly, x3 = x3b + lx;
        if (y3 >= 0 && y3 < 128 && x3 >= 0 && x3 < 256) rv3 = r3[y3 * 256 + x3];
    }
#pragma unroll
    for (int j = 0; j < 2; j++) {
        int i = t + j * 256;
        if (i < 8 * 36) {
            int ly = i / 36, lx = i - ly * 36;
            int y2 = y2b + ly, x2 = x2b + lx;
            if (y2 >= 0 && y2 < 256 && x2 >= 0 && x2 < 512) rv2[j] = r2[y2 * 512 + x2];
        }
    }
#pragma unroll
    for (int j = 0; j < 4; j++) {
        int i = t + j * 256;
        if (i < 12 * 68) {
            int ly = i / 68, lx = i - ly * 68;
            int y1 = y1b + ly, x1 = x1b + lx;
            if (x1 < 1024) {
                int y1c = min(max(y1, 0), 511), x1c = max(x1, 0);
                rv1[j] = r1[y1c * 1024 + x1c];
            }
        }
    }
    __syncthreads();

    // staging: T = 0.125*S8(bc_p(p)) - 0.375*b for all 18 rows
    for (int idx = t; idx < 18 * 32; idx += 256) {
        int ry = idx >> 5, q = idx & 31;
        int gy = y0 - 1 + ry;
        if (gy < 0 || gy >= NYg) continue;
        int r = ry + 1;
        int c = 4 + 4 * q;
        float row[3][6];
#pragma unroll
        for (int j = 0; j < 3; j++) {
            const float* rp_ = &sp[r - 1 + j][0];
            float4 m = *(const float4*)(rp_ + c);
            row[j][0] = rp_[c - 1];
            row[j][1] = m.x; row[j][2] = m.y; row[j][3] = m.z; row[j][4] = m.w;
            row[j][5] = rp_[c + 4];
        }
        float h[6];
#pragma unroll
        for (int j = 0; j < 6; j++) h[j] = row[0][j] + row[1][j] + row[2][j];
        float4 b4 = *(const float4*)(b + gy * NXg + x0 + 4 * q);
        float bb[4] = {b4.x, b4.y, b4.z, b4.w};
        float T[4];
#pragma unroll
        for (int k = 0; k < 4; k++) {
            float S8 = h[k] + h[k + 1] + h[k + 2] - row[1][k + 1];
            T[k] = 0.125f * S8 - 0.375f * bb[k];
        }
        *(float4*)&spn[ry][c] = make_float4(T[0], T[1], T[2], T[3]);
    }
    if (t < 36) {
        int ry = t >> 1;
        int c = (t & 1) ? 132 : 3;
        int gy = y0 - 1 + ry, gx = x0 - 4 + c;
        if (gy >= 0 && gy < NYg && gx >= 0 && gx < NXg) {
            int r = ry + 1;
            float S = sp[r-1][c-1] + sp[r-1][c] + sp[r-1][c+1]
                    + sp[r  ][c-1] +              sp[r  ][c+1]
                    + sp[r+1][c-1] + sp[r+1][c] + sp[r+1][c+1];
            spn[ry][c] = 0.125f * S - 0.375f * b[gy * NXg + gx];
        }
    }

    // ================= wait for k_coarse (A4) =================
    cudaGridDependencySynchronize();

    // A3 directly from global A4 (zero-pad outside [0,64)x[0,128))
    if (t < 120) {
        int ly = t / 20, lx = t - ly * 20;
        int y3 = y3b + ly, x3 = x3b + lx;
        float val = 0.0f;
        if (y3 >= 0 && y3 < 128 && x3 >= 0 && x3 < 256) {
            int yc = (y3 - 1) >> 1, xc = (x3 - 1) >> 1;
            int py = y3 & 1, px = x3 & 1;
            float V00 = (yc >= 0 && xc >= 0)          ? A4[yc * 128 + xc]           : 0.0f;
            float V01 = (yc >= 0 && xc + 1 < 128)     ? A4[yc * 128 + xc + 1]       : 0.0f;
            float V10 = (yc + 1 < 64 && xc >= 0)      ? A4[(yc + 1) * 128 + xc]     : 0.0f;
            float V11 = (yc + 1 < 64 && xc + 1 < 128) ? A4[(yc + 1) * 128 + xc + 1] : 0.0f;
            float wr0 = (float)(1 + py), wr1 = (float)(2 - py);
            float wc0 = (float)(1 + px), wc1 = (float)(2 - px);
            float S9 = wr0 * (wc0 * V00 + wc1 * V01) + wr1 * (wc0 * V10 + wc1 * V11);
            float ctr = py ? (px ? V00 : V01) : (px ? V10 : V11);
            val = 0.125f * (S9 - ctr) - 0.375f * rv3;
        }
        sA3[ly][lx] = val;
    }
    __syncthreads();
#pragma unroll
    for (int j = 0; j < 2; j++) {
        int i = t + j * 256;
        if (i < 8 * 36) {
            int ly = i / 36, lx = i - ly * 36;
            int y2 = y2b + ly, x2 = x2b + lx;
            float val = 0.0f;
            if (y2 >= 0 && y2 < 256 && x2 >= 0 && x2 < 512)
                val = 0.125f * prolong_S8(&sA3[0][0], 20, y3b, x3b, y2, x2) - 0.375f * rv2[j];
            sA2[ly][lx] = val;
        }
    }
    __syncthreads();
#pragma unroll
    for (int j = 0; j < 4; j++) {
        int i = t + j * 256;
        if (i < 12 * 68) {
            int ly = i / 68, lx = i - ly * 68;
            int y1 = y1b + ly, x1 = x1b + lx;
            float val = 0.0f;
            if (x1 < 1024) {
                int y1c = min(max(y1, 0), 511), x1c = max(x1, 0);
                val = 0.125f * prolong_S8(&sA2[0][0], 36, y2b, x2b, y1c, x1c) - 0.375f * rv1[j];
            }
            sA1[ly][lx] = val;
        }
    }
    __syncthreads();

    // finalize: pn = T - 0.125*Sa  (interior rows stream straight to pn)
    for (int idx = t; idx < 18 * 32; idx += 256) {
        int ry = idx >> 5, q = idx & 31;
        int gy = y0 - 1 + ry;
        if (gy < 0 || gy >= NYg) continue;
        int c = 4 + 4 * q;
        int gxb = x0 + 4 * q;
        float4 tv = *(const float4*)&spn[ry][c];
        float T[4] = {tv.x, tv.y, tv.z, tv.w};
        int py = gy & 1;
        int r0 = ((gy - 1) >> 1) - y1b;
        int C  = (gxb >> 1) - x1b;
        const float* R0 = &sA1[r0][0];
        const float* R1 = &sA1[r0 + 1][0];
        const float* Rc = py ? R0 : R1;
        float w0 = py ? 2.0f : 1.0f, w1 = 3.0f - w0;
        float rs[4];
#pragma unroll
        for (int j = 0; j < 4; j++) rs[j] = w0 * R0[C - 1 + j] + w1 * R1[C - 1 + j];
        float Sa[4];
        Sa[0] = rs[0] + 2.0f * rs[1] - Rc[C];
        Sa[1] = 2.0f * rs[1] + rs[2] - Rc[C];
        Sa[2] = rs[1] + 2.0f * rs[2] - Rc[C + 1];
        Sa[3] = 2.0f * rs[2] + rs[3] - Rc[C + 1];
        float4 o = make_float4(T[0] - 0.125f * Sa[0], T[1] - 0.125f * Sa[1],
                               T[2] - 0.125f * Sa[2], T[3] - 0.125f * Sa[3]);
        *(float4*)&spn[ry][c] = o;
        if constexpr (!FINAL) {
            if (ry >= 1 && ry <= 16)
                *(float4*)(pn + gy * NXg + gxb) = o;   // rows 1..16 = tile interior
        }
    }
    if (t < 36) {
        int ry = t >> 1;
        int c = (t & 1) ? 132 : 3;
        int gy = y0 - 1 + ry, gx = x0 - 4 + c;
        if (gy >= 0 && gy < NYg && gx >= 0 && gx < NXg) {
            float Sa = prolong_S8(&sA1[0][0], 68, y1b, x1b, gy, gx);
            spn[ry][c] -= 0.125f * Sa;
        }
    }
    __syncthreads();
    if (t < 18) {
        if (bx == 0) {
            int src = (by == 0 && t == 0) ? 1 : ((by == 63 && t == 17) ? 16 : t);
            spn[t][3] = spn[src][4];
        }
        if (bx == 15) spn[t][132] = 0.0f;
    }
    if (by == 0) {
        for (int c = t; c < 130; c += 256) {
            float v;
            if (c == 0 && bx == 0)         v = spn[1][4];
            else if (c == 129 && bx == 15) v = 0.0f;
            else                           v = spn[1][c + 3];
            spn[0][c + 3] = v;
        }
    }
    if (by == 63) {
        for (int c = t; c < 130; c += 256) {
            float v;
            if (c == 0 && bx == 0)         v = spn[16][4];
            else if (c == 129 && bx == 15) v = 0.0f;
            else                           v = spn[16][c + 3];
            spn[17][c + 3] = v;
        }
    }
    __syncthreads();

    if constexpr (!FINAL) {
        // residual of pn + restriction: r1 tile 8x64 (2 per thread)
#pragma unroll
        for (int j = 0; j < 2; j++) {
            int idx = t + j * 256;
            int ry = idx >> 6, rx = idx & 63;
            int fy = 2 * ry, fx = 2 * rx;
            float s[4][4];
#pragma unroll
            for (int r = 0; r < 4; r++)
#pragma unroll
                for (int c = 0; c < 4; c++)
                    s[r][c] = spn[fy + r][fx + 3 + c];
            float h2[4][2];
#pragma unroll
            for (int r = 0; r < 4; r++) {
                h2[r][0] = s[r][0] + s[r][1] + s[r][2];
                h2[r][1] = s[r][1] + s[r][2] + s[r][3];
            }
            float2 b0 = *(const float2*)(b + (y0 + fy) * NXg + x0 + fx);
            float2 b1 = *(const float2*)(b + (y0 + fy + 1) * NXg + x0 + fx);
            float acc = 0.0f;
            acc += (h2[0][0] + h2[1][0] + h2[2][0] - 9.0f * s[1][1]) * C3 - b0.x;
            acc += (h2[0][1] + h2[1][1] + h2[2][1] - 9.0f * s[1][2]) * C3 - b0.y;
            acc += (h2[1][0] + h2[2][0] + h2[3][0] - 9.0f * s[2][1]) * C3 - b1.x;
            acc += (h2[1][1] + h2[2][1] + h2[3][1] - 9.0f * s[2][2]) * C3 - b1.y;
            float r1v = 0.25f * acc;
            r1o[(8 * by + ry) * 1024 + 64 * bx + rx] = r1v;
            s1[ry * 64 + rx] = r1v;
        }
        __syncthreads();
        if (t < 128) {
            int ty2 = t >> 5, tx2 = t & 31;
            float v = 0.25f * (s1[2*ty2*64 + 2*tx2] + s1[2*ty2*64 + 2*tx2 + 1]
                             + s1[(2*ty2+1)*64 + 2*tx2] + s1[(2*ty2+1)*64 + 2*tx2 + 1]);
            r2o[(4 * by + ty2) * 512 + 32 * bx + tx2] = v;
            s2[ty2 * 32 + tx2] = v;
        }
        __syncthreads();
        if (t < 32) {
            int yy = t >> 4, xx = t & 15;
            float v = 0.25f * (s2[2*yy*32 + 2*xx] + s2[2*yy*32 + 2*xx + 1]
                             + s2[(2*yy+1)*32 + 2*xx] + s2[(2*yy+1)*32 + 2*xx + 1]);
            r3o[(2 * by + yy) * 256 + 16 * bx + xx] = v;
        }
    } else {
        for (int idx = t; idx < 512; idx += 256) {
            int ry = idx >> 5, q = idx & 31;
            int gy = y0 + ry;
            int gxb = x0 + 4 * q;
            int i = gy * NXg + gxb;
            float4 s4 = *(const float4*)(sig + i);
            float4 u4 = *(const float4*)(u2 + i);
            float4 v4 = *(const float4*)(v2 + i);
            float sg[4] = {s4.x, s4.y, s4.z, s4.w};
            float uu[4] = {u4.x, u4.y, u4.z, u4.w};
            float vv[4] = {v4.x, v4.y, v4.z, v4.w};
            float ou[4], ov[4], op[4];
#pragma unroll
            for (int k = 0; k < 4; k++) {
                int c = 4 * q + k + 4, r = ry + 1;
                float pmm = spn[r-1][c-1], pm0 = spn[r-1][c], pmp = spn[r-1][c+1];
                float p0m = spn[r  ][c-1],                     p0p = spn[r  ][c+1];
                float ppm = spn[r+1][c-1], pp0 = spn[r+1][c], ppp = spn[r+1][c+1];
                float Gx = (-pmm + pmp - 4.0f*p0m + 4.0f*p0p - ppm + ppp) * (C12 * DT);
                float Gy = (-pmm - 4.0f*pm0 - pmp + ppm + 4.0f*pp0 + ppp) * (C12 * DT);
                float damp = 1.0f / (1.0f + DT * sg[k]);
                ou[k] = (uu[k] - Gx) * damp;
                ov[k] = (vv[k] - Gy) * damp;
                op[k] = spn[r][c];
            }
            *(float4*)(out + i)            = make_float4(ou[0], ou[1], ou[2], ou[3]);
            *(float4*)(out + N0 + i)       = make_float4(ov[0], ov[1], ov[2], ov[3]);
            *(float4*)(out + 2 * N0 + i)   = make_float4(op[0], op[1], op[2], op[3]);
        }
    }
}

static float* symaddr(const void* s) {
    void* ptr = nullptr;
    cudaGetSymbolAddress(&ptr, s);
    return (float*)ptr;
}

extern "C" void kernel_launch(void* const* d_in, const int* in_sizes, int n_in,
                              void* d_out, int out_size)
{
    const float* u   = (const float*)d_in[0];
    const float* v   = (const float*)d_in[1];
    const float* p   = (const float*)d_in[2];
    const float* sig = (const float*)d_in[3];
    float* out = (float*)d_out;

    float* u2  = symaddr(g_u2);  float* v2  = symaddr(g_v2);
    float* b   = symaddr(g_b);
    float* pa  = symaddr(g_pa);  float* pb  = symaddr(g_pb);
    float* r1a = symaddr(g_r1a); float* r1b = symaddr(g_r1b);
    float* r2a = symaddr(g_r2a); float* r2b = symaddr(g_r2b);
    float* r3a = symaddr(g_r3a); float* r3b = symaddr(g_r3b);
    float* A4  = symaddr(g_A4);

    cudaLaunchAttribute attrs[1];
    attrs[0].id = cudaLaunchAttributeProgrammaticStreamSerialization;
    attrs[0].val.programmaticStreamSerializationAllowed = 1;

    cudaLaunchConfig_t cfg = {};
    cfg.stream = (cudaStream_t)0;
    cfg.attrs = attrs;
    cfg.numAttrs = 1;

    cfg.gridDim = dim3(16, 128);
    cfg.blockDim = dim3(32, 8);
    cudaLaunchKernelEx(&cfg, k_mom, u, v, p, sig, u2, v2, b, r1a, r2a, r3a);

    const float* pc = p;
    float* pn = pa;
    for (int it = 0; it < 5; it++) {
        bool even = (it & 1) == 0;
        float* r1i = even ? r1a : r1b; float* r1o = even ? r1b : r1a;
        float* r2i = even ? r2a : r2b; float* r2o = even ? r2b : r2a;
        float* r3i = even ? r3a : r3b; float* r3o = even ? r3b : r3a;

        cfg.gridDim = dim3(1, 1, 1);
        cfg.blockDim = dim3(1024, 1, 1);
        cudaLaunchKernelEx(&cfg, k_coarse, (const float*)r3i, A4);

        cfg.gridDim = dim3(16, 64);
        cfg.blockDim = dim3(256, 1, 1);
        if (it < 4) {
            cudaLaunchKernelEx(&cfg, k_up<false>,
                pc, (const float*)b, (const float*)r1i, (const float*)r2i,
                (const float*)r3i, (const float*)A4, pn, r1o, r2o, r3o,
                (const float*)nullptr, (const float*)nullptr,
                (const float*)nullptr, (float*)nullptr);
            pc = pn;
            pn = (pn == pa) ? pb : pa;
        } else {
            cudaLaunchKernelEx(&cfg, k_up<true>,
                pc, (const float*)b, (const float*)r1i, (const float*)r2i,
                (const float*)r3i, (const float*)A4, (float*)nullptr,
                (float*)nullptr, (float*)nullptr, (float*)nullptr,
                (const float*)u2, (const float*)v2, (const float*)sig, out);
        }
    }
}

// round 17
// speedup vs baseline: 1.1374x; 1.0029x over previous
#include <cuda_runtime.h>

constexpr int NYg = 1024;
constexpr int NXg = 2048;
constexpr int N0  = NYg * NXg;
constexpr float DT = 0.1f;
constexpr float NU = 0.01f;
constexpr float UB = 1.0f;
constexpr float C12 = 1.0f / 12.0f;
constexpr float C3  = 1.0f / 3.0f;

__device__ float g_u2[N0];
__device__ float g_v2[N0];
__device__ float g_b [N0];
__device__ float g_pa[N0];
__device__ float g_pb[N0];
__device__ float g_r1a[512 * 1024];
__device__ float g_r1b[512 * 1024];
__device__ float g_r2a[256 * 512];
__device__ float g_r2b[256 * 512];
__device__ float g_r3a[128 * 256];
__device__ float g_r3b[128 * 256];
__device__ float g_A4[64 * 128];

// ---------- boundary-condition loaders ----------
__device__ __forceinline__ float ldU(const float* __restrict__ u, int y, int x) {
    if (y < 0 || y >= NYg) return UB;
    if (x < 0) return UB;
    if (x >= NXg) return u[y * NXg + NXg - 1];
    return u[y * NXg + x];
}
__device__ __forceinline__ float ldV(const float* __restrict__ v, int y, int x) {
    if (x >= NXg) { if (y < 0 || y >= NYg) return 0.0f; return v[y * NXg + NXg - 1]; }
    if (y < 0 || y >= NYg || x < 0) return 0.0f;
    return v[y * NXg + x];
}
__device__ __forceinline__ float ldP(const float* __restrict__ p, int y, int x) {
    if (x >= NXg) return 0.0f;
    int yy = min(max(y, 0), NYg - 1);
    int xx = max(x, 0);
    return p[yy * NXg + xx];
}

// generic prolong S8: sum of 3x3 neighborhood (excl. center) of NN-upsampled A
__device__ __forceinline__ float prolong_S8(const float* __restrict__ A, int stride,
                                            int yb, int xb, int y, int x)
{
    int r0 = ((y - 1) >> 1) - yb;
    int c0 = ((x - 1) >> 1) - xb;
    int py = y & 1, px = x & 1;
    float wr0 = (float)(1 + py), wr1 = (float)(2 - py);
    float wc0 = (float)(1 + px), wc1 = (float)(2 - px);
    const float* row0 = A + r0 * stride + c0;
    const float* row1 = row0 + stride;
    float V00 = row0[0], V01 = row0[1], V10 = row1[0], V11 = row1[1];
    float S9 = wr0 * (wc0 * V00 + wc1 * V01) + wr1 * (wc0 * V10 + wc1 * V11);
    float ctr = py ? (px ? V00 : V01) : (px ? V10 : V11);
    return S9 - ctr;
}

// ============ fused momentum + divergence + initial residual pyramid ============
// su2/sv2 alias su/sv (dead after predictor; corrector centers re-read from global)
__global__ __launch_bounds__(256) void k_mom(
    const float* __restrict__ u, const float* __restrict__ v,
    const float* __restrict__ p, const float* __restrict__ sig,
    float* __restrict__ u2g, float* __restrict__ v2g, float* __restrict__ bg,
    float* __restrict__ r1o, float* __restrict__ r2o, float* __restrict__ r3o)
{
    __shared__ float su[14][136], sv[14][136], sp[14][136];
    __shared__ float sbu[12][136], sbv[12][136];
    float (*su2)[136] = (float(*)[136])&su[0][0];   // alias: su dead after predictor
    float (*sv2)[136] = (float(*)[136])&sv[0][0];
    float* sb = &sbu[0][0];
    float* s1 = sb + 8 * 130;
    float* s2 = s1 + 256;

    cudaGridDependencySynchronize();

    int x0 = blockIdx.x * 128, y0 = blockIdx.y * 8;
    int t = threadIdx.y * 32 + threadIdx.x;

    for (int idx = t; idx < 14 * 34; idx += 256) {
        int ry = idx / 34, rc = idx - ry * 34;
        int gy = y0 - 3 + ry, gx = x0 - 4 + rc * 4;
        float4 a, bb, c;
        if (gy >= 0 && gy < NYg && gx >= 0 && gx + 3 < NXg) {
            a  = *(const float4*)(u + gy * NXg + gx);
            bb = *(const float4*)(v + gy * NXg + gx);
            c  = *(const float4*)(p + gy * NXg + gx);
        } else {
            a  = make_float4(ldU(u,gy,gx), ldU(u,gy,gx+1), ldU(u,gy,gx+2), ldU(u,gy,gx+3));
            bb = make_float4(ldV(v,gy,gx), ldV(v,gy,gx+1), ldV(v,gy,gx+2), ldV(v,gy,gx+3));
            c  = make_float4(ldP(p,gy,gx), ldP(p,gy,gx+1), ldP(p,gy,gx+2), ldP(p,gy,gx+3));
        }
        *(float4*)&su[ry][rc*4] = a;
        *(float4*)&sv[ry][rc*4] = bb;
        *(float4*)&sp[ry][rc*4] = c;
    }
    __syncthreads();

    // ---------- predictor: 12 rows x 32 quads, edges scalar ----------
    for (int idx = t; idx < 12 * 32; idx += 256) {
        int ry = idx >> 5, q = idx & 31;
        int c = 4 + 4 * q;
        int gy = y0 - 2 + ry;
        if (gy < 0 || gy >= NYg) {
            *(float4*)&sbu[ry][c] = make_float4(UB, UB, UB, UB);
            *(float4*)&sbv[ry][c] = make_float4(0.f, 0.f, 0.f, 0.f);
            continue;
        }
        int r = ry + 1;
        float4 vc4 = *(const float4*)&sv[r][c];
        float v00[4] = {vc4.x, vc4.y, vc4.z, vc4.w};
        float u00[4], obu[4], obv[4];
        {
            float R[3][6];
#pragma unroll
            for (int j = 0; j < 3; j++) {
                const float* rp_ = &su[r - 1 + j][0];
                float4 m = *(const float4*)(rp_ + c);
                R[j][0]=rp_[c-1]; R[j][1]=m.x; R[j][2]=m.y; R[j][3]=m.z; R[j][4]=m.w; R[j][5]=rp_[c+4];
            }
#pragma unroll
            for (int k = 0; k < 4; k++) {
                float ADx = (R[0][k+2]-R[0][k] + 4.f*(R[1][k+2]-R[1][k]) + R[2][k+2]-R[2][k]) * C12;
                float ADy = (R[2][k]+4.f*R[2][k+1]+R[2][k+2] - R[0][k]-4.f*R[0][k+1]-R[0][k+2]) * C12;
                float c0 = R[1][k+1];
                float AD2 = (R[0][k]+R[0][k+1]+R[0][k+2]+R[1][k]+R[1][k+2]
                           + R[2][k]+R[2][k+1]+R[2][k+2] - 8.f*c0) * C3;
                u00[k] = c0;
                obu[k] = c0 + 0.5f*(NU*AD2*DT - c0*ADx*DT - v00[k]*ADy*DT);
            }
        }
        {
            float R[3][6];
#pragma unroll
            for (int j = 0; j < 3; j++) {
                const float* rp_ = &sv[r - 1 + j][0];
                float4 m = *(const float4*)(rp_ + c);
                R[j][0]=rp_[c-1]; R[j][1]=m.x; R[j][2]=m.y; R[j][3]=m.z; R[j][4]=m.w; R[j][5]=rp_[c+4];
            }
#pragma unroll
            for (int k = 0; k < 4; k++) {
                float ADx = (R[0][k+2]-R[0][k] + 4.f*(R[1][k+2]-R[1][k]) + R[2][k+2]-R[2][k]) * C12;
                float ADy = (R[2][k]+4.f*R[2][k+1]+R[2][k+2] - R[0][k]-4.f*R[0][k+1]-R[0][k+2]) * C12;
                float c0 = R[1][k+1];
                float AD2 = (R[0][k]+R[0][k+1]+R[0][k+2]+R[1][k]+R[1][k+2]
                           + R[2][k]+R[2][k+1]+R[2][k+2] - 8.f*c0) * C3;
                obv[k] = c0 + 0.5f*(NU*AD2*DT - u00[k]*ADx*DT - c0*ADy*DT);
            }
        }
        {
            float R[3][6];
#pragma unroll
            for (int j = 0; j < 3; j++) {
                const float* rp_ = &sp[r - 1 + j][0];
                float4 m = *(const float4*)(rp_ + c);
                R[j][0]=rp_[c-1]; R[j][1]=m.x; R[j][2]=m.y; R[j][3]=m.z; R[j][4]=m.w; R[j][5]=rp_[c+4];
            }
#pragma unroll
            for (int k = 0; k < 4; k++) {
                float Gx = (R[0][k+2]-R[0][k] + 4.f*(R[1][k+2]-R[1][k]) + R[2][k+2]-R[2][k]) * (C12 * DT);
                float Gy = (R[2][k]+4.f*R[2][k+1]+R[2][k+2] - R[0][k]-4.f*R[0][k+1]-R[0][k+2]) * (C12 * DT);
                obu[k] -= Gx; obv[k] -= Gy;
            }
        }
        float4 sg4 = *(const float4*)(sig + gy * NXg + (x0 - 4 + c));
        float sgv[4] = {sg4.x, sg4.y, sg4.z, sg4.w};
#pragma unroll
        for (int k = 0; k < 4; k++) {
            float damp = 1.0f / (1.0f + DT * sgv[k]);
            obu[k] *= damp; obv[k] *= damp;
        }
        *(float4*)&sbu[ry][c] = make_float4(obu[0], obu[1], obu[2], obu[3]);
        *(float4*)&sbv[ry][c] = make_float4(obv[0], obv[1], obv[2], obv[3]);
    }
    if (t < 48) {
        int ry = t >> 2, ec = t & 3;
        int c = (ec < 2) ? (2 + ec) : (130 + ec);
        int gy = y0 - 2 + ry, gx = x0 - 4 + c;
        if (gy < 0 || gy >= NYg || gx < 0) { sbu[ry][c] = UB; sbv[ry][c] = 0.0f; }
        else if (gx < NXg) {
            int r = ry + 1;
            float umm=su[r-1][c-1], um0=su[r-1][c], ump=su[r-1][c+1];
            float u0m=su[r  ][c-1], u00=su[r  ][c], u0p=su[r  ][c+1];
            float upm=su[r+1][c-1], up0=su[r+1][c], upp=su[r+1][c+1];
            float vmm=sv[r-1][c-1], vm0=sv[r-1][c], vmp=sv[r-1][c+1];
            float v0m=sv[r  ][c-1], v00=sv[r  ][c], v0p=sv[r  ][c+1];
            float vpm=sv[r+1][c-1], vp0=sv[r+1][c], vpp=sv[r+1][c+1];
            float pmm=sp[r-1][c-1], pm0=sp[r-1][c], pmp=sp[r-1][c+1];
            float p0m=sp[r  ][c-1],                  p0p=sp[r  ][c+1];
            float ppm=sp[r+1][c-1], pp0=sp[r+1][c], ppp=sp[r+1][c+1];
            float ADx_u = (-umm + ump - 4.0f*u0m + 4.0f*u0p - upm + upp) * C12;
            float ADy_u = (-umm - 4.0f*um0 - ump + upm + 4.0f*up0 + upp) * C12;
            float AD2_u = (umm + um0 + ump + u0m + u0p + upm + up0 + upp - 8.0f*u00) * C3;
            float ADx_v = (-vmm + vmp - 4.0f*v0m + 4.0f*v0p - vpm + vpp) * C12;
            float ADy_v = (-vmm - 4.0f*vm0 - vmp + vpm + 4.0f*vp0 + vpp) * C12;
            float AD2_v = (vmm + vm0 + vmp + v0m + v0p + vpm + vp0 + vpp - 8.0f*v00) * C3;
            float Gx = (-pmm + pmp - 4.0f*p0m + 4.0f*p0p - ppm + ppp) * (C12 * DT);
            float Gy = (-pmm - 4.0f*pm0 - pmp + ppm + 4.0f*pp0 + ppp) * (C12 * DT);
            float damp = 1.0f / (1.0f + DT * sig[gy * NXg + gx]);
            sbu[ry][c] = (u00 + 0.5f*(NU*AD2_u*DT - u00*ADx_u*DT - v00*ADy_u*DT) - Gx) * damp;
            sbv[ry][c] = (v00 + 0.5f*(NU*AD2_v*DT - u00*ADx_v*DT - v00*ADy_v*DT) - Gy) * damp;
        }
    }
    __syncthreads();
    if (x0 + 128 == NXg && t < 12) { sbu[t][132] = sbu[t][131]; sbv[t][132] = sbv[t][131]; }
    __syncthreads();
    // su/sv now DEAD — su2/sv2 alias their storage from here on.

    // ---------- corrector: centers re-read from global u/v ----------
    for (int idx = t; idx < 10 * 32; idx += 256) {
        int ry = idx >> 5, q = idx & 31;
        int c = 4 + 4 * q;
        int gy = y0 - 1 + ry;
        if (gy < 0 || gy >= NYg) {
            *(float4*)&su2[ry][c] = make_float4(UB, UB, UB, UB);
            *(float4*)&sv2[ry][c] = make_float4(0.f, 0.f, 0.f, 0.f);
            continue;
        }
        int rb = ry + 1, rp = ry + 2;
        int gi = gy * NXg + (x0 - 4 + c);
        float4 uo4 = *(const float4*)(u + gi);
        float4 vo4 = *(const float4*)(v + gi);
        float4 bu4 = *(const float4*)&sbu[rb][c];
        float4 bv4 = *(const float4*)&sbv[rb][c];
        float uo[4] = {uo4.x, uo4.y, uo4.z, uo4.w};
        float vo[4] = {vo4.x, vo4.y, vo4.z, vo4.w};
        float bu0[4] = {bu4.x, bu4.y, bu4.z, bu4.w};
        float bv0[4] = {bv4.x, bv4.y, bv4.z, bv4.w};
        float ou[4], ov[4];
        {
            float R[3][6];
#pragma unroll
            for (int j = 0; j < 3; j++) {
                const float* rp_ = &sbu[rb - 1 + j][0];
                float4 m = *(const float4*)(rp_ + c);
                R[j][0]=rp_[c-1]; R[j][1]=m.x; R[j][2]=m.y; R[j][3]=m.z; R[j][4]=m.w; R[j][5]=rp_[c+4];
            }
#pragma unroll
            for (int k = 0; k < 4; k++) {
                float ADx = (R[0][k+2]-R[0][k] + 4.f*(R[1][k+2]-R[1][k]) + R[2][k+2]-R[2][k]) * C12;
                float ADy = (R[2][k]+4.f*R[2][k+1]+R[2][k+2] - R[0][k]-4.f*R[0][k+1]-R[0][k+2]) * C12;
                float c0 = R[1][k+1];
                float AD2 = (R[0][k]+R[0][k+1]+R[0][k+2]+R[1][k]+R[1][k+2]
                           + R[2][k]+R[2][k+1]+R[2][k+2] - 8.f*c0) * C3;
                ou[k] = uo[k] + NU*AD2*DT - bu0[k]*ADx*DT - bv0[k]*ADy*DT;
            }
        }
        {
            float R[3][6];
#pragma unroll
            for (int j = 0; j < 3; j++) {
                const float* rp_ = &sbv[rb - 1 + j][0];
                float4 m = *(const float4*)(rp_ + c);
                R[j][0]=rp_[c-1]; R[j][1]=m.x; R[j][2]=m.y; R[j][3]=m.z; R[j][4]=m.w; R[j][5]=rp_[c+4];
            }
#pragma unroll
            for (int k = 0; k < 4; k++) {
                float ADx = (R[0][k+2]-R[0][k] + 4.f*(R[1][k+2]-R[1][k]) + R[2][k+2]-R[2][k]) * C12;
                float ADy = (R[2][k]+4.f*R[2][k+1]+R[2][k+2] - R[0][k]-4.f*R[0][k+1]-R[0][k+2]) * C12;
                float c0 = R[1][k+1];
                float AD2 = (R[0][k]+R[0][k+1]+R[0][k+2]+R[1][k]+R[1][k+2]
                           + R[2][k]+R[2][k+1]+R[2][k+2] - 8.f*c0) * C3;
                ov[k] = vo[k] + NU*AD2*DT - bu0[k]*ADx*DT - bv0[k]*ADy*DT;
            }
        }
        {
            float R[3][6];
#pragma unroll
            for (int j = 0; j < 3; j++) {
                const float* rp_ = &sp[rp - 1 + j][0];
                float4 m = *(const float4*)(rp_ + c);
                R[j][0]=rp_[c-1]; R[j][1]=m.x; R[j][2]=m.y; R[j][3]=m.z; R[j][4]=m.w; R[j][5]=rp_[c+4];
            }
#pragma unroll
            for (int k = 0; k < 4; k++) {
                float Gx = (R[0][k+2]-R[0][k] + 4.f*(R[1][k+2]-R[1][k]) + R[2][k+2]-R[2][k]) * (C12 * DT);
                float Gy = (R[2][k]+4.f*R[2][k+1]+R[2][k+2] - R[0][k]-4.f*R[0][k+1]-R[0][k+2]) * (C12 * DT);
                ou[k] -= Gx; ov[k] -= Gy;
            }
        }
        float4 sg4 = *(const float4*)(sig + gi);
        float sgv[4] = {sg4.x, sg4.y, sg4.z, sg4.w};
#pragma unroll
        for (int k = 0; k < 4; k++) {
            float damp = 1.0f / (1.0f + DT * sgv[k]);
            ou[k] *= damp; ov[k] *= damp;
        }
        *(float4*)&su2[ry][c] = make_float4(ou[0], ou[1], ou[2], ou[3]);
        *(float4*)&sv2[ry][c] = make_float4(ov[0], ov[1], ov[2], ov[3]);
    }
    if (t < 20) {
        int ry = t >> 1;
        int c = (t & 1) ? 132 : 3;
        int gy = y0 - 1 + ry, gx = x0 - 4 + c;
        if (gy < 0 || gy >= NYg || gx < 0) { su2[ry][c] = UB; sv2[ry][c] = 0.0f; }
        else if (gx < NXg) {
            int rb = ry + 1, rp = ry + 2;
            float umm=sbu[rb-1][c-1], um0=sbu[rb-1][c], ump=sbu[rb-1][c+1];
            float u0m=sbu[rb  ][c-1], bu0=sbu[rb  ][c], u0p=sbu[rb  ][c+1];
            float upm=sbu[rb+1][c-1], up0=sbu[rb+1][c], upp=sbu[rb+1][c+1];
            float vmm=sbv[rb-1][c-1], vm0=sbv[rb-1][c], vmp=sbv[rb-1][c+1];
            float v0m=sbv[rb  ][c-1], bv0=sbv[rb  ][c], v0p=sbv[rb  ][c+1];
            float vpm=sbv[rb+1][c-1], vp0=sbv[rb+1][c], vpp=sbv[rb+1][c+1];
            float pmm=sp[rp-1][c-1], pm0=sp[rp-1][c], pmp=sp[rp-1][c+1];
            float p0m=sp[rp  ][c-1],                  p0p=sp[rp  ][c+1];
            float ppm=sp[rp+1][c-1], pp0=sp[rp+1][c], ppp=sp[rp+1][c+1];
            float ADx_u = (-umm + ump - 4.0f*u0m + 4.0f*u0p - upm + upp) * C12;
            float ADy_u = (-umm - 4.0f*um0 - ump + upm + 4.0f*up0 + upp) * C12;
            float AD2_u = (umm + um0 + ump + u0m + u0p + upm + up0 + upp - 8.0f*bu0) * C3;
            float ADx_v = (-vmm + vmp - 4.0f*v0m + 4.0f*v0p - vpm + vpp) * C12;
            float ADy_v = (-vmm - 4.0f*vm0 - vmp + vpm + 4.0f*vp0 + vpp) * C12;
            float AD2_v = (vmm + vm0 + vmp + v0m + v0p + vpm + vp0 + vpp - 8.0f*bv0) * C3;
            float Gx = (-pmm + pmp - 4.0f*p0m + 4.0f*p0p - ppm + ppp) * (C12 * DT);
            float Gy = (-pmm - 4.0f*pm0 - pmp + ppm + 4.0f*pp0 + ppp) * (C12 * DT);
            float damp = 1.0f / (1.0f + DT * sig[gy * NXg + gx]);
            su2[ry][c] = (u[gy * NXg + gx] + NU*AD2_u*DT - bu0*ADx_u*DT - bv0*ADy_u*DT - Gx) * damp;
            sv2[ry][c] = (v[gy * NXg + gx] + NU*AD2_v*DT - bu0*ADx_v*DT - bv0*ADy_v*DT - Gy) * damp;
        }
    }
    __syncthreads();
    if (x0 + 128 == NXg && t < 10) { su2[t][132] = su2[t][131]; sv2[t][132] = sv2[t][131]; }
    __syncthreads();

    int ty = t >> 5, tx = t & 31;
    int gy = y0 + ty, gxb = x0 + tx * 4;
    int i = gy * NXg + gxb;
    float ob[4], ou[4], ov[4];
#pragma unroll
    for (int k = 0; k < 4; k++) {
        int c = tx * 4 + k + 4;
        float dudx = (-su2[ty][c-1] + su2[ty][c+1] - 4.0f*su2[ty+1][c-1] + 4.0f*su2[ty+1][c+1]
                      - su2[ty+2][c-1] + su2[ty+2][c+1]) * C12;
        float dvdy = (-sv2[ty][c-1] - 4.0f*sv2[ty][c] - sv2[ty][c+1]
                      + sv2[ty+2][c-1] + 4.0f*sv2[ty+2][c] + sv2[ty+2][c+1]) * C12;
        ob[k] = -(dudx + dvdy) * (1.0f / DT);
        ou[k] = su2[ty+1][c];
        ov[k] = sv2[ty+1][c];
    }
    *(float4*)(bg  + i) = make_float4(ob[0], ob[1], ob[2], ob[3]);
    *(float4*)(u2g + i) = make_float4(ou[0], ou[1], ou[2], ou[3]);
    *(float4*)(v2g + i) = make_float4(ov[0], ov[1], ov[2], ov[3]);
    __syncthreads();
#pragma unroll
    for (int k = 0; k < 4; k++) sb[ty * 130 + tx * 4 + k] = ob[k];
    __syncthreads();

    {
        int ry = t >> 6, rx = t & 63;
        int fy = 2 * ry, fx = 2 * rx;
        float s[4][4];
#pragma unroll
        for (int r = 0; r < 4; r++)
#pragma unroll
            for (int c = 0; c < 4; c++)
                s[r][c] = sp[fy + r + 2][fx + 3 + c];
        float h[4][2];
#pragma unroll
        for (int r = 0; r < 4; r++) {
            h[r][0] = s[r][0] + s[r][1] + s[r][2];
            h[r][1] = s[r][1] + s[r][2] + s[r][3];
        }
        float b00 = sb[fy * 130 + fx],       b01 = sb[fy * 130 + fx + 1];
        float b10 = sb[(fy + 1) * 130 + fx], b11 = sb[(fy + 1) * 130 + fx + 1];
        float acc = 0.0f;
        acc += (h[0][0] + h[1][0] + h[2][0] - 9.0f * s[1][1]) * C3 - b00;
        acc += (h[0][1] + h[1][1] + h[2][1] - 9.0f * s[1][2]) * C3 - b01;
        acc += (h[1][0] + h[2][0] + h[3][0] - 9.0f * s[2][1]) * C3 - b10;
        acc += (h[1][1] + h[2][1] + h[3][1] - 9.0f * s[2][2]) * C3 - b11;
        float r1v = 0.25f * acc;
        int bx = blockIdx.x, by = blockIdx.y;
        r1o[(4 * by + ry) * 1024 + 64 * bx + rx] = r1v;
        s1[ry * 64 + rx] = r1v;
        __syncthreads();
        if (t < 64) {
            int ty2 = t >> 5, tx2 = t & 31;
            float v2l = 0.25f * (s1[2*ty2*64 + 2*tx2] + s1[2*ty2*64 + 2*tx2 + 1]
                               + s1[(2*ty2+1)*64 + 2*tx2] + s1[(2*ty2+1)*64 + 2*tx2 + 1]);
            r2o[(2 * by + ty2) * 512 + 32 * bx + tx2] = v2l;
            s2[ty2 * 32 + tx2] = v2l;
        }
        __syncthreads();
        if (t < 16) {
            float v3l = 0.25f * (s2[2*t] + s2[2*t + 1] + s2[32 + 2*t] + s2[32 + 2*t + 1]);
            r3o[by * 256 + 16 * bx + t] = v3l;
        }
    }
}

// ---------- coarse pyramid: r3 -> ... -> A4 (r4 cached, prolong up-sweep) ----------
__global__ __launch_bounds__(1024) void k_coarse(
    const float* __restrict__ r3, float* __restrict__ A4g)
{
    __shared__ float sr4[64 * 128];
    __shared__ float sr5[32 * 64];
    __shared__ float sr6[16 * 32], sr7[8 * 16], sr8[4 * 8], sr9[8];
    __shared__ float sA10[2], sA9[8], sA8[32];
    __shared__ float sA7h[10][18];
    __shared__ float sA6h[18][34];
    __shared__ float sA5h[34][66];
    int t = threadIdx.x;

    for (int i = t; i < 10 * 18; i += 1024) (&sA7h[0][0])[i] = 0.0f;
    for (int i = t; i < 18 * 34; i += 1024) (&sA6h[0][0])[i] = 0.0f;
    for (int i = t; i < 34 * 66; i += 1024) (&sA5h[0][0])[i] = 0.0f;

    cudaTriggerProgrammaticLaunchCompletion();
    cudaGridDependencySynchronize();

    for (int i = t; i < 2048; i += 1024) {
        int y = i >> 6, x = i & 63;
        float4 q0 = *(const float4*)(r3 + (4 * y    ) * 256 + 4 * x);
        float4 q1 = *(const float4*)(r3 + (4 * y + 1) * 256 + 4 * x);
        float4 q2 = *(const float4*)(r3 + (4 * y + 2) * 256 + 4 * x);
        float4 q3 = *(const float4*)(r3 + (4 * y + 3) * 256 + 4 * x);
        float a00 = q0.x + q0.y + q1.x + q1.y;
        float a01 = q0.z + q0.w + q1.z + q1.w;
        float a10 = q2.x + q2.y + q3.x + q3.y;
        float a11 = q2.z + q2.w + q3.z + q3.w;
        sr4[(2*y) * 128 + 2*x]     = 0.25f * a00;
        sr4[(2*y) * 128 + 2*x + 1] = 0.25f * a01;
        sr4[(2*y+1) * 128 + 2*x]     = 0.25f * a10;
        sr4[(2*y+1) * 128 + 2*x + 1] = 0.25f * a11;
        sr5[i] = 0.0625f * (a00 + a01 + a10 + a11);
    }
    __syncthreads();

    if (t < 512) {
        int y = t >> 5, x = t & 31;
        sr6[t] = 0.25f * (sr5[(2*y)*64 + 2*x] + sr5[(2*y)*64 + 2*x + 1]
                        + sr5[(2*y+1)*64 + 2*x] + sr5[(2*y+1)*64 + 2*x + 1]);
    } else if (t < 640) {
        int i = t - 512; int y = i >> 4, x = i & 15;
        float s = 0.0f;
#pragma unroll
        for (int dy = 0; dy < 4; dy++)
#pragma unroll
            for (int dx = 0; dx < 4; dx++)
                s += sr5[(4*y + dy)*64 + 4*x + dx];
        sr7[i] = 0.0625f * s;
    } else if (t < 672) {
        int i = t - 640; int y = i >> 3, x = i & 7;
        float s = 0.0f;
        for (int dy = 0; dy < 8; dy++)
#pragma unroll
            for (int dx = 0; dx < 8; dx++)
                s += sr5[(8*y + dy)*64 + 8*x + dx];
        sr8[i] = 0.015625f * s;
    }
    __syncthreads();

    if (t < 32) {
        if (t < 8) {
            int y = t >> 2, x = t & 3;
            sr9[t] = 0.25f * (sr8[(2*y)*8 + 2*x] + sr8[(2*y)*8 + 2*x + 1]
                            + sr8[(2*y+1)*8 + 2*x] + sr8[(2*y+1)*8 + 2*x + 1]);
        }
        __syncwarp();
        if (t < 2) {
            float r10 = 0.25f * (sr9[2*t] + sr9[2*t + 1] + sr9[4 + 2*t] + sr9[4 + 2*t + 1]);
            sA10[t] = -0.375f * r10;
        }
        __syncwarp();
        if (t < 8) {
            int y = t >> 2, x = t & 3;
            float S = 0.0f;
#pragma unroll
            for (int dy = -1; dy <= 1; dy++)
#pragma unroll
                for (int dx = -1; dx <= 1; dx++) {
                    if (dy == 0 && dx == 0) continue;
                    int yy = y + dy, xx = x + dx;
                    if (yy >= 0 && yy < 2 && xx >= 0 && xx < 4) S += sA10[xx >> 1];
                }
            sA9[t] = 0.125f * S - 0.375f * sr9[t];
        }
        __syncwarp();
        {
            int y = t >> 3, x = t & 7;
            float S = 0.0f;
#pragma unroll
            for (int dy = -1; dy <= 1; dy++)
#pragma unroll
                for (int dx = -1; dx <= 1; dx++) {
                    if (dy == 0 && dx == 0) continue;
                    int yy = y + dy, xx = x + dx;
                    if (yy >= 0 && yy < 4 && xx >= 0 && xx < 8) S += sA9[(yy >> 1) * 4 + (xx >> 1)];
                }
            sA8[t] = 0.125f * S - 0.375f * sr8[t];
        }
    }
    __syncthreads();

    if (t < 128) {
        int y = t >> 4, x = t & 15;
        float S = 0.0f;
#pragma unroll
        for (int dy = -1; dy <= 1; dy++)
#pragma unroll
            for (int dx = -1; dx <= 1; dx++) {
                if (dy == 0 && dx == 0) continue;
                int yy = y + dy, xx = x + dx;
                if (yy >= 0 && yy < 8 && xx >= 0 && xx < 16) S += sA8[(yy >> 1) * 8 + (xx >> 1)];
            }
        sA7h[1 + y][1 + x] = 0.125f * S - 0.375f * sr7[t];
    }
    __syncthreads();
    if (t < 512) {
        int y = t >> 5, x = t & 31;
        sA6h[1 + y][1 + x] = 0.125f * prolong_S8(&sA7h[1][1], 18, 0, 0, y, x)
                           - 0.375f * sr6[t];
    }
    __syncthreads();
    for (int i = t; i < 2048; i += 1024) {
        int y = i >> 6, x = i & 63;
        sA5h[1 + y][1 + x] = 0.125f * prolong_S8(&sA6h[1][1], 34, 0, 0, y, x)
                           - 0.375f * sr5[i];
    }
    __syncthreads();
    for (int i = t; i < 64 * 128; i += 1024) {
        int y = i >> 7, x = i & 127;
        A4g[i] = 0.125f * prolong_S8(&sA5h[1][1], 66, 0, 0, y, x)
               - 0.375f * sr4[i];
    }
}

// ============ fused up-sweep + fine smooth + (residual pyramid | projection) ============
template<bool FINAL>
__global__ __launch_bounds__(256) void k_up(
    const float* __restrict__ p, const float* __restrict__ b,
    const float* __restrict__ r1, const float* __restrict__ r2,
    const float* __restrict__ r3, const float* __restrict__ A4,
    float* __restrict__ pn,
    float* __restrict__ r1o, float* __restrict__ r2o, float* __restrict__ r3o,
    const float* __restrict__ u2, const float* __restrict__ v2,
    const float* __restrict__ sig, float* __restrict__ out)
{
    __shared__ float sp[20][136];
    __shared__ float spn[18][136];
    __shared__ float sA1[12][68];
    __shared__ float sA2[8][36];
    __shared__ float sA3[6][20];
    __shared__ float s1[8 * 64];
    __shared__ float s2[4 * 32];

    int bx = blockIdx.x, by = blockIdx.y;
    int x0 = bx * 128, y0 = by * 16;
    int t = threadIdx.x;
    int y3b = 2 * by - 2, x3b = 16 * bx - 2;
    int y2b = 4 * by - 2, x2b = 32 * bx - 2;
    int y1b = 8 * by - 2, x1b = 64 * bx - 2;

    // ================= PREAMBLE =================
    for (int idx = t; idx < 20 * 34; idx += 256) {
        int ry = idx / 34, rc = idx - ry * 34;
        int gy = y0 - 2 + ry, gx = x0 - 4 + rc * 4;
        float4 c;
        if (gy >= 0 && gy < NYg && gx >= 0 && gx + 3 < NXg)
            c = *(const float4*)(p + gy * NXg + gx);
        else
            c = make_float4(ldP(p,gy,gx), ldP(p,gy,gx+1), ldP(p,gy,gx+2), ldP(p,gy,gx+3));
        *(float4*)&sp[ry][rc * 4] = c;
    }
    float rv3 = 0.0f, rv2[2] = {0.0f, 0.0f}, rv1[4] = {0.0f, 0.0f, 0.0f, 0.0f};
    if (t < 120) {
        int ly = t / 20, lx = t - ly * 20;
        int y3 = y3b + ly, x3 = x3b + lx;
        if (y3 >= 0 && y3 < 128 && x3 >= 0 && x3 < 256) rv3 = r3[y3 * 256 + x3];
    }
#pragma unroll
    for (int j = 0; j < 2; j++) {
        int i = t + j * 256;
        if (i < 8 * 36) {
            int ly = i / 36, lx = i - ly * 36;
            int y2 = y2b + ly, x2 = x2b + lx;
            if (y2 >= 0 && y2 < 256 && x2 >= 0 && x2 < 512) rv2[j] = r2[y2 * 512 + x2];
        }
    }
#pragma unroll
    for (int j = 0; j < 4; j++) {
        int i = t + j * 256;
        if (i < 12 * 68) {
            int ly = i / 68, lx = i - ly * 68;
            int y1 = y1b + ly, x1 = x1b + lx;
            if (x1 < 1024) {
                int y1c = min(max(y1, 0), 511), x1c = max(x1, 0);
                rv1[j] = r1[y1c * 1024 + x1c];
            }
        }
    }
    __syncthreads();

    // staging: T = 0.125*S8(bc_p(p)) - 0.375*b for all 18 rows
    for (int idx = t; idx < 18 * 32; idx += 256) {
        int ry = idx >> 5, q = idx & 31;
        int gy = y0 - 1 + ry;
        if (gy < 0 || gy >= NYg) continue;
        int r = ry + 1;
        int c = 4 + 4 * q;
        float row[3][6];
#pragma unroll
        for (int j = 0; j < 3; j++) {
            const float* rp_ = &sp[r - 1 + j][0];
            float4 m = *(const float4*)(rp_ + c);
            row[j][0] = rp_[c - 1];
            row[j][1] = m.x; row[j][2] = m.y; row[j][3] = m.z; row[j][4] = m.w;
            row[j][5] = rp_[c + 4];
        }
        float h[6];
#pragma unroll
        for (int j = 0; j < 6; j++) h[j] = row[0][j] + row[1][j] + row[2][j];
        float4 b4 = *(const float4*)(b + gy * NXg + x0 + 4 * q);
        float bb[4] = {b4.x, b4.y, b4.z, b4.w};
        float T[4];
#pragma unroll
        for (int k = 0; k < 4; k++) {
            float S8 = h[k] + h[k + 1] + h[k + 2] - row[1][k + 1];
            T[k] = 0.125f * S8 - 0.375f * bb[k];
        }
        *(float4*)&spn[ry][c] = make_float4(T[0], T[1], T[2], T[3]);
    }
    if (t < 36) {
        int ry = t >> 1;
        int c = (t & 1) ? 132 : 3;
        int gy = y0 - 1 + ry, gx = x0 - 4 + c;
        if (gy >= 0 && gy < NYg && gx >= 0 && gx < NXg) {
            int r = ry + 1;
            float S = sp[r-1][c-1] + sp[r-1][c] + sp[r-1][c+1]
                    + sp[r  ][c-1] +              sp[r  ][c+1]
                    + sp[r+1][c-1] + sp[r+1][c] + sp[r+1][c+1];
            spn[ry][c] = 0.125f * S - 0.375f * b[gy * NXg + gx];
        }
    }

    // ================= wait for k_coarse (A4) =================
    cudaGridDependencySynchronize();

    // A3 directly from global A4 (zero-pad outside [0,64)x[0,128))
    if (t < 120) {
        int ly = t / 20, lx = t - ly * 20;
        int y3 = y3b + ly, x3 = x3b + lx;
        float val = 0.0f;
        if (y3 >= 0 && y3 < 128 && x3 >= 0 && x3 < 256) {
            int yc = (y3 - 1) >> 1, xc = (x3 - 1) >> 1;
            int py = y3 & 1, px = x3 & 1;
            float V00 = (yc >= 0 && xc >= 0)          ? A4[yc * 128 + xc]           : 0.0f;
            float V01 = (yc >= 0 && xc + 1 < 128)     ? A4[yc * 128 + xc + 1]       : 0.0f;
            float V10 = (yc + 1 < 64 && xc >= 0)      ? A4[(yc + 1) * 128 + xc]     : 0.0f;
            float V11 = (yc + 1 < 64 && xc + 1 < 128) ? A4[(yc + 1) * 128 + xc + 1] : 0.0f;
            float wr0 = (float)(1 + py), wr1 = (float)(2 - py);
            float wc0 = (float)(1 + px), wc1 = (float)(2 - px);
            float S9 = wr0 * (wc0 * V00 + wc1 * V01) + wr1 * (wc0 * V10 + wc1 * V11);
            float ctr = py ? (px ? V00 : V01) : (px ? V10 : V11);
            val = 0.125f * (S9 - ctr) - 0.375f * rv3;
        }
        sA3[ly][lx] = val;
    }
    __syncthreads();
#pragma unroll
    for (int j = 0; j < 2; j++) {
        int i = t + j * 256;
        if (i < 8 * 36) {
            int ly = i / 36, lx = i - ly * 36;
            int y2 = y2b + ly, x2 = x2b + lx;
            float val = 0.0f;
            if (y2 >= 0 && y2 < 256 && x2 >= 0 && x2 < 512)
                val = 0.125f * prolong_S8(&sA3[0][0], 20, y3b, x3b, y2, x2) - 0.375f * rv2[j];
            sA2[ly][lx] = val;
        }
    }
    __syncthreads();
#pragma unroll
    for (int j = 0; j < 4; j++) {
        int i = t + j * 256;
        if (i < 12 * 68) {
            int ly = i / 68, lx = i - ly * 68;
            int y1 = y1b + ly, x1 = x1b + lx;
            float val = 0.0f;
            if (x1 < 1024) {
                int y1c = min(max(y1, 0), 511), x1c = max(x1, 0);
                val = 0.125f * prolong_S8(&sA2[0][0], 36, y2b, x2b, y1c, x1c) - 0.375f * rv1[j];
            }
            sA1[ly][lx] = val;
        }
    }
    __syncthreads();

    // finalize: pn = T - 0.125*Sa  (interior rows stream straight to pn)
    for (int idx = t; idx < 18 * 32; idx += 256) {
        int ry = idx >> 5, q = idx & 31;
        int gy = y0 - 1 + ry;
        if (gy < 0 || gy >= NYg) continue;
        int c = 4 + 4 * q;
        int gxb = x0 + 4 * q;
        float4 tv = *(const float4*)&spn[ry][c];
        float T[4] = {tv.x, tv.y, tv.z, tv.w};
        int py = gy & 1;
        int r0 = ((gy - 1) >> 1) - y1b;
        int C  = (gxb >> 1) - x1b;
        const float* R0 = &sA1[r0][0];
        const float* R1 = &sA1[r0 + 1][0];
        const float* Rc = py ? R0 : R1;
        float w0 = py ? 2.0f : 1.0f, w1 = 3.0f - w0;
        float rs[4];
#pragma unroll
        for (int j = 0; j < 4; j++) rs[j] = w0 * R0[C - 1 + j] + w1 * R1[C - 1 + j];
        float Sa[4];
        Sa[0] = rs[0] + 2.0f * rs[1] - Rc[C];
        Sa[1] = 2.0f * rs[1] + rs[2] - Rc[C];
        Sa[2] = rs[1] + 2.0f * rs[2] - Rc[C + 1];
        Sa[3] = 2.0f * rs[2] + rs[3] - Rc[C + 1];
        float4 o = make_float4(T[0] - 0.125f * Sa[0], T[1] - 0.125f * Sa[1],
                               T[2] - 0.125f * Sa[2], T[3] - 0.125f * Sa[3]);
        *(float4*)&spn[ry][c] = o;
        if constexpr (!FINAL) {
            if (ry >= 1 && ry <= 16)
                *(float4*)(pn + gy * NXg + gxb) = o;
        }
    }
    if (t < 36) {
        int ry = t >> 1;
        int c = (t & 1) ? 132 : 3;
        int gy = y0 - 1 + ry, gx = x0 - 4 + c;
        if (gy >= 0 && gy < NYg && gx >= 0 && gx < NXg) {
            float Sa = prolong_S8(&sA1[0][0], 68, y1b, x1b, gy, gx);
            spn[ry][c] -= 0.125f * Sa;
        }
    }
    __syncthreads();
    if (t < 18) {
        if (bx == 0) {
            int src = (by == 0 && t == 0) ? 1 : ((by == 63 && t == 17) ? 16 : t);
            spn[t][3] = spn[src][4];
        }
        if (bx == 15) spn[t][132] = 0.0f;
    }
    if (by == 0) {
        for (int c = t; c < 130; c += 256) {
            float v;
            if (c == 0 && bx == 0)         v = spn[1][4];
            else if (c == 129 && bx == 15) v = 0.0f;
            else                           v = spn[1][c + 3];
            spn[0][c + 3] = v;
        }
    }
    if (by == 63) {
        for (int c = t; c < 130; c += 256) {
            float v;
            if (c == 0 && bx == 0)         v = spn[16][4];
            else if (c == 129 && bx == 15) v = 0.0f;
            else                           v = spn[16][c + 3];
            spn[17][c + 3] = v;
        }
    }
    __syncthreads();

    if constexpr (!FINAL) {
#pragma unroll
        for (int j = 0; j < 2; j++) {
            int idx = t + j * 256;
            int ry = idx >> 6, rx = idx & 63;
            int fy = 2 * ry, fx = 2 * rx;
            float s[4][4];
#pragma unroll
            for (int r = 0; r < 4; r++)
#pragma unroll
                for (int c = 0; c < 4; c++)
                    s[r][c] = spn[fy + r][fx + 3 + c];
            float h2[4][2];
#pragma unroll
            for (int r = 0; r < 4; r++) {
                h2[r][0] = s[r][0] + s[r][1] + s[r][2];
                h2[r][1] = s[r][1] + s[r][2] + s[r][3];
            }
            float2 b0 = *(const float2*)(b + (y0 + fy) * NXg + x0 + fx);
            float2 b1 = *(const float2*)(b + (y0 + fy + 1) * NXg + x0 + fx);
            float acc = 0.0f;
            acc += (h2[0][0] + h2[1][0] + h2[2][0] - 9.0f * s[1][1]) * C3 - b0.x;
            acc += (h2[0][1] + h2[1][1] + h2[2][1] - 9.0f * s[1][2]) * C3 - b0.y;
            acc += (h2[1][0] + h2[2][0] + h2[3][0] - 9.0f * s[2][1]) * C3 - b1.x;
            acc += (h2[1][1] + h2[2][1] + h2[3][1] - 9.0f * s[2][2]) * C3 - b1.y;
            float r1v = 0.25f * acc;
            r1o[(8 * by + ry) * 1024 + 64 * bx + rx] = r1v;
            s1[ry * 64 + rx] = r1v;
        }
        __syncthreads();
        if (t < 128) {
            int ty2 = t >> 5, tx2 = t & 31;
            float v = 0.25f * (s1[2*ty2*64 + 2*tx2] + s1[2*ty2*64 + 2*tx2 + 1]
                             + s1[(2*ty2+1)*64 + 2*tx2] + s1[(2*ty2+1)*64 + 2*tx2 + 1]);
            r2o[(4 * by + ty2) * 512 + 32 * bx + tx2] = v;
            s2[ty2 * 32 + tx2] = v;
        }
        __syncthreads();
        if (t < 32) {
            int yy = t >> 4, xx = t & 15;
            float v = 0.25f * (s2[2*yy*32 + 2*xx] + s2[2*yy*32 + 2*xx + 1]
                             + s2[(2*yy+1)*32 + 2*xx] + s2[(2*yy+1)*32 + 2*xx + 1]);
            r3o[(2 * by + yy) * 256 + 16 * bx + xx] = v;
        }
    } else {
        for (int idx = t; idx < 512; idx += 256) {
            int ry = idx >> 5, q = idx & 31;
            int gy = y0 + ry;
            int gxb = x0 + 4 * q;
            int i = gy * NXg + gxb;
            float4 s4 = *(const float4*)(sig + i);
            float4 u4 = *(const float4*)(u2 + i);
            float4 v4 = *(const float4*)(v2 + i);
            float sg[4] = {s4.x, s4.y, s4.z, s4.w};
            float uu[4] = {u4.x, u4.y, u4.z, u4.w};
            float vv[4] = {v4.x, v4.y, v4.z, v4.w};
            float ou[4], ov[4], op[4];
#pragma unroll
            for (int k = 0; k < 4; k++) {
                int c = 4 * q + k + 4, r = ry + 1;
                float pmm = spn[r-1][c-1], pm0 = spn[r-1][c], pmp = spn[r-1][c+1];
                float p0m = spn[r  ][c-1],                     p0p = spn[r  ][c+1];
                float ppm = spn[r+1][c-1], pp0 = spn[r+1][c], ppp = spn[r+1][c+1];
                float Gx = (-pmm + pmp - 4.0f*p0m + 4.0f*p0p - ppm + ppp) * (C12 * DT);
                float Gy = (-pmm - 4.0f*pm0 - pmp + ppm + 4.0f*pp0 + ppp) * (C12 * DT);
                float damp = 1.0f / (1.0f + DT * sg[k]);
                ou[k] = (uu[k] - Gx) * damp;
                ov[k] = (vv[k] - Gy) * damp;
                op[k] = spn[r][c];
            }
            *(float4*)(out + i)            = make_float4(ou[0], ou[1], ou[2], ou[3]);
            *(float4*)(out + N0 + i)       = make_float4(ov[0], ov[1], ov[2], ov[3]);
            *(float4*)(out + 2 * N0 + i)   = make_float4(op[0], op[1], op[2], op[3]);
        }
    }
}

static float* symaddr(const void* s) {
    void* ptr = nullptr;
    cudaGetSymbolAddress(&ptr, s);
    return (float*)ptr;
}

extern "C" void kernel_launch(void* const* d_in, const int* in_sizes, int n_in,
                              void* d_out, int out_size)
{
    const float* u   = (const float*)d_in[0];
    const float* v   = (const float*)d_in[1];
    const float* p   = (const float*)d_in[2];
    const float* sig = (const float*)d_in[3];
    float* out = (float*)d_out;

    float* u2  = symaddr(g_u2);  float* v2  = symaddr(g_v2);
    float* b   = symaddr(g_b);
    float* pa  = symaddr(g_pa);  float* pb  = symaddr(g_pb);
    float* r1a = symaddr(g_r1a); float* r1b = symaddr(g_r1b);
    float* r2a = symaddr(g_r2a); float* r2b = symaddr(g_r2b);
    float* r3a = symaddr(g_r3a); float* r3b = symaddr(g_r3b);
    float* A4  = symaddr(g_A4);

    cudaLaunchAttribute attrs[1];
    attrs[0].id = cudaLaunchAttributeProgrammaticStreamSerialization;
    attrs[0].val.programmaticStreamSerializationAllowed = 1;

    cudaLaunchConfig_t cfg = {};
    cfg.stream = (cudaStream_t)0;
    cfg.attrs = attrs;
    cfg.numAttrs = 1;

    cfg.gridDim = dim3(16, 128);
    cfg.blockDim = dim3(32, 8);
    cudaLaunchKernelEx(&cfg, k_mom, u, v, p, sig, u2, v2, b, r1a, r2a, r3a);

    const float* pc = p;
    float* pn = pa;
    for (int it = 0; it < 5; it++) {
        bool even = (it & 1) == 0;
        float* r1i = even ? r1a : r1b; float* r1o = even ? r1b : r1a;
        float* r2i = even ? r2a : r2b; float* r2o = even ? r2b : r2a;
        float* r3i = even ? r3a : r3b; float* r3o = even ? r3b : r3a;

        cfg.gridDim = dim3(1, 1, 1);
        cfg.blockDim = dim3(1024, 1, 1);
        cudaLaunchKernelEx(&cfg, k_coarse, (const float*)r3i, A4);

        cfg.gridDim = dim3(16, 64);
        cfg.blockDim = dim3(256, 1, 1);
        if (it < 4) {
            cudaLaunchKernelEx(&cfg, k_up<false>,
                pc, (const float*)b, (const float*)r1i, (const float*)r2i,
                (const float*)r3i, (const float*)A4, pn, r1o, r2o, r3o,
                (const float*)nullptr, (const float*)nullptr,
                (const float*)nullptr, (float*)nullptr);
            pc = pn;
            pn = (pn == pa) ? pb : pa;
        } else {
            cudaLaunchKernelEx(&cfg, k_up<true>,
                pc, (const float*)b, (const float*)r1i, (const float*)r2i,
                (const float*)r3i, (const float*)A4, (float*)nullptr,
                (float*)nullptr, (float*)nullptr, (float*)nullptr,
                (const float*)u2, (const float*)v2, (const float*)sig, out);
        }
    }
}